// round 1
// baseline (speedup 1.0000x reference)
#include <cuda_runtime.h>
#include <math.h>

#define D_MODEL   1024
#define NUM_HEADS 16
#define DEPTH     64
#define BB        2
#define SS        2048
#define MROWS     (BB * SS)                 // 4096
#define ATTN_ELEMS ((size_t)BB * NUM_HEADS * SS * SS)   // 134,217,728
#define OUT_ELEMS  ((size_t)MROWS * D_MODEL)            // 4,194,304

// ---------------- scratch (static device globals; no allocations) ----------------
__device__ float g_q[(size_t)BB * NUM_HEADS * SS * DEPTH];   // [b,h,s,d]
__device__ float g_k[(size_t)BB * NUM_HEADS * SS * DEPTH];
__device__ float g_v[(size_t)BB * NUM_HEADS * SS * DEPTH];
__device__ float g_o[(size_t)MROWS * D_MODEL];               // [b,s, h*64+d]
__device__ float g_attn_fallback[ATTN_ELEMS];                // used only if d_out lacks attn

// =====================================================================
// 128x128x8 fp32 GEMM with bias: C = A[MxK] @ W[KxN] + bias[N]
// LAYOUT 0: row-major C[M x N]
// LAYOUT 1: qkv split-heads: row r=(b*S+s), col c=h*64+d -> C[((b*H+h)*S+s)*64+d]
// 256 threads, 8x8 microtile. M,N,K multiples of 128/128/8 (true here).
// =====================================================================
template <int LAYOUT>
__global__ __launch_bounds__(256)
void gemm128_bias(const float* __restrict__ A, const float* __restrict__ W,
                  const float* __restrict__ bias, float* __restrict__ C,
                  int M, int N, int K)
{
    __shared__ float As[8][128];
    __shared__ float Ws[8][128];

    const int tid      = threadIdx.x;
    const int blockRow = blockIdx.y * 128;
    const int blockCol = blockIdx.x * 128;

    const int aRow = tid >> 1;          // 0..127
    const int aCol = (tid & 1) * 4;     // 0 or 4
    const int wRow = tid >> 5;          // 0..7
    const int wCol = (tid & 31) * 4;    // 0..124

    const int tRow = (tid >> 4) * 8;
    const int tCol = (tid & 15) * 8;

    float acc[8][8];
#pragma unroll
    for (int i = 0; i < 8; i++)
#pragma unroll
        for (int j = 0; j < 8; j++) acc[i][j] = 0.0f;

    for (int k0 = 0; k0 < K; k0 += 8) {
        float4 a4 = *(const float4*)&A[(size_t)(blockRow + aRow) * K + k0 + aCol];
        As[aCol + 0][aRow] = a4.x;
        As[aCol + 1][aRow] = a4.y;
        As[aCol + 2][aRow] = a4.z;
        As[aCol + 3][aRow] = a4.w;

        float4 w4 = *(const float4*)&W[(size_t)(k0 + wRow) * N + blockCol + wCol];
        *(float4*)&Ws[wRow][wCol] = w4;

        __syncthreads();

#pragma unroll
        for (int k = 0; k < 8; k++) {
            float4 ra0 = *(const float4*)&As[k][tRow];
            float4 ra1 = *(const float4*)&As[k][tRow + 4];
            float4 rb0 = *(const float4*)&Ws[k][tCol];
            float4 rb1 = *(const float4*)&Ws[k][tCol + 4];
            float ra[8] = {ra0.x, ra0.y, ra0.z, ra0.w, ra1.x, ra1.y, ra1.z, ra1.w};
            float rb[8] = {rb0.x, rb0.y, rb0.z, rb0.w, rb1.x, rb1.y, rb1.z, rb1.w};
#pragma unroll
            for (int i = 0; i < 8; i++)
#pragma unroll
                for (int j = 0; j < 8; j++)
                    acc[i][j] = fmaf(ra[i], rb[j], acc[i][j]);
        }
        __syncthreads();
    }

#pragma unroll
    for (int i = 0; i < 8; i++) {
        int r = blockRow + tRow + i;
#pragma unroll
        for (int j = 0; j < 8; j++) {
            int c = blockCol + tCol + j;
            float v = acc[i][j] + bias[c];
            if (LAYOUT == 0) {
                C[(size_t)r * N + c] = v;
            } else {
                int b = r / SS, s = r % SS;
                int h = c / DEPTH, d = c % DEPTH;
                C[(((size_t)b * NUM_HEADS + h) * SS + s) * DEPTH + d] = v;
            }
        }
    }
}

// =====================================================================
// scores[z, i, j] = 0.125 * dot(q[z,i,:], k[z,j,:])   (z = b*H+h, K=64)
// 128x128 tile, B accessed as rows (A @ B^T).
// =====================================================================
__global__ __launch_bounds__(256)
void scores_kernel(const float* __restrict__ Qh, const float* __restrict__ Kh,
                   float* __restrict__ attn)
{
    const int z = blockIdx.z;
    const float* A  = Qh + (size_t)z * SS * DEPTH;
    const float* Bm = Kh + (size_t)z * SS * DEPTH;
    float* C        = attn + (size_t)z * SS * SS;

    __shared__ float As[8][128];
    __shared__ float Bs[8][128];

    const int tid      = threadIdx.x;
    const int blockRow = blockIdx.y * 128;
    const int blockCol = blockIdx.x * 128;

    const int lRow = tid >> 1;
    const int lCol = (tid & 1) * 4;

    const int tRow = (tid >> 4) * 8;
    const int tCol = (tid & 15) * 8;

    float acc[8][8];
#pragma unroll
    for (int i = 0; i < 8; i++)
#pragma unroll
        for (int j = 0; j < 8; j++) acc[i][j] = 0.0f;

    for (int k0 = 0; k0 < DEPTH; k0 += 8) {
        float4 a4 = *(const float4*)&A[(size_t)(blockRow + lRow) * DEPTH + k0 + lCol];
        As[lCol + 0][lRow] = a4.x;
        As[lCol + 1][lRow] = a4.y;
        As[lCol + 2][lRow] = a4.z;
        As[lCol + 3][lRow] = a4.w;

        float4 b4 = *(const float4*)&Bm[(size_t)(blockCol + lRow) * DEPTH + k0 + lCol];
        Bs[lCol + 0][lRow] = b4.x;
        Bs[lCol + 1][lRow] = b4.y;
        Bs[lCol + 2][lRow] = b4.z;
        Bs[lCol + 3][lRow] = b4.w;

        __syncthreads();

#pragma unroll
        for (int k = 0; k < 8; k++) {
            float4 ra0 = *(const float4*)&As[k][tRow];
            float4 ra1 = *(const float4*)&As[k][tRow + 4];
            float4 rb0 = *(const float4*)&Bs[k][tCol];
            float4 rb1 = *(const float4*)&Bs[k][tCol + 4];
            float ra[8] = {ra0.x, ra0.y, ra0.z, ra0.w, ra1.x, ra1.y, ra1.z, ra1.w};
            float rb[8] = {rb0.x, rb0.y, rb0.z, rb0.w, rb1.x, rb1.y, rb1.z, rb1.w};
#pragma unroll
            for (int i = 0; i < 8; i++)
#pragma unroll
                for (int j = 0; j < 8; j++)
                    acc[i][j] = fmaf(ra[i], rb[j], acc[i][j]);
        }
        __syncthreads();
    }

#pragma unroll
    for (int i = 0; i < 8; i++) {
        int r = blockRow + tRow + i;
#pragma unroll
        for (int j = 0; j < 8; j++) {
            int c = blockCol + tCol + j;
            C[(size_t)r * SS + c] = acc[i][j] * 0.125f;  // 1/sqrt(64)
        }
    }
}

// =====================================================================
// In-place masked softmax over last dim (S=2048). One block per row.
// row = z*S + q ; b = z / H ; mask[b,k] * -1e9 added before softmax.
// =====================================================================
__global__ __launch_bounds__(256)
void softmax_kernel(float* __restrict__ attn, const float* __restrict__ mask)
{
    const size_t row = blockIdx.x;
    const int z = (int)(row / SS);
    const int b = z / NUM_HEADS;

    float* p = attn + row * SS;
    const float* m = mask + (size_t)b * SS;

    const int tid = threadIdx.x;   // 256 threads, 8 elems each
    __shared__ float sdata[256];

    float vals[8];
    float mx = -INFINITY;
#pragma unroll
    for (int i = 0; i < 8; i++) {
        int c = tid + i * 256;
        float v = p[c] + m[c] * (-1e9f);
        vals[i] = v;
        mx = fmaxf(mx, v);
    }

    sdata[tid] = mx;
    __syncthreads();
    for (int s = 128; s > 0; s >>= 1) {
        if (tid < s) sdata[tid] = fmaxf(sdata[tid], sdata[tid + s]);
        __syncthreads();
    }
    const float rowmax = sdata[0];
    __syncthreads();

    float sum = 0.0f;
#pragma unroll
    for (int i = 0; i < 8; i++) {
        vals[i] = __expf(vals[i] - rowmax);
        sum += vals[i];
    }
    sdata[tid] = sum;
    __syncthreads();
    for (int s = 128; s > 0; s >>= 1) {
        if (tid < s) sdata[tid] += sdata[tid + s];
        __syncthreads();
    }
    const float inv = 1.0f / sdata[0];

#pragma unroll
    for (int i = 0; i < 8; i++)
        p[tid + i * 256] = vals[i] * inv;
}

// =====================================================================
// O[b, q, h*64+d] = sum_k attn[z,q,k] * v[z,k,d]   (per z: [2048,2048]@[2048,64])
// 64x64 tile, BK=16, 256 threads, 4x4 microtile.
// =====================================================================
__global__ __launch_bounds__(256)
void av_kernel(const float* __restrict__ attn, const float* __restrict__ Vh,
               float* __restrict__ O)
{
    const int z = blockIdx.z;
    const int b = z / NUM_HEADS;
    const int h = z % NUM_HEADS;
    const float* A  = attn + (size_t)z * SS * SS;
    const float* Bm = Vh + (size_t)z * SS * DEPTH;

    __shared__ float As[16][64];
    __shared__ float Bs[16][64];

    const int tid      = threadIdx.x;
    const int blockRow = blockIdx.y * 64;

    const int aRow  = tid >> 2;          // 0..63
    const int aCol  = (tid & 3) * 4;     // 0..12
    const int bRow  = tid >> 4;          // 0..15
    const int bCol  = (tid & 15) * 4;    // 0..60

    const int tRow = (tid >> 4) * 4;
    const int tCol = (tid & 15) * 4;

    float acc[4][4];
#pragma unroll
    for (int i = 0; i < 4; i++)
#pragma unroll
        for (int j = 0; j < 4; j++) acc[i][j] = 0.0f;

    for (int k0 = 0; k0 < SS; k0 += 16) {
        float4 a4 = *(const float4*)&A[(size_t)(blockRow + aRow) * SS + k0 + aCol];
        As[aCol + 0][aRow] = a4.x;
        As[aCol + 1][aRow] = a4.y;
        As[aCol + 2][aRow] = a4.z;
        As[aCol + 3][aRow] = a4.w;

        float4 b4 = *(const float4*)&Bm[(size_t)(k0 + bRow) * DEPTH + bCol];
        *(float4*)&Bs[bRow][bCol] = b4;

        __syncthreads();

#pragma unroll
        for (int k = 0; k < 16; k++) {
            float4 ra = *(const float4*)&As[k][tRow];
            float4 rb = *(const float4*)&Bs[k][tCol];
            float raa[4] = {ra.x, ra.y, ra.z, ra.w};
            float rbb[4] = {rb.x, rb.y, rb.z, rb.w};
#pragma unroll
            for (int i = 0; i < 4; i++)
#pragma unroll
                for (int j = 0; j < 4; j++)
                    acc[i][j] = fmaf(raa[i], rbb[j], acc[i][j]);
        }
        __syncthreads();
    }

#pragma unroll
    for (int i = 0; i < 4; i++) {
        int q = blockRow + tRow + i;
#pragma unroll
        for (int j = 0; j < 4; j++) {
            int d = tCol + j;
            O[((size_t)b * SS + q) * D_MODEL + h * DEPTH + d] = acc[i][j];
        }
    }
}

// =====================================================================
extern "C" void kernel_launch(void* const* d_in, const int* in_sizes, int n_in,
                              void* d_out, int out_size)
{
    const float* Q    = (const float*)d_in[0];
    const float* K    = (const float*)d_in[1];
    const float* V    = (const float*)d_in[2];
    const float* mask = (const float*)d_in[3];
    const float* Wq   = (const float*)d_in[4];
    const float* bq   = (const float*)d_in[5];
    const float* Wk   = (const float*)d_in[6];
    const float* bk   = (const float*)d_in[7];
    const float* Wv   = (const float*)d_in[8];
    const float* bv   = (const float*)d_in[9];
    const float* Wo   = (const float*)d_in[10];
    const float* bo   = (const float*)d_in[11];

    float* out = (float*)d_out;

    // Locate scratch symbols
    float *qh, *kh, *vh, *oh, *attn;
    cudaGetSymbolAddress((void**)&qh, g_q);
    cudaGetSymbolAddress((void**)&kh, g_k);
    cudaGetSymbolAddress((void**)&vh, g_v);
    cudaGetSymbolAddress((void**)&oh, g_o);

    if ((size_t)out_size >= OUT_ELEMS + ATTN_ELEMS) {
        attn = out + OUT_ELEMS;   // attn is part of the harness output
    } else {
        cudaGetSymbolAddress((void**)&attn, g_attn_fallback);
    }

    dim3 projGrid(D_MODEL / 128, MROWS / 128);   // (8, 32)
    gemm128_bias<1><<<projGrid, 256>>>(Q, Wq, bq, qh, MROWS, D_MODEL, D_MODEL);
    gemm128_bias<1><<<projGrid, 256>>>(K, Wk, bk, kh, MROWS, D_MODEL, D_MODEL);
    gemm128_bias<1><<<projGrid, 256>>>(V, Wv, bv, vh, MROWS, D_MODEL, D_MODEL);

    dim3 scoreGrid(SS / 128, SS / 128, BB * NUM_HEADS);  // (16,16,32)
    scores_kernel<<<scoreGrid, 256>>>(qh, kh, attn);

    softmax_kernel<<<(unsigned)(BB * NUM_HEADS * SS), 256>>>(attn, mask);

    dim3 avGrid(1, SS / 64, BB * NUM_HEADS);             // (1,32,32)
    av_kernel<<<avGrid, 256>>>(attn, vh, oh);

    gemm128_bias<0><<<projGrid, 256>>>(oh, Wo, bo, out, MROWS, D_MODEL, D_MODEL);
}

// round 3
// speedup vs baseline: 1.3595x; 1.3595x over previous
#include <cuda_runtime.h>
#include <cuda_bf16.h>
#include <cstdint>
#include <math.h>

#define D_MODEL   1024
#define NUM_HEADS 16
#define DEPTH     64
#define BB        2
#define SS        2048
#define MROWS     (BB * SS)                              // 4096
#define ATTN_ELEMS ((size_t)BB * NUM_HEADS * SS * SS)    // 134,217,728
#define OUT_ELEMS  ((size_t)MROWS * D_MODEL)             // 4,194,304
#define NZ        (BB * NUM_HEADS)                       // 32

// ---------------- scratch (static device globals; no allocations) ------------
__device__ float g_q[(size_t)NZ * SS * DEPTH];           // [z,s,d]
__device__ float g_k[(size_t)NZ * SS * DEPTH];
__device__ float g_v[(size_t)NZ * SS * DEPTH];
__device__ float g_o[(size_t)MROWS * D_MODEL];           // [b,s, h*64+d]
__device__ float g_rowsum[(size_t)NZ * SS * 16];         // partial exp sums per 128-col block
__device__ __nv_bfloat16 g_a_hi[(size_t)MROWS * D_MODEL];
__device__ __nv_bfloat16 g_a_lo[(size_t)MROWS * D_MODEL];
__device__ __nv_bfloat16 g_wt_hi[(size_t)D_MODEL * D_MODEL];  // [n][k] transposed
__device__ __nv_bfloat16 g_wt_lo[(size_t)D_MODEL * D_MODEL];
__device__ float g_attn_fallback[ATTN_ELEMS];

// m16n8k16 bf16 mma, fp32 accum (arch-portable, sm_80+)
#define MMA16816(d, a, b)                                                     \
    asm volatile("mma.sync.aligned.m16n8k16.row.col.f32.bf16.bf16.f32 "       \
        "{%0,%1,%2,%3}, {%4,%5,%6,%7}, {%8,%9}, {%0,%1,%2,%3};"               \
        : "+f"((d)[0]), "+f"((d)[1]), "+f"((d)[2]), "+f"((d)[3])              \
        : "r"((a)[0]), "r"((a)[1]), "r"((a)[2]), "r"((a)[3]),                 \
          "r"((b)[0]), "r"((b)[1]))

// ============================ split kernels ==================================
__global__ __launch_bounds__(256)
void split_a_kernel(const float* __restrict__ A, __nv_bfloat16* __restrict__ hi,
                    __nv_bfloat16* __restrict__ lo, int n)
{
    int i = blockIdx.x * 256 + threadIdx.x;
    if (i < n) {
        float x = A[i];
        __nv_bfloat16 h = __float2bfloat16(x);
        hi[i] = h;
        lo[i] = __float2bfloat16(x - __bfloat162float(h));
    }
}

// W[k][n] -> wt_hi/lo[n][k], 32x32 smem transpose
__global__ __launch_bounds__(256)
void split_wt_kernel(const float* __restrict__ W, __nv_bfloat16* __restrict__ hi,
                     __nv_bfloat16* __restrict__ lo)
{
    __shared__ float t[32][33];
    int tx = threadIdx.x, ty = threadIdx.y;           // block (32, 8)
    int n0 = blockIdx.x * 32, k0 = blockIdx.y * 32;
#pragma unroll
    for (int j = 0; j < 4; j++)
        t[ty + j * 8][tx] = W[(size_t)(k0 + ty + j * 8) * D_MODEL + n0 + tx];
    __syncthreads();
#pragma unroll
    for (int j = 0; j < 4; j++) {
        float x = t[tx][ty + j * 8];
        __nv_bfloat16 h = __float2bfloat16(x);
        size_t o = (size_t)(n0 + ty + j * 8) * D_MODEL + k0 + tx;
        hi[o] = h;
        lo[o] = __float2bfloat16(x - __bfloat162float(h));
    }
}

// ==================== mma.sync projection GEMM ================================
// C[4096 x 1024] = A @ W + bias, via (Ah+Al)@(Wh+Wl) ~ AhWh + AhWl + AlWh.
// Block 128x128, 8 warps (2x4), warp tile 64x32. K staged 32 at a time.
// Smem rows padded to 40 halves (80B): fragment-row bank offsets
// {0,20,8,28,16,4,24,12} -> conflict-free quad loads.
// LAYOUT 0: row-major. LAYOUT 1: split-heads [z][s][d].
#define SPAD 40

template <int LAYOUT>
__global__ __launch_bounds__(256)
void proj_mma_kernel(const __nv_bfloat16* __restrict__ a_hi, const __nv_bfloat16* __restrict__ a_lo,
                     const __nv_bfloat16* __restrict__ w_hi, const __nv_bfloat16* __restrict__ w_lo,
                     const float* __restrict__ bias, float* __restrict__ C)
{
    __shared__ alignas(16) __nv_bfloat16 sAh[128 * SPAD];
    __shared__ alignas(16) __nv_bfloat16 sAl[128 * SPAD];
    __shared__ alignas(16) __nv_bfloat16 sBh[128 * SPAD];
    __shared__ alignas(16) __nv_bfloat16 sBl[128 * SPAD];

    const int tid  = threadIdx.x;
    const int lane = tid & 31;
    const int wid  = tid >> 5;
    const int warpM = (wid >> 2) * 64;
    const int warpN = (wid & 3) * 32;
    const int blockRow = blockIdx.y * 128;
    const int blockCol = blockIdx.x * 128;

    float acc[4][4][4];
#pragma unroll
    for (int mt = 0; mt < 4; mt++)
#pragma unroll
        for (int nt = 0; nt < 4; nt++)
#pragma unroll
            for (int r = 0; r < 4; r++) acc[mt][nt][r] = 0.0f;

    for (int k0 = 0; k0 < D_MODEL; k0 += 32) {
        // gmem -> smem: each tile 128 rows x 32 halves (64B) = 512 uint4
#pragma unroll
        for (int i = 0; i < 2; i++) {
            int id  = tid + i * 256;         // 0..511
            int row = id >> 2;
            int q   = id & 3;                // 16B chunk
            size_t goA = (size_t)(blockRow + row) * D_MODEL + k0 + q * 8;
            size_t goB = (size_t)(blockCol + row) * D_MODEL + k0 + q * 8;
            uint32_t so = (uint32_t)(row * (SPAD * 2) + q * 16);
            *(uint4*)((char*)sAh + so) = *(const uint4*)&a_hi[goA];
            *(uint4*)((char*)sAl + so) = *(const uint4*)&a_lo[goA];
            *(uint4*)((char*)sBh + so) = *(const uint4*)&w_hi[goB];
            *(uint4*)((char*)sBl + so) = *(const uint4*)&w_lo[goB];
        }
        __syncthreads();

#pragma unroll
        for (int ks = 0; ks < 2; ks++) {
            const int kb = ks * 16;
            uint32_t aH[4][4], aL[4][4], bH[4][2], bL[4][2];
#pragma unroll
            for (int mt = 0; mt < 4; mt++) {
#pragma unroll
                for (int r = 0; r < 4; r++) {
                    int row = warpM + mt * 16 + (lane >> 2) + 8 * (r & 1);
                    int col = kb + (lane & 3) * 2 + 8 * (r >> 1);
                    uint32_t off = (uint32_t)(row * SPAD + col) * 2;
                    aH[mt][r] = *(const uint32_t*)((const char*)sAh + off);
                    aL[mt][r] = *(const uint32_t*)((const char*)sAl + off);
                }
            }
#pragma unroll
            for (int nt = 0; nt < 4; nt++) {
#pragma unroll
                for (int r = 0; r < 2; r++) {
                    int n = warpN + nt * 8 + (lane >> 2);
                    int k = kb + (lane & 3) * 2 + 8 * r;
                    uint32_t off = (uint32_t)(n * SPAD + k) * 2;
                    bH[nt][r] = *(const uint32_t*)((const char*)sBh + off);
                    bL[nt][r] = *(const uint32_t*)((const char*)sBl + off);
                }
            }
#pragma unroll
            for (int mt = 0; mt < 4; mt++)
#pragma unroll
                for (int nt = 0; nt < 4; nt++) {
                    MMA16816(acc[mt][nt], aH[mt], bH[nt]);
                    MMA16816(acc[mt][nt], aH[mt], bL[nt]);
                    MMA16816(acc[mt][nt], aL[mt], bH[nt]);
                }
        }
        __syncthreads();
    }

    // epilogue: c{0,1} at (row, col..col+1), c{2,3} at (row+8, ...)
#pragma unroll
    for (int mt = 0; mt < 4; mt++) {
#pragma unroll
        for (int nt = 0; nt < 4; nt++) {
            int row0 = blockRow + warpM + mt * 16 + (lane >> 2);
            int col  = blockCol + warpN + nt * 8 + (lane & 3) * 2;
            float b0 = bias[col], b1 = bias[col + 1];
#pragma unroll
            for (int half = 0; half < 2; half++) {
                int r = row0 + half * 8;
                float2 v;
                v.x = acc[mt][nt][half * 2 + 0] + b0;
                v.y = acc[mt][nt][half * 2 + 1] + b1;
                if (LAYOUT == 0) {
                    *(float2*)&C[(size_t)r * D_MODEL + col] = v;
                } else {
                    int bb = r / SS, s = r % SS;
                    int h = col / DEPTH, d = col % DEPTH;
                    *(float2*)&C[(((size_t)bb * NUM_HEADS + h) * SS + s) * DEPTH + d] = v;
                }
            }
        }
    }
}

// ==================== scores + exp + partial rowsums (fp32 SIMT) =============
// attn[z,i,j] = exp(0.125 * dot(q[z,i,:], k[z,j,:]) + mask[b,j] * -1e9)
__global__ __launch_bounds__(256)
void scores_kernel(const float* __restrict__ Qh, const float* __restrict__ Kh,
                   const float* __restrict__ mask, float* __restrict__ attn,
                   float* __restrict__ rowsum)
{
    extern __shared__ float sm[];
    float (*As)[128] = (float (*)[128])sm;            // [64][128]
    float (*Bs)[128] = (float (*)[128])(sm + 64 * 128);

    const int z = blockIdx.z;
    const int b = z / NUM_HEADS;
    const float* A  = Qh + (size_t)z * SS * DEPTH;
    const float* Bm = Kh + (size_t)z * SS * DEPTH;
    float* C        = attn + (size_t)z * SS * SS;

    const int tid = threadIdx.x;
    const int blockRow = blockIdx.y * 128;
    const int blockCol = blockIdx.x * 128;

#pragma unroll
    for (int i = 0; i < 8; i++) {
        int id = tid + i * 256;
        int row = id >> 4, q = id & 15;
        float4 a4 = *(const float4*)&A[(size_t)(blockRow + row) * DEPTH + q * 4];
        As[q * 4 + 0][row] = a4.x; As[q * 4 + 1][row] = a4.y;
        As[q * 4 + 2][row] = a4.z; As[q * 4 + 3][row] = a4.w;
        float4 b4 = *(const float4*)&Bm[(size_t)(blockCol + row) * DEPTH + q * 4];
        Bs[q * 4 + 0][row] = b4.x; Bs[q * 4 + 1][row] = b4.y;
        Bs[q * 4 + 2][row] = b4.z; Bs[q * 4 + 3][row] = b4.w;
    }
    __syncthreads();

    const int tRow = (tid >> 4) * 8;
    const int tCol = (tid & 15) * 8;

    float acc[8][8];
#pragma unroll
    for (int i = 0; i < 8; i++)
#pragma unroll
        for (int j = 0; j < 8; j++) acc[i][j] = 0.0f;

#pragma unroll 16
    for (int k = 0; k < 64; k++) {
        float4 ra0 = *(const float4*)&As[k][tRow];
        float4 ra1 = *(const float4*)&As[k][tRow + 4];
        float4 rb0 = *(const float4*)&Bs[k][tCol];
        float4 rb1 = *(const float4*)&Bs[k][tCol + 4];
        float ra[8] = {ra0.x, ra0.y, ra0.z, ra0.w, ra1.x, ra1.y, ra1.z, ra1.w};
        float rb[8] = {rb0.x, rb0.y, rb0.z, rb0.w, rb1.x, rb1.y, rb1.z, rb1.w};
#pragma unroll
        for (int i = 0; i < 8; i++)
#pragma unroll
            for (int j = 0; j < 8; j++)
                acc[i][j] = fmaf(ra[i], rb[j], acc[i][j]);
    }

    float mcol[8];
#pragma unroll
    for (int j = 0; j < 8; j++)
        mcol[j] = mask[(size_t)b * SS + blockCol + tCol + j] * (-1e9f);

    float rs[8];
#pragma unroll
    for (int i = 0; i < 8; i++) {
        float e[8];
#pragma unroll
        for (int j = 0; j < 8; j++)
            e[j] = __expf(acc[i][j] * 0.125f + mcol[j]);
        float4 v0 = {e[0], e[1], e[2], e[3]};
        float4 v1 = {e[4], e[5], e[6], e[7]};
        size_t ro = (size_t)(blockRow + tRow + i) * SS + blockCol + tCol;
        *(float4*)&C[ro]     = v0;
        *(float4*)&C[ro + 4] = v1;
        rs[i] = ((e[0] + e[1]) + (e[2] + e[3])) + ((e[4] + e[5]) + (e[6] + e[7]));
    }
#pragma unroll
    for (int i = 0; i < 8; i++) {
#pragma unroll
        for (int off = 1; off < 16; off <<= 1)
            rs[i] += __shfl_xor_sync(0xffffffff, rs[i], off);
    }
    if ((tid & 15) == 0) {
#pragma unroll
        for (int i = 0; i < 8; i++)
            rowsum[((size_t)z * SS + blockRow + tRow + i) * 16 + blockIdx.x] = rs[i];
    }
}

// ==================== AV + normalize + attn writeback ========================
__global__ __launch_bounds__(256)
void av_kernel(float* __restrict__ attn, const float* __restrict__ Vh,
               const float* __restrict__ rowsum, float* __restrict__ O)
{
    __shared__ float As[16][128];
    __shared__ float Bs[16][64];
    __shared__ float invs[128];

    const int z = blockIdx.y;
    const int b = z / NUM_HEADS;
    const int h = z % NUM_HEADS;
    const int rowbase = blockIdx.x * 128;
    const int tid = threadIdx.x;

    float* Az       = attn + (size_t)z * SS * SS;
    const float* Vz = Vh + (size_t)z * SS * DEPTH;

    if (tid < 128) {
        const float* rsp = &rowsum[((size_t)z * SS + rowbase + tid) * 16];
        float s = 0.0f;
#pragma unroll
        for (int j = 0; j < 16; j++) s += rsp[j];
        invs[tid] = 1.0f / s;
    }
    __syncthreads();

    const int lRow = tid >> 1;             // 0..127
    const int lK   = (tid & 1) * 8;        // 0 or 8
    const float inv = invs[lRow];
    const int bRow = tid >> 4;             // 0..15
    const int bCol = (tid & 15) * 4;

    const int tRow = (tid >> 4) * 8;
    const int tCol = (tid & 15) * 4;

    float acc[8][4];
#pragma unroll
    for (int i = 0; i < 8; i++)
#pragma unroll
        for (int j = 0; j < 4; j++) acc[i][j] = 0.0f;

    for (int k0 = 0; k0 < SS; k0 += 16) {
        size_t base = (size_t)(rowbase + lRow) * SS + k0 + lK;
        float4 a0 = *(const float4*)&Az[base];
        float4 a1 = *(const float4*)&Az[base + 4];
        a0.x *= inv; a0.y *= inv; a0.z *= inv; a0.w *= inv;
        a1.x *= inv; a1.y *= inv; a1.z *= inv; a1.w *= inv;
        *(float4*)&Az[base]     = a0;
        *(float4*)&Az[base + 4] = a1;
        As[lK + 0][lRow] = a0.x; As[lK + 1][lRow] = a0.y;
        As[lK + 2][lRow] = a0.z; As[lK + 3][lRow] = a0.w;
        As[lK + 4][lRow] = a1.x; As[lK + 5][lRow] = a1.y;
        As[lK + 6][lRow] = a1.z; As[lK + 7][lRow] = a1.w;

        *(float4*)&Bs[bRow][bCol] = *(const float4*)&Vz[(size_t)(k0 + bRow) * DEPTH + bCol];
        __syncthreads();

#pragma unroll
        for (int k = 0; k < 16; k++) {
            float4 ra0 = *(const float4*)&As[k][tRow];
            float4 ra1 = *(const float4*)&As[k][tRow + 4];
            float4 rb  = *(const float4*)&Bs[k][tCol];
            float ra[8] = {ra0.x, ra0.y, ra0.z, ra0.w, ra1.x, ra1.y, ra1.z, ra1.w};
            float rbb[4] = {rb.x, rb.y, rb.z, rb.w};
#pragma unroll
            for (int i = 0; i < 8; i++)
#pragma unroll
                for (int j = 0; j < 4; j++)
                    acc[i][j] = fmaf(ra[i], rbb[j], acc[i][j]);
        }
        __syncthreads();
    }

#pragma unroll
    for (int i = 0; i < 8; i++) {
        int q = rowbase + tRow + i;
        float4 v = {acc[i][0], acc[i][1], acc[i][2], acc[i][3]};
        *(float4*)&O[((size_t)b * SS + q) * D_MODEL + h * DEPTH + tCol] = v;
    }
}

// =====================================================================
extern "C" void kernel_launch(void* const* d_in, const int* in_sizes, int n_in,
                              void* d_out, int out_size)
{
    const float* Q    = (const float*)d_in[0];
    const float* K    = (const float*)d_in[1];
    const float* V    = (const float*)d_in[2];
    const float* mask = (const float*)d_in[3];
    const float* Wq   = (const float*)d_in[4];
    const float* bq   = (const float*)d_in[5];
    const float* Wk   = (const float*)d_in[6];
    const float* bk   = (const float*)d_in[7];
    const float* Wv   = (const float*)d_in[8];
    const float* bv   = (const float*)d_in[9];
    const float* Wo   = (const float*)d_in[10];
    const float* bo   = (const float*)d_in[11];

    float* out = (float*)d_out;

    float *qh, *kh, *vh, *oh, *rowsum, *attn;
    __nv_bfloat16 *ah, *al, *wh, *wl;
    cudaGetSymbolAddress((void**)&qh, g_q);
    cudaGetSymbolAddress((void**)&kh, g_k);
    cudaGetSymbolAddress((void**)&vh, g_v);
    cudaGetSymbolAddress((void**)&oh, g_o);
    cudaGetSymbolAddress((void**)&rowsum, g_rowsum);
    cudaGetSymbolAddress((void**)&ah, g_a_hi);
    cudaGetSymbolAddress((void**)&al, g_a_lo);
    cudaGetSymbolAddress((void**)&wh, g_wt_hi);
    cudaGetSymbolAddress((void**)&wl, g_wt_lo);

    if ((size_t)out_size >= OUT_ELEMS + ATTN_ELEMS) {
        attn = out + OUT_ELEMS;
    } else {
        cudaGetSymbolAddress((void**)&attn, g_attn_fallback);
    }

    static bool attr_done = false;
    if (!attr_done) {
        cudaFuncSetAttribute(scores_kernel, cudaFuncAttributeMaxDynamicSharedMemorySize, 65536);
        attr_done = true;
    }

    const int NELEM = MROWS * D_MODEL;
    dim3 wtGrid(32, 32), wtBlock(32, 8);
    dim3 projGrid(8, 32);

    // Q projection
    split_wt_kernel<<<wtGrid, wtBlock>>>(Wq, wh, wl);
    split_a_kernel<<<NELEM / 256, 256>>>(Q, ah, al, NELEM);
    proj_mma_kernel<1><<<projGrid, 256>>>(ah, al, wh, wl, bq, qh);
    // K projection
    split_wt_kernel<<<wtGrid, wtBlock>>>(Wk, wh, wl);
    split_a_kernel<<<NELEM / 256, 256>>>(K, ah, al, NELEM);
    proj_mma_kernel<1><<<projGrid, 256>>>(ah, al, wh, wl, bk, kh);
    // V projection
    split_wt_kernel<<<wtGrid, wtBlock>>>(Wv, wh, wl);
    split_a_kernel<<<NELEM / 256, 256>>>(V, ah, al, NELEM);
    proj_mma_kernel<1><<<projGrid, 256>>>(ah, al, wh, wl, bv, vh);

    // scores + exp + rowsums
    dim3 scoreGrid(16, 16, NZ);
    scores_kernel<<<scoreGrid, 256, 65536>>>(qh, kh, mask, attn, rowsum);

    // AV + normalize + writeback
    dim3 avGrid(16, NZ);
    av_kernel<<<avGrid, 256>>>(attn, vh, rowsum, oh);

    // output projection
    split_wt_kernel<<<wtGrid, wtBlock>>>(Wo, wh, wl);
    split_a_kernel<<<NELEM / 256, 256>>>(oh, ah, al, NELEM);
    proj_mma_kernel<0><<<projGrid, 256>>>(ah, al, wh, wl, bo, out);
}

// round 4
// speedup vs baseline: 1.8653x; 1.3720x over previous
#include <cuda_runtime.h>
#include <cuda_bf16.h>
#include <cstdint>
#include <math.h>

#define D_MODEL   1024
#define NUM_HEADS 16
#define DEPTH     64
#define BB        2
#define SS        2048
#define MROWS     (BB * SS)                              // 4096
#define ATTN_ELEMS ((size_t)BB * NUM_HEADS * SS * SS)    // 134,217,728
#define OUT_ELEMS  ((size_t)MROWS * D_MODEL)             // 4,194,304
#define NZ        (BB * NUM_HEADS)                       // 32
#define RS_W      64                                     // rowsum partials per row

// ---------------- scratch (static device globals; no allocations) ------------
__device__ float g_q[(size_t)NZ * SS * DEPTH];           // [z,s,d]
__device__ float g_k[(size_t)NZ * SS * DEPTH];
__device__ float g_v[(size_t)NZ * SS * DEPTH];
__device__ float g_o[(size_t)MROWS * D_MODEL];           // [b,s, h*64+d]
__device__ float g_rowsum[(size_t)NZ * SS * RS_W];
__device__ __nv_bfloat16 g_a_hi[(size_t)MROWS * D_MODEL];
__device__ __nv_bfloat16 g_a_lo[(size_t)MROWS * D_MODEL];
__device__ __nv_bfloat16 g_wt_hi[(size_t)D_MODEL * D_MODEL];  // [n][k] transposed
__device__ __nv_bfloat16 g_wt_lo[(size_t)D_MODEL * D_MODEL];
__device__ __nv_bfloat16 g_q_hi[(size_t)NZ * SS * DEPTH];
__device__ __nv_bfloat16 g_q_lo[(size_t)NZ * SS * DEPTH];
__device__ __nv_bfloat16 g_k_hi[(size_t)NZ * SS * DEPTH];
__device__ __nv_bfloat16 g_k_lo[(size_t)NZ * SS * DEPTH];
__device__ __nv_bfloat16 g_vt_hi[(size_t)NZ * SS * DEPTH];    // [z,d,s]
__device__ __nv_bfloat16 g_vt_lo[(size_t)NZ * SS * DEPTH];
__device__ float g_attn_fallback[ATTN_ELEMS];

// m16n8k16 bf16 mma, fp32 accum (arch-portable, sm_80+)
#define MMA16816(d, a, b)                                                     \
    asm volatile("mma.sync.aligned.m16n8k16.row.col.f32.bf16.bf16.f32 "       \
        "{%0,%1,%2,%3}, {%4,%5,%6,%7}, {%8,%9}, {%0,%1,%2,%3};"               \
        : "+f"((d)[0]), "+f"((d)[1]), "+f"((d)[2]), "+f"((d)[3])              \
        : "r"((a)[0]), "r"((a)[1]), "r"((a)[2]), "r"((a)[3]),                 \
          "r"((b)[0]), "r"((b)[1]))

// ============================ split kernels ==================================
__global__ __launch_bounds__(256)
void split_a_kernel(const float* __restrict__ A, __nv_bfloat16* __restrict__ hi,
                    __nv_bfloat16* __restrict__ lo, int n)
{
    int i = blockIdx.x * 256 + threadIdx.x;
    if (i < n) {
        float x = A[i];
        __nv_bfloat16 h = __float2bfloat16(x);
        hi[i] = h;
        lo[i] = __float2bfloat16(x - __bfloat162float(h));
    }
}

// W[k][n] -> wt_hi/lo[n][k], 32x32 smem transpose
__global__ __launch_bounds__(256)
void split_wt_kernel(const float* __restrict__ W, __nv_bfloat16* __restrict__ hi,
                     __nv_bfloat16* __restrict__ lo)
{
    __shared__ float t[32][33];
    int tx = threadIdx.x, ty = threadIdx.y;           // block (32, 8)
    int n0 = blockIdx.x * 32, k0 = blockIdx.y * 32;
#pragma unroll
    for (int j = 0; j < 4; j++)
        t[ty + j * 8][tx] = W[(size_t)(k0 + ty + j * 8) * D_MODEL + n0 + tx];
    __syncthreads();
#pragma unroll
    for (int j = 0; j < 4; j++) {
        float x = t[tx][ty + j * 8];
        __nv_bfloat16 h = __float2bfloat16(x);
        size_t o = (size_t)(n0 + ty + j * 8) * D_MODEL + k0 + tx;
        hi[o] = h;
        lo[o] = __float2bfloat16(x - __bfloat162float(h));
    }
}

// v[z][s][d] -> vt_hi/lo[z][d][s]
__global__ __launch_bounds__(256)
void trans_split_v(const float* __restrict__ v, __nv_bfloat16* __restrict__ hi,
                   __nv_bfloat16* __restrict__ lo)
{
    __shared__ float t[32][33];
    int z = blockIdx.z;
    int s0 = blockIdx.x * 32, d0 = blockIdx.y * 32;
    int tx = threadIdx.x, ty = threadIdx.y;           // (32, 8)
    const float* V = v + (size_t)z * SS * DEPTH;
#pragma unroll
    for (int j = 0; j < 4; j++)
        t[ty + j * 8][tx] = V[(size_t)(s0 + ty + j * 8) * DEPTH + d0 + tx];
    __syncthreads();
#pragma unroll
    for (int j = 0; j < 4; j++) {
        float x = t[tx][ty + j * 8];                  // V[s0+tx][d0+ty+j*8]
        __nv_bfloat16 h = __float2bfloat16(x);
        size_t o = ((size_t)z * DEPTH + d0 + ty + j * 8) * SS + s0 + tx;
        hi[o] = h;
        lo[o] = __float2bfloat16(x - __bfloat162float(h));
    }
}

// ==================== mma.sync projection GEMM ================================
#define SPAD 40

template <int LAYOUT>
__global__ __launch_bounds__(256)
void proj_mma_kernel(const __nv_bfloat16* __restrict__ a_hi, const __nv_bfloat16* __restrict__ a_lo,
                     const __nv_bfloat16* __restrict__ w_hi, const __nv_bfloat16* __restrict__ w_lo,
                     const float* __restrict__ bias, float* __restrict__ C)
{
    __shared__ alignas(16) __nv_bfloat16 sAh[128 * SPAD];
    __shared__ alignas(16) __nv_bfloat16 sAl[128 * SPAD];
    __shared__ alignas(16) __nv_bfloat16 sBh[128 * SPAD];
    __shared__ alignas(16) __nv_bfloat16 sBl[128 * SPAD];

    const int tid  = threadIdx.x;
    const int lane = tid & 31;
    const int wid  = tid >> 5;
    const int warpM = (wid >> 2) * 64;
    const int warpN = (wid & 3) * 32;
    const int blockRow = blockIdx.y * 128;
    const int blockCol = blockIdx.x * 128;

    float acc[4][4][4];
#pragma unroll
    for (int mt = 0; mt < 4; mt++)
#pragma unroll
        for (int nt = 0; nt < 4; nt++)
#pragma unroll
            for (int r = 0; r < 4; r++) acc[mt][nt][r] = 0.0f;

    for (int k0 = 0; k0 < D_MODEL; k0 += 32) {
#pragma unroll
        for (int i = 0; i < 2; i++) {
            int id  = tid + i * 256;
            int row = id >> 2;
            int q   = id & 3;
            size_t goA = (size_t)(blockRow + row) * D_MODEL + k0 + q * 8;
            size_t goB = (size_t)(blockCol + row) * D_MODEL + k0 + q * 8;
            uint32_t so = (uint32_t)(row * (SPAD * 2) + q * 16);
            *(uint4*)((char*)sAh + so) = *(const uint4*)&a_hi[goA];
            *(uint4*)((char*)sAl + so) = *(const uint4*)&a_lo[goA];
            *(uint4*)((char*)sBh + so) = *(const uint4*)&w_hi[goB];
            *(uint4*)((char*)sBl + so) = *(const uint4*)&w_lo[goB];
        }
        __syncthreads();

#pragma unroll
        for (int ks = 0; ks < 2; ks++) {
            const int kb = ks * 16;
            uint32_t aH[4][4], aL[4][4], bH[4][2], bL[4][2];
#pragma unroll
            for (int mt = 0; mt < 4; mt++) {
#pragma unroll
                for (int r = 0; r < 4; r++) {
                    int row = warpM + mt * 16 + (lane >> 2) + 8 * (r & 1);
                    int col = kb + (lane & 3) * 2 + 8 * (r >> 1);
                    uint32_t off = (uint32_t)(row * SPAD + col) * 2;
                    aH[mt][r] = *(const uint32_t*)((const char*)sAh + off);
                    aL[mt][r] = *(const uint32_t*)((const char*)sAl + off);
                }
            }
#pragma unroll
            for (int nt = 0; nt < 4; nt++) {
#pragma unroll
                for (int r = 0; r < 2; r++) {
                    int n = warpN + nt * 8 + (lane >> 2);
                    int k = kb + (lane & 3) * 2 + 8 * r;
                    uint32_t off = (uint32_t)(n * SPAD + k) * 2;
                    bH[nt][r] = *(const uint32_t*)((const char*)sBh + off);
                    bL[nt][r] = *(const uint32_t*)((const char*)sBl + off);
                }
            }
#pragma unroll
            for (int mt = 0; mt < 4; mt++)
#pragma unroll
                for (int nt = 0; nt < 4; nt++) {
                    MMA16816(acc[mt][nt], aH[mt], bH[nt]);
                    MMA16816(acc[mt][nt], aH[mt], bL[nt]);
                    MMA16816(acc[mt][nt], aL[mt], bH[nt]);
                }
        }
        __syncthreads();
    }

#pragma unroll
    for (int mt = 0; mt < 4; mt++) {
#pragma unroll
        for (int nt = 0; nt < 4; nt++) {
            int row0 = blockRow + warpM + mt * 16 + (lane >> 2);
            int col  = blockCol + warpN + nt * 8 + (lane & 3) * 2;
            float b0 = bias[col], b1 = bias[col + 1];
#pragma unroll
            for (int half = 0; half < 2; half++) {
                int r = row0 + half * 8;
                float2 v;
                v.x = acc[mt][nt][half * 2 + 0] + b0;
                v.y = acc[mt][nt][half * 2 + 1] + b1;
                if (LAYOUT == 0) {
                    *(float2*)&C[(size_t)r * D_MODEL + col] = v;
                } else {
                    int bb = r / SS, s = r % SS;
                    int h = col / DEPTH, d = col % DEPTH;
                    *(float2*)&C[(((size_t)bb * NUM_HEADS + h) * SS + s) * DEPTH + d] = v;
                }
            }
        }
    }
}

// ==================== scores: mma.sync + exp + rowsum partials ===============
// attn[z,i,j] = exp(0.125*dot(q_i,k_j) + mask[b,j]*-1e9), rowsum partials out.
// Block 128x128, 8 warps (2x4), warp 64x32. K=64 fully resident (stride 72).
#define QPAD 72

__global__ __launch_bounds__(256)
void scores_mma_kernel(const __nv_bfloat16* __restrict__ qh, const __nv_bfloat16* __restrict__ ql,
                       const __nv_bfloat16* __restrict__ kh, const __nv_bfloat16* __restrict__ kl,
                       const float* __restrict__ mask, float* __restrict__ attn,
                       float* __restrict__ rowsum)
{
    extern __shared__ char sm[];
    __nv_bfloat16* sQh = (__nv_bfloat16*)sm;              // 128*72 halves each
    __nv_bfloat16* sQl = sQh + 128 * QPAD;
    __nv_bfloat16* sKh = sQl + 128 * QPAD;
    __nv_bfloat16* sKl = sKh + 128 * QPAD;

    const int z = blockIdx.z;
    const int b = z / NUM_HEADS;
    const int tid = threadIdx.x, lane = tid & 31, wid = tid >> 5;
    const int warpM = (wid >> 2) * 64, warpN = (wid & 3) * 32;
    const int blockRow = blockIdx.y * 128, blockCol = blockIdx.x * 128;

    // load q/k tiles: 128 rows x 64 halves, 8 x uint4 per row
#pragma unroll
    for (int i = 0; i < 4; i++) {
        int id = tid + i * 256;
        int row = id >> 3, q = id & 7;
        size_t gq = ((size_t)z * SS + blockRow + row) * DEPTH + q * 8;
        size_t gk = ((size_t)z * SS + blockCol + row) * DEPTH + q * 8;
        int so = row * QPAD + q * 8;
        *(uint4*)&sQh[so] = *(const uint4*)&qh[gq];
        *(uint4*)&sQl[so] = *(const uint4*)&ql[gq];
        *(uint4*)&sKh[so] = *(const uint4*)&kh[gk];
        *(uint4*)&sKl[so] = *(const uint4*)&kl[gk];
    }
    __syncthreads();

    float acc[4][4][4];
#pragma unroll
    for (int mt = 0; mt < 4; mt++)
#pragma unroll
        for (int nt = 0; nt < 4; nt++)
#pragma unroll
            for (int r = 0; r < 4; r++) acc[mt][nt][r] = 0.0f;

#pragma unroll
    for (int ks = 0; ks < 4; ks++) {
        const int kb = ks * 16;
        uint32_t aH[4][4], aL[4][4], bH[4][2], bL[4][2];
#pragma unroll
        for (int mt = 0; mt < 4; mt++) {
#pragma unroll
            for (int r = 0; r < 4; r++) {
                int row = warpM + mt * 16 + (lane >> 2) + 8 * (r & 1);
                int col = kb + (lane & 3) * 2 + 8 * (r >> 1);
                uint32_t off = (uint32_t)(row * QPAD + col) * 2;
                aH[mt][r] = *(const uint32_t*)((const char*)sQh + off);
                aL[mt][r] = *(const uint32_t*)((const char*)sQl + off);
            }
        }
#pragma unroll
        for (int nt = 0; nt < 4; nt++) {
#pragma unroll
            for (int r = 0; r < 2; r++) {
                int n = warpN + nt * 8 + (lane >> 2);
                int k = kb + (lane & 3) * 2 + 8 * r;
                uint32_t off = (uint32_t)(n * QPAD + k) * 2;
                bH[nt][r] = *(const uint32_t*)((const char*)sKh + off);
                bL[nt][r] = *(const uint32_t*)((const char*)sKl + off);
            }
        }
#pragma unroll
        for (int mt = 0; mt < 4; mt++)
#pragma unroll
            for (int nt = 0; nt < 4; nt++) {
                MMA16816(acc[mt][nt], aH[mt], bH[nt]);
                MMA16816(acc[mt][nt], aH[mt], bL[nt]);
                MMA16816(acc[mt][nt], aL[mt], bH[nt]);
            }
    }

    // epilogue: scale, mask, exp, store, per-warp row sums
    float mcol[4][2];
#pragma unroll
    for (int nt = 0; nt < 4; nt++) {
        int col = blockCol + warpN + nt * 8 + (lane & 3) * 2;
        mcol[nt][0] = mask[(size_t)b * SS + col]     * (-1e9f);
        mcol[nt][1] = mask[(size_t)b * SS + col + 1] * (-1e9f);
    }
    float* Cz = attn + (size_t)z * SS * SS;

#pragma unroll
    for (int mt = 0; mt < 4; mt++) {
#pragma unroll
        for (int half = 0; half < 2; half++) {
            int row = blockRow + warpM + mt * 16 + (lane >> 2) + half * 8;
            float rs = 0.0f;
#pragma unroll
            for (int nt = 0; nt < 4; nt++) {
                int col = blockCol + warpN + nt * 8 + (lane & 3) * 2;
                float e0 = __expf(acc[mt][nt][half * 2 + 0] * 0.125f + mcol[nt][0]);
                float e1 = __expf(acc[mt][nt][half * 2 + 1] * 0.125f + mcol[nt][1]);
                rs += e0 + e1;
                float2 v = {e0, e1};
                *(float2*)&Cz[(size_t)row * SS + col] = v;
            }
            rs += __shfl_xor_sync(0xffffffffu, rs, 1);
            rs += __shfl_xor_sync(0xffffffffu, rs, 2);
            if ((lane & 3) == 0)
                rowsum[((size_t)z * SS + row) * RS_W + blockIdx.x * 4 + (wid & 3)] = rs;
        }
    }
}

// ==================== AV: normalize + writeback + mma.sync ===================
// Block: 128 attn rows x 64 d. 8 warps (4x2), warp 32x32. K chunk 32 keys.
__global__ __launch_bounds__(256)
void av_mma_kernel(float* __restrict__ attn,
                   const __nv_bfloat16* __restrict__ vth, const __nv_bfloat16* __restrict__ vtl,
                   const float* __restrict__ rowsum, float* __restrict__ O)
{
    __shared__ alignas(16) __nv_bfloat16 sAh[128 * SPAD];
    __shared__ alignas(16) __nv_bfloat16 sAl[128 * SPAD];
    __shared__ alignas(16) __nv_bfloat16 sBh[64 * SPAD];
    __shared__ alignas(16) __nv_bfloat16 sBl[64 * SPAD];
    __shared__ float invs[128];

    const int z = blockIdx.y;
    const int b = z / NUM_HEADS, h = z % NUM_HEADS;
    const int rowbase = blockIdx.x * 128;
    const int tid = threadIdx.x, lane = tid & 31, wid = tid >> 5;
    const int warpM = (wid >> 1) * 32, warpN = (wid & 1) * 32;

    if (tid < 128) {
        const float* rp = &rowsum[((size_t)z * SS + rowbase + tid) * RS_W];
        float s = 0.0f;
#pragma unroll
        for (int j = 0; j < RS_W; j++) s += rp[j];
        invs[tid] = 1.0f / s;
    }
    __syncthreads();

    float* Az = attn + (size_t)z * SS * SS;
    const int arow = tid >> 1;
    const int acol = (tid & 1) * 16;
    const float inv = invs[arow];

    float acc[2][4][4];
#pragma unroll
    for (int mt = 0; mt < 2; mt++)
#pragma unroll
        for (int nt = 0; nt < 4; nt++)
#pragma unroll
            for (int r = 0; r < 4; r++) acc[mt][nt][r] = 0.0f;

    for (int k0 = 0; k0 < SS; k0 += 32) {
        // attn 128x32: load, normalize, write back, convert to bf16 hi/lo smem
        size_t base = (size_t)(rowbase + arow) * SS + k0 + acol;
#pragma unroll
        for (int j = 0; j < 4; j++) {
            float4 a = *(const float4*)&Az[base + j * 4];
            a.x *= inv; a.y *= inv; a.z *= inv; a.w *= inv;
            *(float4*)&Az[base + j * 4] = a;
            int so = arow * SPAD + acol + j * 4;
            __nv_bfloat16 h0 = __float2bfloat16(a.x);
            __nv_bfloat16 h1 = __float2bfloat16(a.y);
            __nv_bfloat16 h2 = __float2bfloat16(a.z);
            __nv_bfloat16 h3 = __float2bfloat16(a.w);
            sAh[so + 0] = h0; sAl[so + 0] = __float2bfloat16(a.x - __bfloat162float(h0));
            sAh[so + 1] = h1; sAl[so + 1] = __float2bfloat16(a.y - __bfloat162float(h1));
            sAh[so + 2] = h2; sAl[so + 2] = __float2bfloat16(a.z - __bfloat162float(h2));
            sAh[so + 3] = h3; sAl[so + 3] = __float2bfloat16(a.w - __bfloat162float(h3));
        }
        // v tiles: 64 d-rows x 32 keys bf16 (pre-split, [z][d][s])
        {
            int row = tid >> 2, q = tid & 3;
            size_t g = ((size_t)z * DEPTH + row) * SS + k0 + q * 8;
            *(uint4*)&sBh[row * SPAD + q * 8] = *(const uint4*)&vth[g];
            *(uint4*)&sBl[row * SPAD + q * 8] = *(const uint4*)&vtl[g];
        }
        __syncthreads();

#pragma unroll
        for (int ks = 0; ks < 2; ks++) {
            const int kb = ks * 16;
            uint32_t aH[2][4], aL[2][4], bH[4][2], bL[4][2];
#pragma unroll
            for (int mt = 0; mt < 2; mt++) {
#pragma unroll
                for (int r = 0; r < 4; r++) {
                    int row = warpM + mt * 16 + (lane >> 2) + 8 * (r & 1);
                    int col = kb + (lane & 3) * 2 + 8 * (r >> 1);
                    uint32_t off = (uint32_t)(row * SPAD + col) * 2;
                    aH[mt][r] = *(const uint32_t*)((const char*)sAh + off);
                    aL[mt][r] = *(const uint32_t*)((const char*)sAl + off);
                }
            }
#pragma unroll
            for (int nt = 0; nt < 4; nt++) {
#pragma unroll
                for (int r = 0; r < 2; r++) {
                    int n = warpN + nt * 8 + (lane >> 2);
                    int k = kb + (lane & 3) * 2 + 8 * r;
                    uint32_t off = (uint32_t)(n * SPAD + k) * 2;
                    bH[nt][r] = *(const uint32_t*)((const char*)sBh + off);
                    bL[nt][r] = *(const uint32_t*)((const char*)sBl + off);
                }
            }
#pragma unroll
            for (int mt = 0; mt < 2; mt++)
#pragma unroll
                for (int nt = 0; nt < 4; nt++) {
                    MMA16816(acc[mt][nt], aH[mt], bH[nt]);
                    MMA16816(acc[mt][nt], aH[mt], bL[nt]);
                    MMA16816(acc[mt][nt], aL[mt], bH[nt]);
                }
        }
        __syncthreads();
    }

#pragma unroll
    for (int mt = 0; mt < 2; mt++) {
#pragma unroll
        for (int nt = 0; nt < 4; nt++) {
            int row0 = rowbase + warpM + mt * 16 + (lane >> 2);
            int col  = warpN + nt * 8 + (lane & 3) * 2;
#pragma unroll
            for (int half = 0; half < 2; half++) {
                int r = row0 + half * 8;
                float2 v = {acc[mt][nt][half * 2 + 0], acc[mt][nt][half * 2 + 1]};
                *(float2*)&O[((size_t)b * SS + r) * D_MODEL + h * DEPTH + col] = v;
            }
        }
    }
}

// =====================================================================
extern "C" void kernel_launch(void* const* d_in, const int* in_sizes, int n_in,
                              void* d_out, int out_size)
{
    const float* Q    = (const float*)d_in[0];
    const float* K    = (const float*)d_in[1];
    const float* V    = (const float*)d_in[2];
    const float* mask = (const float*)d_in[3];
    const float* Wq   = (const float*)d_in[4];
    const float* bq   = (const float*)d_in[5];
    const float* Wk   = (const float*)d_in[6];
    const float* bk   = (const float*)d_in[7];
    const float* Wv   = (const float*)d_in[8];
    const float* bv   = (const float*)d_in[9];
    const float* Wo   = (const float*)d_in[10];
    const float* bo   = (const float*)d_in[11];

    float* out = (float*)d_out;

    float *qf, *kf, *vf, *oh, *rowsum, *attn;
    __nv_bfloat16 *ah, *al, *wh, *wl, *qhh, *qll, *khh, *kll, *vth, *vtl;
    cudaGetSymbolAddress((void**)&qf, g_q);
    cudaGetSymbolAddress((void**)&kf, g_k);
    cudaGetSymbolAddress((void**)&vf, g_v);
    cudaGetSymbolAddress((void**)&oh, g_o);
    cudaGetSymbolAddress((void**)&rowsum, g_rowsum);
    cudaGetSymbolAddress((void**)&ah, g_a_hi);
    cudaGetSymbolAddress((void**)&al, g_a_lo);
    cudaGetSymbolAddress((void**)&wh, g_wt_hi);
    cudaGetSymbolAddress((void**)&wl, g_wt_lo);
    cudaGetSymbolAddress((void**)&qhh, g_q_hi);
    cudaGetSymbolAddress((void**)&qll, g_q_lo);
    cudaGetSymbolAddress((void**)&khh, g_k_hi);
    cudaGetSymbolAddress((void**)&kll, g_k_lo);
    cudaGetSymbolAddress((void**)&vth, g_vt_hi);
    cudaGetSymbolAddress((void**)&vtl, g_vt_lo);

    if ((size_t)out_size >= OUT_ELEMS + ATTN_ELEMS) {
        attn = out + OUT_ELEMS;
    } else {
        cudaGetSymbolAddress((void**)&attn, g_attn_fallback);
    }

    static bool attr_done = false;
    if (!attr_done) {
        cudaFuncSetAttribute(scores_mma_kernel, cudaFuncAttributeMaxDynamicSharedMemorySize,
                             4 * 128 * QPAD * 2);
        attr_done = true;
    }

    const int NELEM = MROWS * D_MODEL;
    const int NQK   = NZ * SS * DEPTH;       // 4,194,304
    dim3 wtGrid(32, 32), wtBlock(32, 8);
    dim3 projGrid(8, 32);

    // projections
    split_wt_kernel<<<wtGrid, wtBlock>>>(Wq, wh, wl);
    split_a_kernel<<<NELEM / 256, 256>>>(Q, ah, al, NELEM);
    proj_mma_kernel<1><<<projGrid, 256>>>(ah, al, wh, wl, bq, qf);

    split_wt_kernel<<<wtGrid, wtBlock>>>(Wk, wh, wl);
    split_a_kernel<<<NELEM / 256, 256>>>(K, ah, al, NELEM);
    proj_mma_kernel<1><<<projGrid, 256>>>(ah, al, wh, wl, bk, kf);

    split_wt_kernel<<<wtGrid, wtBlock>>>(Wv, wh, wl);
    split_a_kernel<<<NELEM / 256, 256>>>(V, ah, al, NELEM);
    proj_mma_kernel<1><<<projGrid, 256>>>(ah, al, wh, wl, bv, vf);

    // bf16 operand prep for attention
    split_a_kernel<<<NQK / 256, 256>>>(qf, qhh, qll, NQK);
    split_a_kernel<<<NQK / 256, 256>>>(kf, khh, kll, NQK);
    dim3 vtGrid(SS / 32, DEPTH / 32, NZ);
    trans_split_v<<<vtGrid, wtBlock>>>(vf, vth, vtl);

    // scores (tensor core) + exp + rowsum partials
    dim3 scoreGrid(16, 16, NZ);
    scores_mma_kernel<<<scoreGrid, 256, 4 * 128 * QPAD * 2>>>(qhh, qll, khh, kll,
                                                              mask, attn, rowsum);

    // AV (tensor core) + normalize + attn writeback
    dim3 avGrid(16, NZ);
    av_mma_kernel<<<avGrid, 256>>>(attn, vth, vtl, rowsum, oh);

    // output projection
    split_wt_kernel<<<wtGrid, wtBlock>>>(Wo, wh, wl);
    split_a_kernel<<<NELEM / 256, 256>>>(oh, ah, al, NELEM);
    proj_mma_kernel<0><<<projGrid, 256>>>(ah, al, wh, wl, bo, out);
}

// round 5
// speedup vs baseline: 2.0034x; 1.0740x over previous
#include <cuda_runtime.h>
#include <cuda_bf16.h>
#include <cstdint>
#include <math.h>

#define D_MODEL   1024
#define NUM_HEADS 16
#define DEPTH     64
#define BB        2
#define SS        2048
#define MROWS     (BB * SS)                              // 4096
#define ATTN_ELEMS ((size_t)BB * NUM_HEADS * SS * SS)    // 134,217,728
#define OUT_ELEMS  ((size_t)MROWS * D_MODEL)             // 4,194,304
#define NZ        (BB * NUM_HEADS)                       // 32
#define RS_W      64

// ---------------- scratch (static device globals; no allocations) ------------
__device__ float g_rowsum[(size_t)NZ * SS * RS_W];
__device__ __nv_bfloat16 g_a_hi[(size_t)MROWS * D_MODEL];
__device__ __nv_bfloat16 g_a_lo[(size_t)MROWS * D_MODEL];
__device__ __nv_bfloat16 g_wt_hi[(size_t)D_MODEL * D_MODEL];  // [n][k]
__device__ __nv_bfloat16 g_wt_lo[(size_t)D_MODEL * D_MODEL];
__device__ __nv_bfloat16 g_q_hi[(size_t)NZ * SS * DEPTH];     // [z,s,d]
__device__ __nv_bfloat16 g_q_lo[(size_t)NZ * SS * DEPTH];
__device__ __nv_bfloat16 g_k_hi[(size_t)NZ * SS * DEPTH];
__device__ __nv_bfloat16 g_k_lo[(size_t)NZ * SS * DEPTH];
__device__ __nv_bfloat16 g_vt_hi[(size_t)NZ * SS * DEPTH];    // [z,d,s]
__device__ __nv_bfloat16 g_vt_lo[(size_t)NZ * SS * DEPTH];
__device__ float g_attn_fallback[ATTN_ELEMS];

// ============================ PTX helpers ====================================
#define MMA16816(d, a, b)                                                     \
    asm volatile("mma.sync.aligned.m16n8k16.row.col.f32.bf16.bf16.f32 "       \
        "{%0,%1,%2,%3}, {%4,%5,%6,%7}, {%8,%9}, {%0,%1,%2,%3};"               \
        : "+f"((d)[0]), "+f"((d)[1]), "+f"((d)[2]), "+f"((d)[3])              \
        : "r"((a)[0]), "r"((a)[1]), "r"((a)[2]), "r"((a)[3]),                 \
          "r"((b)[0]), "r"((b)[1]))

#define LDSM4(R0, R1, R2, R3, ADDR)                                           \
    asm volatile("ldmatrix.sync.aligned.m8n8.x4.shared.b16 {%0,%1,%2,%3}, [%4];" \
        : "=r"(R0), "=r"(R1), "=r"(R2), "=r"(R3) : "r"(ADDR))

#define CP16(SADDR, GPTR)                                                     \
    asm volatile("cp.async.cg.shared.global [%0], [%1], 16;"                  \
        :: "r"(SADDR), "l"(GPTR))
#define CP_COMMIT() asm volatile("cp.async.commit_group;" ::: "memory")
#define CP_WAIT1()  asm volatile("cp.async.wait_group 1;" ::: "memory")
#define CP_WAIT0()  asm volatile("cp.async.wait_group 0;" ::: "memory")

__device__ __forceinline__ uint32_t smem_u32(const void* p) {
    uint32_t a;
    asm("{ .reg .u64 t; cvta.to.shared.u64 t, %1; cvt.u32.u64 %0, t; }" : "=r"(a) : "l"(p));
    return a;
}

// ============================ split kernels ==================================
__global__ __launch_bounds__(256)
void split_a_kernel(const float* __restrict__ A, __nv_bfloat16* __restrict__ hi,
                    __nv_bfloat16* __restrict__ lo, int n)
{
    int i = blockIdx.x * 256 + threadIdx.x;
    if (i < n) {
        float x = A[i];
        __nv_bfloat16 h = __float2bfloat16(x);
        hi[i] = h;
        lo[i] = __float2bfloat16(x - __bfloat162float(h));
    }
}

__global__ __launch_bounds__(256)
void split_wt_kernel(const float* __restrict__ W, __nv_bfloat16* __restrict__ hi,
                     __nv_bfloat16* __restrict__ lo)
{
    __shared__ float t[32][33];
    int tx = threadIdx.x, ty = threadIdx.y;           // block (32, 8)
    int n0 = blockIdx.x * 32, k0 = blockIdx.y * 32;
#pragma unroll
    for (int j = 0; j < 4; j++)
        t[ty + j * 8][tx] = W[(size_t)(k0 + ty + j * 8) * D_MODEL + n0 + tx];
    __syncthreads();
#pragma unroll
    for (int j = 0; j < 4; j++) {
        float x = t[tx][ty + j * 8];
        __nv_bfloat16 h = __float2bfloat16(x);
        size_t o = (size_t)(n0 + ty + j * 8) * D_MODEL + k0 + tx;
        hi[o] = h;
        lo[o] = __float2bfloat16(x - __bfloat162float(h));
    }
}

// ==================== projection GEMM v2 (cp.async + ldmatrix) ===============
// LAYOUT 0: fp32 row-major C.   LAYOUT 1: bf16 hi/lo split-heads [z][s][d].
// LAYOUT 2: bf16 hi/lo transposed [z][d][s]  (for V).
#define SPAD 40
#define STAGE_BYTES 40960     // 4 arrays * 128*40*2
#define OFF_AH 0
#define OFF_AL 10240
#define OFF_BH 20480
#define OFF_BL 30720

template <int LAYOUT>
__global__ __launch_bounds__(256, 1)
void proj_mma_kernel(const __nv_bfloat16* __restrict__ a_hi, const __nv_bfloat16* __restrict__ a_lo,
                     const __nv_bfloat16* __restrict__ w_hi, const __nv_bfloat16* __restrict__ w_lo,
                     const float* __restrict__ bias, float* __restrict__ C,
                     __nv_bfloat16* __restrict__ out_hi, __nv_bfloat16* __restrict__ out_lo)
{
    extern __shared__ char smem[];
    const uint32_t sb0 = smem_u32(smem);

    const int tid  = threadIdx.x;
    const int lane = tid & 31;
    const int wid  = tid >> 5;
    const int warpM = (wid >> 2) * 64;
    const int warpN = (wid & 3) * 32;
    const int blockRow = blockIdx.y * 128;
    const int blockCol = blockIdx.x * 128;

    // per-thread load indices: 2 chunks of 16B per array
    const int ldRow0 = tid >> 2;              // rows 0..63   (j=0)
    const int ldQ    = (tid & 3) * 16;        // byte offset in 64B row
    // ldmatrix lane geometry
    const int lmRow = lane & 15;
    const int lmK   = (lane >> 4) * 8;

    float acc[4][4][4];
#pragma unroll
    for (int mt = 0; mt < 4; mt++)
#pragma unroll
        for (int nt = 0; nt < 4; nt++)
#pragma unroll
            for (int r = 0; r < 4; r++) acc[mt][nt][r] = 0.0f;

    auto load_stage = [&](int stage, int chunk) {
        const int k0 = chunk * 32;
        const uint32_t sb = sb0 + stage * STAGE_BYTES;
#pragma unroll
        for (int j = 0; j < 2; j++) {
            int row = ldRow0 + j * 64;
            uint32_t so = (uint32_t)(row * 80) + ldQ;
            const __nv_bfloat16* gA = &a_hi[(size_t)(blockRow + row) * D_MODEL + k0] + ldQ / 2;
            const __nv_bfloat16* gAl = &a_lo[(size_t)(blockRow + row) * D_MODEL + k0] + ldQ / 2;
            const __nv_bfloat16* gB = &w_hi[(size_t)(blockCol + row) * D_MODEL + k0] + ldQ / 2;
            const __nv_bfloat16* gBl = &w_lo[(size_t)(blockCol + row) * D_MODEL + k0] + ldQ / 2;
            CP16(sb + OFF_AH + so, gA);
            CP16(sb + OFF_AL + so, gAl);
            CP16(sb + OFF_BH + so, gB);
            CP16(sb + OFF_BL + so, gBl);
        }
        CP_COMMIT();
    };

    load_stage(0, 0);

    for (int chunk = 0; chunk < 32; chunk++) {
        if (chunk < 31) load_stage((chunk + 1) & 1, chunk + 1);
        if (chunk < 31) { CP_WAIT1(); } else { CP_WAIT0(); }
        __syncthreads();

        const uint32_t sb = sb0 + (chunk & 1) * STAGE_BYTES;
        const uint32_t aAddrBase = sb + (uint32_t)(((warpM + lmRow) * SPAD + lmK) * 2);
        const uint32_t bAddrBase = sb + (uint32_t)(((warpN + lmRow) * SPAD + lmK) * 2);

#pragma unroll
        for (int ks = 0; ks < 2; ks++) {
            const uint32_t kOff = (uint32_t)(ks * 16 * 2);
            uint32_t aH[4][4], aL[4][4], bH[4][2], bL[4][2];
#pragma unroll
            for (int mt = 0; mt < 4; mt++) {
                uint32_t ad = aAddrBase + kOff + (uint32_t)(mt * 16 * SPAD * 2);
                LDSM4(aH[mt][0], aH[mt][1], aH[mt][2], aH[mt][3], ad + OFF_AH);
                LDSM4(aL[mt][0], aL[mt][1], aL[mt][2], aL[mt][3], ad + OFF_AL);
            }
#pragma unroll
            for (int ntp = 0; ntp < 2; ntp++) {
                uint32_t bd = bAddrBase + kOff + (uint32_t)(ntp * 16 * SPAD * 2);
                uint32_t r0, r1, r2, r3;
                LDSM4(r0, r1, r2, r3, bd + OFF_BH);
                bH[2 * ntp][0] = r0; bH[2 * ntp + 1][0] = r1;
                bH[2 * ntp][1] = r2; bH[2 * ntp + 1][1] = r3;
                LDSM4(r0, r1, r2, r3, bd + OFF_BL);
                bL[2 * ntp][0] = r0; bL[2 * ntp + 1][0] = r1;
                bL[2 * ntp][1] = r2; bL[2 * ntp + 1][1] = r3;
            }
#pragma unroll
            for (int mt = 0; mt < 4; mt++)
#pragma unroll
                for (int nt = 0; nt < 4; nt++) {
                    MMA16816(acc[mt][nt], aH[mt], bH[nt]);
                    MMA16816(acc[mt][nt], aH[mt], bL[nt]);
                    MMA16816(acc[mt][nt], aL[mt], bH[nt]);
                }
        }
        __syncthreads();
    }

    // epilogue
#pragma unroll
    for (int mt = 0; mt < 4; mt++) {
#pragma unroll
        for (int nt = 0; nt < 4; nt++) {
            int row0 = blockRow + warpM + mt * 16 + (lane >> 2);
            int col  = blockCol + warpN + nt * 8 + (lane & 3) * 2;
            float b0 = bias[col], b1 = bias[col + 1];
#pragma unroll
            for (int half = 0; half < 2; half++) {
                int r = row0 + half * 8;
                float vx = acc[mt][nt][half * 2 + 0] + b0;
                float vy = acc[mt][nt][half * 2 + 1] + b1;
                if (LAYOUT == 0) {
                    float2 v = {vx, vy};
                    *(float2*)&C[(size_t)r * D_MODEL + col] = v;
                } else if (LAYOUT == 1) {
                    int z = (r >> 11) * NUM_HEADS + (col >> 6);
                    int s = r & (SS - 1);
                    int d = col & (DEPTH - 1);
                    size_t o = ((size_t)z * SS + s) * DEPTH + d;
                    __nv_bfloat16 hx = __float2bfloat16(vx);
                    __nv_bfloat16 hy = __float2bfloat16(vy);
                    __nv_bfloat162 hp = {hx, hy};
                    *(__nv_bfloat162*)&out_hi[o] = hp;
                    __nv_bfloat162 lp = {__float2bfloat16(vx - __bfloat162float(hx)),
                                         __float2bfloat16(vy - __bfloat162float(hy))};
                    *(__nv_bfloat162*)&out_lo[o] = lp;
                } else {
                    int z = (r >> 11) * NUM_HEADS + (col >> 6);
                    int s = r & (SS - 1);
                    int d = col & (DEPTH - 1);
                    size_t o = ((size_t)z * DEPTH + d) * SS + s;
                    __nv_bfloat16 hx = __float2bfloat16(vx);
                    __nv_bfloat16 hy = __float2bfloat16(vy);
                    out_hi[o]      = hx;
                    out_hi[o + SS] = hy;
                    out_lo[o]      = __float2bfloat16(vx - __bfloat162float(hx));
                    out_lo[o + SS] = __float2bfloat16(vy - __bfloat162float(hy));
                }
            }
        }
    }
}

// ==================== scores: mma.sync + exp + rowsum partials ===============
#define QPAD 72

__global__ __launch_bounds__(256)
void scores_mma_kernel(const __nv_bfloat16* __restrict__ qh, const __nv_bfloat16* __restrict__ ql,
                       const __nv_bfloat16* __restrict__ kh, const __nv_bfloat16* __restrict__ kl,
                       const float* __restrict__ mask, float* __restrict__ attn,
                       float* __restrict__ rowsum)
{
    extern __shared__ char sm[];
    const uint32_t sq = smem_u32(sm);
    __nv_bfloat16* sQh = (__nv_bfloat16*)sm;
    __nv_bfloat16* sQl = sQh + 128 * QPAD;
    __nv_bfloat16* sKh = sQl + 128 * QPAD;
    __nv_bfloat16* sKl = sKh + 128 * QPAD;
    const uint32_t OQH = 0, OQL = 128 * QPAD * 2, OKH = 2 * 128 * QPAD * 2, OKL = 3 * 128 * QPAD * 2;

    const int z = blockIdx.z;
    const int b = z / NUM_HEADS;
    const int tid = threadIdx.x, lane = tid & 31, wid = tid >> 5;
    const int warpM = (wid >> 2) * 64, warpN = (wid & 3) * 32;
    const int blockRow = blockIdx.y * 128, blockCol = blockIdx.x * 128;
    const int lmRow = lane & 15, lmK = (lane >> 4) * 8;

#pragma unroll
    for (int i = 0; i < 4; i++) {
        int id = tid + i * 256;
        int row = id >> 3, q = id & 7;
        size_t gq = ((size_t)z * SS + blockRow + row) * DEPTH + q * 8;
        size_t gk = ((size_t)z * SS + blockCol + row) * DEPTH + q * 8;
        int so = row * QPAD + q * 8;
        *(uint4*)&sQh[so] = *(const uint4*)&qh[gq];
        *(uint4*)&sQl[so] = *(const uint4*)&ql[gq];
        *(uint4*)&sKh[so] = *(const uint4*)&kh[gk];
        *(uint4*)&sKl[so] = *(const uint4*)&kl[gk];
    }
    __syncthreads();

    float acc[4][4][4];
#pragma unroll
    for (int mt = 0; mt < 4; mt++)
#pragma unroll
        for (int nt = 0; nt < 4; nt++)
#pragma unroll
            for (int r = 0; r < 4; r++) acc[mt][nt][r] = 0.0f;

    const uint32_t aAddrBase = sq + (uint32_t)(((warpM + lmRow) * QPAD + lmK) * 2);
    const uint32_t bAddrBase = sq + (uint32_t)(((warpN + lmRow) * QPAD + lmK) * 2);

#pragma unroll
    for (int ks = 0; ks < 4; ks++) {
        const uint32_t kOff = (uint32_t)(ks * 16 * 2);
        uint32_t aH[4][4], aL[4][4], bH[4][2], bL[4][2];
#pragma unroll
        for (int mt = 0; mt < 4; mt++) {
            uint32_t ad = aAddrBase + kOff + (uint32_t)(mt * 16 * QPAD * 2);
            LDSM4(aH[mt][0], aH[mt][1], aH[mt][2], aH[mt][3], ad + OQH);
            LDSM4(aL[mt][0], aL[mt][1], aL[mt][2], aL[mt][3], ad + OQL);
        }
#pragma unroll
        for (int ntp = 0; ntp < 2; ntp++) {
            uint32_t bd = bAddrBase + kOff + (uint32_t)(ntp * 16 * QPAD * 2);
            uint32_t r0, r1, r2, r3;
            LDSM4(r0, r1, r2, r3, bd + OKH);
            bH[2 * ntp][0] = r0; bH[2 * ntp + 1][0] = r1;
            bH[2 * ntp][1] = r2; bH[2 * ntp + 1][1] = r3;
            LDSM4(r0, r1, r2, r3, bd + OKL);
            bL[2 * ntp][0] = r0; bL[2 * ntp + 1][0] = r1;
            bL[2 * ntp][1] = r2; bL[2 * ntp + 1][1] = r3;
        }
#pragma unroll
        for (int mt = 0; mt < 4; mt++)
#pragma unroll
            for (int nt = 0; nt < 4; nt++) {
                MMA16816(acc[mt][nt], aH[mt], bH[nt]);
                MMA16816(acc[mt][nt], aH[mt], bL[nt]);
                MMA16816(acc[mt][nt], aL[mt], bH[nt]);
            }
    }

    float mcol[4][2];
#pragma unroll
    for (int nt = 0; nt < 4; nt++) {
        int col = blockCol + warpN + nt * 8 + (lane & 3) * 2;
        mcol[nt][0] = mask[(size_t)b * SS + col]     * (-1e9f);
        mcol[nt][1] = mask[(size_t)b * SS + col + 1] * (-1e9f);
    }
    float* Cz = attn + (size_t)z * SS * SS;

#pragma unroll
    for (int mt = 0; mt < 4; mt++) {
#pragma unroll
        for (int half = 0; half < 2; half++) {
            int row = blockRow + warpM + mt * 16 + (lane >> 2) + half * 8;
            float rs = 0.0f;
#pragma unroll
            for (int nt = 0; nt < 4; nt++) {
                int col = blockCol + warpN + nt * 8 + (lane & 3) * 2;
                float e0 = __expf(acc[mt][nt][half * 2 + 0] * 0.125f + mcol[nt][0]);
                float e1 = __expf(acc[mt][nt][half * 2 + 1] * 0.125f + mcol[nt][1]);
                rs += e0 + e1;
                float2 v = {e0, e1};
                *(float2*)&Cz[(size_t)row * SS + col] = v;
            }
            rs += __shfl_xor_sync(0xffffffffu, rs, 1);
            rs += __shfl_xor_sync(0xffffffffu, rs, 2);
            if ((lane & 3) == 0)
                rowsum[((size_t)z * SS + row) * RS_W + blockIdx.x * 4 + (wid & 3)] = rs;
        }
    }
}

// ==================== AV: normalize + writeback + mma.sync ===================
__global__ __launch_bounds__(256)
void av_mma_kernel(float* __restrict__ attn,
                   const __nv_bfloat16* __restrict__ vth, const __nv_bfloat16* __restrict__ vtl,
                   const float* __restrict__ rowsum,
                   __nv_bfloat16* __restrict__ o_hi, __nv_bfloat16* __restrict__ o_lo)
{
    __shared__ alignas(16) __nv_bfloat16 sAh[128 * SPAD];
    __shared__ alignas(16) __nv_bfloat16 sAl[128 * SPAD];
    __shared__ alignas(16) __nv_bfloat16 sBh[64 * SPAD];
    __shared__ alignas(16) __nv_bfloat16 sBl[64 * SPAD];
    __shared__ float invs[128];

    const uint32_t aAh = smem_u32(sAh), aAl = smem_u32(sAl);
    const uint32_t aBh = smem_u32(sBh), aBl = smem_u32(sBl);

    const int z = blockIdx.y;
    const int b = z / NUM_HEADS, h = z % NUM_HEADS;
    const int rowbase = blockIdx.x * 128;
    const int tid = threadIdx.x, lane = tid & 31, wid = tid >> 5;
    const int warpM = (wid >> 1) * 32, warpN = (wid & 1) * 32;
    const int lmRow = lane & 15, lmK = (lane >> 4) * 8;

    if (tid < 128) {
        const float* rp = &rowsum[((size_t)z * SS + rowbase + tid) * RS_W];
        float s = 0.0f;
#pragma unroll
        for (int j = 0; j < RS_W; j++) s += rp[j];
        invs[tid] = 1.0f / s;
    }
    __syncthreads();

    float* Az = attn + (size_t)z * SS * SS;
    const int arow = tid >> 1;
    const int acol = (tid & 1) * 16;
    const float inv = invs[arow];

    float acc[2][4][4];
#pragma unroll
    for (int mt = 0; mt < 2; mt++)
#pragma unroll
        for (int nt = 0; nt < 4; nt++)
#pragma unroll
            for (int r = 0; r < 4; r++) acc[mt][nt][r] = 0.0f;

    for (int k0 = 0; k0 < SS; k0 += 32) {
        size_t base = (size_t)(rowbase + arow) * SS + k0 + acol;
#pragma unroll
        for (int j = 0; j < 4; j++) {
            float4 a = *(const float4*)&Az[base + j * 4];
            a.x *= inv; a.y *= inv; a.z *= inv; a.w *= inv;
            *(float4*)&Az[base + j * 4] = a;
            int so = arow * SPAD + acol + j * 4;
            __nv_bfloat16 h0 = __float2bfloat16(a.x);
            __nv_bfloat16 h1 = __float2bfloat16(a.y);
            __nv_bfloat16 h2 = __float2bfloat16(a.z);
            __nv_bfloat16 h3 = __float2bfloat16(a.w);
            sAh[so + 0] = h0; sAl[so + 0] = __float2bfloat16(a.x - __bfloat162float(h0));
            sAh[so + 1] = h1; sAl[so + 1] = __float2bfloat16(a.y - __bfloat162float(h1));
            sAh[so + 2] = h2; sAl[so + 2] = __float2bfloat16(a.z - __bfloat162float(h2));
            sAh[so + 3] = h3; sAl[so + 3] = __float2bfloat16(a.w - __bfloat162float(h3));
        }
        {
            int row = tid >> 2, q = tid & 3;
            size_t g = ((size_t)z * DEPTH + row) * SS + k0 + q * 8;
            *(uint4*)&sBh[row * SPAD + q * 8] = *(const uint4*)&vth[g];
            *(uint4*)&sBl[row * SPAD + q * 8] = *(const uint4*)&vtl[g];
        }
        __syncthreads();

        const uint32_t aBase = (uint32_t)(((warpM + lmRow) * SPAD + lmK) * 2);
        const uint32_t bBase = (uint32_t)(((warpN + lmRow) * SPAD + lmK) * 2);

#pragma unroll
        for (int ks = 0; ks < 2; ks++) {
            const uint32_t kOff = (uint32_t)(ks * 16 * 2);
            uint32_t aH[2][4], aL[2][4], bH[4][2], bL[4][2];
#pragma unroll
            for (int mt = 0; mt < 2; mt++) {
                uint32_t ad = aBase + kOff + (uint32_t)(mt * 16 * SPAD * 2);
                LDSM4(aH[mt][0], aH[mt][1], aH[mt][2], aH[mt][3], aAh + ad);
                LDSM4(aL[mt][0], aL[mt][1], aL[mt][2], aL[mt][3], aAl + ad);
            }
#pragma unroll
            for (int ntp = 0; ntp < 2; ntp++) {
                uint32_t bd = bBase + kOff + (uint32_t)(ntp * 16 * SPAD * 2);
                uint32_t r0, r1, r2, r3;
                LDSM4(r0, r1, r2, r3, aBh + bd);
                bH[2 * ntp][0] = r0; bH[2 * ntp + 1][0] = r1;
                bH[2 * ntp][1] = r2; bH[2 * ntp + 1][1] = r3;
                LDSM4(r0, r1, r2, r3, aBl + bd);
                bL[2 * ntp][0] = r0; bL[2 * ntp + 1][0] = r1;
                bL[2 * ntp][1] = r2; bL[2 * ntp + 1][1] = r3;
            }
#pragma unroll
            for (int mt = 0; mt < 2; mt++)
#pragma unroll
                for (int nt = 0; nt < 4; nt++) {
                    MMA16816(acc[mt][nt], aH[mt], bH[nt]);
                    MMA16816(acc[mt][nt], aH[mt], bL[nt]);
                    MMA16816(acc[mt][nt], aL[mt], bH[nt]);
                }
        }
        __syncthreads();
    }

#pragma unroll
    for (int mt = 0; mt < 2; mt++) {
#pragma unroll
        for (int nt = 0; nt < 4; nt++) {
            int row0 = rowbase + warpM + mt * 16 + (lane >> 2);
            int col  = warpN + nt * 8 + (lane & 3) * 2;
#pragma unroll
            for (int half = 0; half < 2; half++) {
                int r = row0 + half * 8;
                float vx = acc[mt][nt][half * 2 + 0];
                float vy = acc[mt][nt][half * 2 + 1];
                size_t o = ((size_t)b * SS + r) * D_MODEL + h * DEPTH + col;
                __nv_bfloat16 hx = __float2bfloat16(vx);
                __nv_bfloat16 hy = __float2bfloat16(vy);
                __nv_bfloat162 hp = {hx, hy};
                *(__nv_bfloat162*)&o_hi[o] = hp;
                __nv_bfloat162 lp = {__float2bfloat16(vx - __bfloat162float(hx)),
                                     __float2bfloat16(vy - __bfloat162float(hy))};
                *(__nv_bfloat162*)&o_lo[o] = lp;
            }
        }
    }
}

// =====================================================================
extern "C" void kernel_launch(void* const* d_in, const int* in_sizes, int n_in,
                              void* d_out, int out_size)
{
    const float* Q    = (const float*)d_in[0];
    const float* K    = (const float*)d_in[1];
    const float* V    = (const float*)d_in[2];
    const float* mask = (const float*)d_in[3];
    const float* Wq   = (const float*)d_in[4];
    const float* bq   = (const float*)d_in[5];
    const float* Wk   = (const float*)d_in[6];
    const float* bk   = (const float*)d_in[7];
    const float* Wv   = (const float*)d_in[8];
    const float* bv   = (const float*)d_in[9];
    const float* Wo   = (const float*)d_in[10];
    const float* bo   = (const float*)d_in[11];

    float* out = (float*)d_out;

    float *rowsum, *attn;
    __nv_bfloat16 *ah, *al, *wh, *wl, *qhh, *qll, *khh, *kll, *vth, *vtl;
    cudaGetSymbolAddress((void**)&rowsum, g_rowsum);
    cudaGetSymbolAddress((void**)&ah, g_a_hi);
    cudaGetSymbolAddress((void**)&al, g_a_lo);
    cudaGetSymbolAddress((void**)&wh, g_wt_hi);
    cudaGetSymbolAddress((void**)&wl, g_wt_lo);
    cudaGetSymbolAddress((void**)&qhh, g_q_hi);
    cudaGetSymbolAddress((void**)&qll, g_q_lo);
    cudaGetSymbolAddress((void**)&khh, g_k_hi);
    cudaGetSymbolAddress((void**)&kll, g_k_lo);
    cudaGetSymbolAddress((void**)&vth, g_vt_hi);
    cudaGetSymbolAddress((void**)&vtl, g_vt_lo);

    if ((size_t)out_size >= OUT_ELEMS + ATTN_ELEMS) {
        attn = out + OUT_ELEMS;
    } else {
        cudaGetSymbolAddress((void**)&attn, g_attn_fallback);
    }

    static bool attr_done = false;
    if (!attr_done) {
        cudaFuncSetAttribute(proj_mma_kernel<0>, cudaFuncAttributeMaxDynamicSharedMemorySize, 2 * STAGE_BYTES);
        cudaFuncSetAttribute(proj_mma_kernel<1>, cudaFuncAttributeMaxDynamicSharedMemorySize, 2 * STAGE_BYTES);
        cudaFuncSetAttribute(proj_mma_kernel<2>, cudaFuncAttributeMaxDynamicSharedMemorySize, 2 * STAGE_BYTES);
        cudaFuncSetAttribute(scores_mma_kernel, cudaFuncAttributeMaxDynamicSharedMemorySize, 4 * 128 * QPAD * 2);
        attr_done = true;
    }

    const int NELEM = MROWS * D_MODEL;
    dim3 wtGrid(32, 32), wtBlock(32, 8);
    dim3 projGrid(8, 32);

    // Q projection -> bf16 hi/lo split-heads
    split_wt_kernel<<<wtGrid, wtBlock>>>(Wq, wh, wl);
    split_a_kernel<<<NELEM / 256, 256>>>(Q, ah, al, NELEM);
    proj_mma_kernel<1><<<projGrid, 256, 2 * STAGE_BYTES>>>(ah, al, wh, wl, bq, nullptr, qhh, qll);

    // K projection
    split_wt_kernel<<<wtGrid, wtBlock>>>(Wk, wh, wl);
    split_a_kernel<<<NELEM / 256, 256>>>(K, ah, al, NELEM);
    proj_mma_kernel<1><<<projGrid, 256, 2 * STAGE_BYTES>>>(ah, al, wh, wl, bk, nullptr, khh, kll);

    // V projection -> transposed bf16 hi/lo [z][d][s]
    split_wt_kernel<<<wtGrid, wtBlock>>>(Wv, wh, wl);
    split_a_kernel<<<NELEM / 256, 256>>>(V, ah, al, NELEM);
    proj_mma_kernel<2><<<projGrid, 256, 2 * STAGE_BYTES>>>(ah, al, wh, wl, bv, nullptr, vth, vtl);

    // scores (tensor core) + exp + rowsum partials
    dim3 scoreGrid(16, 16, NZ);
    scores_mma_kernel<<<scoreGrid, 256, 4 * 128 * QPAD * 2>>>(qhh, qll, khh, kll,
                                                              mask, attn, rowsum);

    // AV (tensor core) + normalize + attn writeback; O emitted as bf16 hi/lo
    dim3 avGrid(16, NZ);
    av_mma_kernel<<<avGrid, 256>>>(attn, vth, vtl, rowsum, ah, al);

    // output projection (reads O hi/lo directly)
    split_wt_kernel<<<wtGrid, wtBlock>>>(Wo, wh, wl);
    proj_mma_kernel<0><<<projGrid, 256, 2 * STAGE_BYTES>>>(ah, al, wh, wl, bo, out, nullptr, nullptr);
}

// round 6
// speedup vs baseline: 2.3568x; 1.1764x over previous
#include <cuda_runtime.h>
#include <cuda_bf16.h>
#include <cuda_fp16.h>
#include <cstdint>
#include <math.h>

#define D_MODEL   1024
#define NUM_HEADS 16
#define DEPTH     64
#define BB        2
#define SS        2048
#define MROWS     (BB * SS)                              // 4096
#define ATTN_ELEMS ((size_t)BB * NUM_HEADS * SS * SS)    // 134,217,728
#define OUT_ELEMS  ((size_t)MROWS * D_MODEL)             // 4,194,304
#define NZ        (BB * NUM_HEADS)                       // 32
#define RS_W      64
#define NELEM     (MROWS * D_MODEL)                      // 4,194,304
#define WELEM     (D_MODEL * D_MODEL)                    // 1,048,576

// ---------------- scratch (static device globals; no allocations) ------------
__device__ float g_rowsum[(size_t)NZ * SS * RS_W];
__device__ __nv_bfloat16 g_in_hi[3 * (size_t)NELEM];     // QKV inputs, bf16 hi
__device__ __nv_bfloat16 g_in_lo[3 * (size_t)NELEM];
__device__ __nv_bfloat16 g_w_hi[4 * (size_t)WELEM];      // Wq,Wk,Wv,Wo [n][k]
__device__ __nv_bfloat16 g_w_lo[4 * (size_t)WELEM];
__device__ __half g_q_hi[(size_t)NZ * SS * DEPTH];       // [z,s,d] fp16
__device__ __half g_q_lo[(size_t)NZ * SS * DEPTH];
__device__ __half g_k_f[(size_t)NZ * SS * DEPTH];        // [z,s,d] fp16 single
__device__ __half g_vt_hi[(size_t)NZ * SS * DEPTH];      // [z,d,s] fp16
__device__ __half g_vt_lo[(size_t)NZ * SS * DEPTH];
__device__ __nv_bfloat16 g_o_hi[(size_t)NELEM];          // attn output O, bf16 hi/lo
__device__ __nv_bfloat16 g_o_lo[(size_t)NELEM];
__device__ float g_attn_fallback[ATTN_ELEMS];

// ============================ PTX helpers ====================================
#define MMABF(d, a, b)                                                        \
    asm volatile("mma.sync.aligned.m16n8k16.row.col.f32.bf16.bf16.f32 "       \
        "{%0,%1,%2,%3}, {%4,%5,%6,%7}, {%8,%9}, {%0,%1,%2,%3};"               \
        : "+f"((d)[0]), "+f"((d)[1]), "+f"((d)[2]), "+f"((d)[3])              \
        : "r"((a)[0]), "r"((a)[1]), "r"((a)[2]), "r"((a)[3]),                 \
          "r"((b)[0]), "r"((b)[1]))

#define MMAH(d, a, b)                                                         \
    asm volatile("mma.sync.aligned.m16n8k16.row.col.f32.f16.f16.f32 "         \
        "{%0,%1,%2,%3}, {%4,%5,%6,%7}, {%8,%9}, {%0,%1,%2,%3};"               \
        : "+f"((d)[0]), "+f"((d)[1]), "+f"((d)[2]), "+f"((d)[3])              \
        : "r"((a)[0]), "r"((a)[1]), "r"((a)[2]), "r"((a)[3]),                 \
          "r"((b)[0]), "r"((b)[1]))

#define LDSM4(R0, R1, R2, R3, ADDR)                                           \
    asm volatile("ldmatrix.sync.aligned.m8n8.x4.shared.b16 {%0,%1,%2,%3}, [%4];" \
        : "=r"(R0), "=r"(R1), "=r"(R2), "=r"(R3) : "r"(ADDR))

#define CP16(SADDR, GPTR)                                                     \
    asm volatile("cp.async.cg.shared.global [%0], [%1], 16;"                  \
        :: "r"(SADDR), "l"(GPTR))
#define CP_COMMIT() asm volatile("cp.async.commit_group;" ::: "memory")
#define CP_WAIT1()  asm volatile("cp.async.wait_group 1;" ::: "memory")
#define CP_WAIT0()  asm volatile("cp.async.wait_group 0;" ::: "memory")

__device__ __forceinline__ uint32_t smem_u32(const void* p) {
    uint32_t a;
    asm("{ .reg .u64 t; cvta.to.shared.u64 t, %1; cvt.u32.u64 %0, t; }" : "=r"(a) : "l"(p));
    return a;
}

// ============================ split kernels ==================================
// all 3 inputs in one launch
__global__ __launch_bounds__(256)
void split_in3_kernel(const float* __restrict__ Q, const float* __restrict__ K,
                      const float* __restrict__ V,
                      __nv_bfloat16* __restrict__ hi, __nv_bfloat16* __restrict__ lo)
{
    int z = blockIdx.y;
    const float* A = (z == 0) ? Q : (z == 1) ? K : V;
    size_t i = (size_t)blockIdx.x * 256 + threadIdx.x;
    float x = A[i];
    __nv_bfloat16 h = __float2bfloat16(x);
    size_t o = (size_t)z * NELEM + i;
    hi[o] = h;
    lo[o] = __float2bfloat16(x - __bfloat162float(h));
}

// all 4 weights, transposed to [n][k], in one launch
__global__ __launch_bounds__(256)
void split_w4_kernel(const float* __restrict__ W0, const float* __restrict__ W1,
                     const float* __restrict__ W2, const float* __restrict__ W3,
                     __nv_bfloat16* __restrict__ hi, __nv_bfloat16* __restrict__ lo)
{
    __shared__ float t[32][33];
    int z = blockIdx.z;
    const float* W = (z == 0) ? W0 : (z == 1) ? W1 : (z == 2) ? W2 : W3;
    int tx = threadIdx.x, ty = threadIdx.y;           // block (32, 8)
    int n0 = blockIdx.x * 32, k0 = blockIdx.y * 32;
#pragma unroll
    for (int j = 0; j < 4; j++)
        t[ty + j * 8][tx] = W[(size_t)(k0 + ty + j * 8) * D_MODEL + n0 + tx];
    __syncthreads();
#pragma unroll
    for (int j = 0; j < 4; j++) {
        float x = t[tx][ty + j * 8];
        __nv_bfloat16 h = __float2bfloat16(x);
        size_t o = (size_t)z * WELEM + (size_t)(n0 + ty + j * 8) * D_MODEL + k0 + tx;
        hi[o] = h;
        lo[o] = __float2bfloat16(x - __bfloat162float(h));
    }
}

// ==================== QKV projection (one launch, bf16 3-split) ==============
#define SPAD 40
#define STAGE_BYTES 40960
#define OFF_AH 0
#define OFF_AL 10240
#define OFF_BH 20480
#define OFF_BL 30720

__global__ __launch_bounds__(256, 1)
void proj_qkv_kernel(const __nv_bfloat16* __restrict__ in_hi, const __nv_bfloat16* __restrict__ in_lo,
                     const __nv_bfloat16* __restrict__ w_hi, const __nv_bfloat16* __restrict__ w_lo,
                     const float* __restrict__ bq, const float* __restrict__ bk,
                     const float* __restrict__ bv,
                     __half* __restrict__ qhi, __half* __restrict__ qlo,
                     __half* __restrict__ kf,
                     __half* __restrict__ vthi, __half* __restrict__ vtlo)
{
    extern __shared__ char smem[];
    const uint32_t sb0 = smem_u32(smem);

    const int zz = blockIdx.z;        // 0=Q 1=K 2=V
    const __nv_bfloat16* a_hi = in_hi + (size_t)zz * NELEM;
    const __nv_bfloat16* a_lo = in_lo + (size_t)zz * NELEM;
    const __nv_bfloat16* wh   = w_hi + (size_t)zz * WELEM;
    const __nv_bfloat16* wl   = w_lo + (size_t)zz * WELEM;
    const float* bias = (zz == 0) ? bq : (zz == 1) ? bk : bv;

    const int tid  = threadIdx.x;
    const int lane = tid & 31;
    const int wid  = tid >> 5;
    const int warpM = (wid >> 2) * 64;
    const int warpN = (wid & 3) * 32;
    const int blockRow = blockIdx.y * 128;
    const int blockCol = blockIdx.x * 128;

    const int ldRow0 = tid >> 2;
    const int ldQ    = (tid & 3) * 16;
    const int lmRow = lane & 15;
    const int lmK   = (lane >> 4) * 8;

    float acc[4][4][4];
#pragma unroll
    for (int mt = 0; mt < 4; mt++)
#pragma unroll
        for (int nt = 0; nt < 4; nt++)
#pragma unroll
            for (int r = 0; r < 4; r++) acc[mt][nt][r] = 0.0f;

    auto load_stage = [&](int stage, int chunk) {
        const int k0 = chunk * 32;
        const uint32_t sb = sb0 + stage * STAGE_BYTES;
#pragma unroll
        for (int j = 0; j < 2; j++) {
            int row = ldRow0 + j * 64;
            uint32_t so = (uint32_t)(row * 80) + ldQ;
            CP16(sb + OFF_AH + so, &a_hi[(size_t)(blockRow + row) * D_MODEL + k0] + ldQ / 2);
            CP16(sb + OFF_AL + so, &a_lo[(size_t)(blockRow + row) * D_MODEL + k0] + ldQ / 2);
            CP16(sb + OFF_BH + so, &wh[(size_t)(blockCol + row) * D_MODEL + k0] + ldQ / 2);
            CP16(sb + OFF_BL + so, &wl[(size_t)(blockCol + row) * D_MODEL + k0] + ldQ / 2);
        }
        CP_COMMIT();
    };

    load_stage(0, 0);

    for (int chunk = 0; chunk < 32; chunk++) {
        if (chunk < 31) { load_stage((chunk + 1) & 1, chunk + 1); CP_WAIT1(); }
        else           { CP_WAIT0(); }
        __syncthreads();

        const uint32_t sb = sb0 + (chunk & 1) * STAGE_BYTES;
        const uint32_t aAddrBase = sb + (uint32_t)(((warpM + lmRow) * SPAD + lmK) * 2);
        const uint32_t bAddrBase = sb + (uint32_t)(((warpN + lmRow) * SPAD + lmK) * 2);

#pragma unroll
        for (int ks = 0; ks < 2; ks++) {
            const uint32_t kOff = (uint32_t)(ks * 16 * 2);
            uint32_t aH[4][4], aL[4][4], bH[4][2], bL[4][2];
#pragma unroll
            for (int mt = 0; mt < 4; mt++) {
                uint32_t ad = aAddrBase + kOff + (uint32_t)(mt * 16 * SPAD * 2);
                LDSM4(aH[mt][0], aH[mt][1], aH[mt][2], aH[mt][3], ad + OFF_AH);
                LDSM4(aL[mt][0], aL[mt][1], aL[mt][2], aL[mt][3], ad + OFF_AL);
            }
#pragma unroll
            for (int ntp = 0; ntp < 2; ntp++) {
                uint32_t bd = bAddrBase + kOff + (uint32_t)(ntp * 16 * SPAD * 2);
                uint32_t r0, r1, r2, r3;
                LDSM4(r0, r1, r2, r3, bd + OFF_BH);
                bH[2 * ntp][0] = r0; bH[2 * ntp + 1][0] = r1;
                bH[2 * ntp][1] = r2; bH[2 * ntp + 1][1] = r3;
                LDSM4(r0, r1, r2, r3, bd + OFF_BL);
                bL[2 * ntp][0] = r0; bL[2 * ntp + 1][0] = r1;
                bL[2 * ntp][1] = r2; bL[2 * ntp + 1][1] = r3;
            }
#pragma unroll
            for (int mt = 0; mt < 4; mt++)
#pragma unroll
                for (int nt = 0; nt < 4; nt++) {
                    MMABF(acc[mt][nt], aH[mt], bH[nt]);
                    MMABF(acc[mt][nt], aH[mt], bL[nt]);
                    MMABF(acc[mt][nt], aL[mt], bH[nt]);
                }
        }
        __syncthreads();
    }

#pragma unroll
    for (int mt = 0; mt < 4; mt++) {
#pragma unroll
        for (int nt = 0; nt < 4; nt++) {
            int row0 = blockRow + warpM + mt * 16 + (lane >> 2);
            int col  = blockCol + warpN + nt * 8 + (lane & 3) * 2;
            float b0 = bias[col], b1 = bias[col + 1];
#pragma unroll
            for (int half = 0; half < 2; half++) {
                int r = row0 + half * 8;
                float vx = acc[mt][nt][half * 2 + 0] + b0;
                float vy = acc[mt][nt][half * 2 + 1] + b1;
                int z = (r >> 11) * NUM_HEADS + (col >> 6);
                int s = r & (SS - 1);
                int d = col & (DEPTH - 1);
                if (zz == 0) {            // Q: fp16 hi/lo, [z][s][d]
                    size_t o = ((size_t)z * SS + s) * DEPTH + d;
                    __half hx = __float2half(vx);
                    __half hy = __float2half(vy);
                    __half2 hp = {hx, hy};
                    *(__half2*)&qhi[o] = hp;
                    __half2 lp = {__float2half(vx - __half2float(hx)),
                                  __float2half(vy - __half2float(hy))};
                    *(__half2*)&qlo[o] = lp;
                } else if (zz == 1) {     // K: fp16 single, [z][s][d]
                    size_t o = ((size_t)z * SS + s) * DEPTH + d;
                    __half2 hp = {__float2half(vx), __float2half(vy)};
                    *(__half2*)&kf[o] = hp;
                } else {                  // V: fp16 hi/lo transposed [z][d][s]
                    size_t o = ((size_t)z * DEPTH + d) * SS + s;
                    __half hx = __float2half(vx);
                    __half hy = __float2half(vy);
                    vthi[o]      = hx;
                    vthi[o + SS] = hy;
                    vtlo[o]      = __float2half(vx - __half2float(hx));
                    vtlo[o + SS] = __float2half(vy - __half2float(hy));
                }
            }
        }
    }
}

// ==================== output projection (bf16 3-split, fp32 out) =============
__global__ __launch_bounds__(256, 1)
void proj_out_kernel(const __nv_bfloat16* __restrict__ a_hi, const __nv_bfloat16* __restrict__ a_lo,
                     const __nv_bfloat16* __restrict__ w_hi, const __nv_bfloat16* __restrict__ w_lo,
                     const float* __restrict__ bias, float* __restrict__ C)
{
    extern __shared__ char smem[];
    const uint32_t sb0 = smem_u32(smem);

    const int tid  = threadIdx.x;
    const int lane = tid & 31;
    const int wid  = tid >> 5;
    const int warpM = (wid >> 2) * 64;
    const int warpN = (wid & 3) * 32;
    const int blockRow = blockIdx.y * 128;
    const int blockCol = blockIdx.x * 128;

    const int ldRow0 = tid >> 2;
    const int ldQ    = (tid & 3) * 16;
    const int lmRow = lane & 15;
    const int lmK   = (lane >> 4) * 8;

    float acc[4][4][4];
#pragma unroll
    for (int mt = 0; mt < 4; mt++)
#pragma unroll
        for (int nt = 0; nt < 4; nt++)
#pragma unroll
            for (int r = 0; r < 4; r++) acc[mt][nt][r] = 0.0f;

    auto load_stage = [&](int stage, int chunk) {
        const int k0 = chunk * 32;
        const uint32_t sb = sb0 + stage * STAGE_BYTES;
#pragma unroll
        for (int j = 0; j < 2; j++) {
            int row = ldRow0 + j * 64;
            uint32_t so = (uint32_t)(row * 80) + ldQ;
            CP16(sb + OFF_AH + so, &a_hi[(size_t)(blockRow + row) * D_MODEL + k0] + ldQ / 2);
            CP16(sb + OFF_AL + so, &a_lo[(size_t)(blockRow + row) * D_MODEL + k0] + ldQ / 2);
            CP16(sb + OFF_BH + so, &w_hi[(size_t)(blockCol + row) * D_MODEL + k0] + ldQ / 2);
            CP16(sb + OFF_BL + so, &w_lo[(size_t)(blockCol + row) * D_MODEL + k0] + ldQ / 2);
        }
        CP_COMMIT();
    };

    load_stage(0, 0);

    for (int chunk = 0; chunk < 32; chunk++) {
        if (chunk < 31) { load_stage((chunk + 1) & 1, chunk + 1); CP_WAIT1(); }
        else           { CP_WAIT0(); }
        __syncthreads();

        const uint32_t sb = sb0 + (chunk & 1) * STAGE_BYTES;
        const uint32_t aAddrBase = sb + (uint32_t)(((warpM + lmRow) * SPAD + lmK) * 2);
        const uint32_t bAddrBase = sb + (uint32_t)(((warpN + lmRow) * SPAD + lmK) * 2);

#pragma unroll
        for (int ks = 0; ks < 2; ks++) {
            const uint32_t kOff = (uint32_t)(ks * 16 * 2);
            uint32_t aH[4][4], aL[4][4], bH[4][2], bL[4][2];
#pragma unroll
            for (int mt = 0; mt < 4; mt++) {
                uint32_t ad = aAddrBase + kOff + (uint32_t)(mt * 16 * SPAD * 2);
                LDSM4(aH[mt][0], aH[mt][1], aH[mt][2], aH[mt][3], ad + OFF_AH);
                LDSM4(aL[mt][0], aL[mt][1], aL[mt][2], aL[mt][3], ad + OFF_AL);
            }
#pragma unroll
            for (int ntp = 0; ntp < 2; ntp++) {
                uint32_t bd = bAddrBase + kOff + (uint32_t)(ntp * 16 * SPAD * 2);
                uint32_t r0, r1, r2, r3;
                LDSM4(r0, r1, r2, r3, bd + OFF_BH);
                bH[2 * ntp][0] = r0; bH[2 * ntp + 1][0] = r1;
                bH[2 * ntp][1] = r2; bH[2 * ntp + 1][1] = r3;
                LDSM4(r0, r1, r2, r3, bd + OFF_BL);
                bL[2 * ntp][0] = r0; bL[2 * ntp + 1][0] = r1;
                bL[2 * ntp][1] = r2; bL[2 * ntp + 1][1] = r3;
            }
#pragma unroll
            for (int mt = 0; mt < 4; mt++)
#pragma unroll
                for (int nt = 0; nt < 4; nt++) {
                    MMABF(acc[mt][nt], aH[mt], bH[nt]);
                    MMABF(acc[mt][nt], aH[mt], bL[nt]);
                    MMABF(acc[mt][nt], aL[mt], bH[nt]);
                }
        }
        __syncthreads();
    }

#pragma unroll
    for (int mt = 0; mt < 4; mt++) {
#pragma unroll
        for (int nt = 0; nt < 4; nt++) {
            int row0 = blockRow + warpM + mt * 16 + (lane >> 2);
            int col  = blockCol + warpN + nt * 8 + (lane & 3) * 2;
            float b0 = bias[col], b1 = bias[col + 1];
#pragma unroll
            for (int half = 0; half < 2; half++) {
                int r = row0 + half * 8;
                float2 v = {acc[mt][nt][half * 2 + 0] + b0, acc[mt][nt][half * 2 + 1] + b1};
                *(float2*)&C[(size_t)r * D_MODEL + col] = v;
            }
        }
    }
}

// ==================== scores: fp16 2-term mma + exp + rowsums ================
#define QPAD 72

__global__ __launch_bounds__(256, 2)
void scores_mma_kernel(const __half* __restrict__ qh, const __half* __restrict__ ql,
                       const __half* __restrict__ kf,
                       const float* __restrict__ mask, float* __restrict__ attn,
                       float* __restrict__ rowsum)
{
    extern __shared__ char sm[];
    const uint32_t sq = smem_u32(sm);
    __half* sQh = (__half*)sm;
    __half* sQl = sQh + 128 * QPAD;
    __half* sKh = sQl + 128 * QPAD;
    const uint32_t OQH = 0, OQL = 128 * QPAD * 2, OKH = 2 * 128 * QPAD * 2;

    const int z = blockIdx.z;
    const int b = z / NUM_HEADS;
    const int tid = threadIdx.x, lane = tid & 31, wid = tid >> 5;
    const int warpM = (wid >> 2) * 64, warpN = (wid & 3) * 32;
    const int blockRow = blockIdx.y * 128, blockCol = blockIdx.x * 128;
    const int lmRow = lane & 15, lmK = (lane >> 4) * 8;

#pragma unroll
    for (int i = 0; i < 4; i++) {
        int id = tid + i * 256;
        int row = id >> 3, q = id & 7;
        size_t gq = ((size_t)z * SS + blockRow + row) * DEPTH + q * 8;
        size_t gk = ((size_t)z * SS + blockCol + row) * DEPTH + q * 8;
        int so = row * QPAD + q * 8;
        *(uint4*)&sQh[so] = *(const uint4*)&qh[gq];
        *(uint4*)&sQl[so] = *(const uint4*)&ql[gq];
        *(uint4*)&sKh[so] = *(const uint4*)&kf[gk];
    }
    __syncthreads();

    float acc[4][4][4];
#pragma unroll
    for (int mt = 0; mt < 4; mt++)
#pragma unroll
        for (int nt = 0; nt < 4; nt++)
#pragma unroll
            for (int r = 0; r < 4; r++) acc[mt][nt][r] = 0.0f;

    const uint32_t aAddrBase = sq + (uint32_t)(((warpM + lmRow) * QPAD + lmK) * 2);
    const uint32_t bAddrBase = sq + (uint32_t)(((warpN + lmRow) * QPAD + lmK) * 2);

#pragma unroll
    for (int ks = 0; ks < 4; ks++) {
        const uint32_t kOff = (uint32_t)(ks * 16 * 2);
        uint32_t aH[4][4], aL[4][4], bH[4][2];
#pragma unroll
        for (int mt = 0; mt < 4; mt++) {
            uint32_t ad = aAddrBase + kOff + (uint32_t)(mt * 16 * QPAD * 2);
            LDSM4(aH[mt][0], aH[mt][1], aH[mt][2], aH[mt][3], ad + OQH);
            LDSM4(aL[mt][0], aL[mt][1], aL[mt][2], aL[mt][3], ad + OQL);
        }
#pragma unroll
        for (int ntp = 0; ntp < 2; ntp++) {
            uint32_t bd = bAddrBase + kOff + (uint32_t)(ntp * 16 * QPAD * 2);
            uint32_t r0, r1, r2, r3;
            LDSM4(r0, r1, r2, r3, bd + OKH);
            bH[2 * ntp][0] = r0; bH[2 * ntp + 1][0] = r1;
            bH[2 * ntp][1] = r2; bH[2 * ntp + 1][1] = r3;
        }
#pragma unroll
        for (int mt = 0; mt < 4; mt++)
#pragma unroll
            for (int nt = 0; nt < 4; nt++) {
                MMAH(acc[mt][nt], aH[mt], bH[nt]);
                MMAH(acc[mt][nt], aL[mt], bH[nt]);
            }
    }

    float mcol[4][2];
#pragma unroll
    for (int nt = 0; nt < 4; nt++) {
        int col = blockCol + warpN + nt * 8 + (lane & 3) * 2;
        mcol[nt][0] = mask[(size_t)b * SS + col]     * (-1e9f);
        mcol[nt][1] = mask[(size_t)b * SS + col + 1] * (-1e9f);
    }
    float* Cz = attn + (size_t)z * SS * SS;

#pragma unroll
    for (int mt = 0; mt < 4; mt++) {
#pragma unroll
        for (int half = 0; half < 2; half++) {
            int row = blockRow + warpM + mt * 16 + (lane >> 2) + half * 8;
            float rs = 0.0f;
#pragma unroll
            for (int nt = 0; nt < 4; nt++) {
                int col = blockCol + warpN + nt * 8 + (lane & 3) * 2;
                float e0 = __expf(acc[mt][nt][half * 2 + 0] * 0.125f + mcol[nt][0]);
                float e1 = __expf(acc[mt][nt][half * 2 + 1] * 0.125f + mcol[nt][1]);
                rs += e0 + e1;
                float2 v = {e0, e1};
                *(float2*)&Cz[(size_t)row * SS + col] = v;
            }
            rs += __shfl_xor_sync(0xffffffffu, rs, 1);
            rs += __shfl_xor_sync(0xffffffffu, rs, 2);
            if ((lane & 3) == 0)
                rowsum[((size_t)z * SS + row) * RS_W + blockIdx.x * 4 + (wid & 3)] = rs;
        }
    }
}

// ==================== AV: fp16, attn single + V hi/lo ========================
__global__ __launch_bounds__(256, 2)
void av_mma_kernel(float* __restrict__ attn,
                   const __half* __restrict__ vth, const __half* __restrict__ vtl,
                   const float* __restrict__ rowsum,
                   __nv_bfloat16* __restrict__ o_hi, __nv_bfloat16* __restrict__ o_lo)
{
    __shared__ alignas(16) __half sA[128 * SPAD];
    __shared__ alignas(16) __half sBh[64 * SPAD];
    __shared__ alignas(16) __half sBl[64 * SPAD];
    __shared__ float invs[128];

    const uint32_t aA = smem_u32(sA);
    const uint32_t aBh = smem_u32(sBh), aBl = smem_u32(sBl);

    const int z = blockIdx.y;
    const int b = z / NUM_HEADS, h = z % NUM_HEADS;
    const int rowbase = blockIdx.x * 128;
    const int tid = threadIdx.x, lane = tid & 31, wid = tid >> 5;
    const int warpM = (wid >> 1) * 32, warpN = (wid & 1) * 32;
    const int lmRow = lane & 15, lmK = (lane >> 4) * 8;

    if (tid < 128) {
        const float* rp = &rowsum[((size_t)z * SS + rowbase + tid) * RS_W];
        float s = 0.0f;
#pragma unroll
        for (int j = 0; j < RS_W; j++) s += rp[j];
        invs[tid] = 1.0f / s;
    }
    __syncthreads();

    float* Az = attn + (size_t)z * SS * SS;
    const int arow = tid >> 1;
    const int acol = (tid & 1) * 16;
    const float inv = invs[arow];

    float acc[2][4][4];
#pragma unroll
    for (int mt = 0; mt < 2; mt++)
#pragma unroll
        for (int nt = 0; nt < 4; nt++)
#pragma unroll
            for (int r = 0; r < 4; r++) acc[mt][nt][r] = 0.0f;

    for (int k0 = 0; k0 < SS; k0 += 32) {
        size_t base = (size_t)(rowbase + arow) * SS + k0 + acol;
#pragma unroll
        for (int j = 0; j < 4; j++) {
            float4 a = *(const float4*)&Az[base + j * 4];
            a.x *= inv; a.y *= inv; a.z *= inv; a.w *= inv;
            *(float4*)&Az[base + j * 4] = a;
            int so = arow * SPAD + acol + j * 4;
            __half2 p0 = __floats2half2_rn(a.x, a.y);
            __half2 p1 = __floats2half2_rn(a.z, a.w);
            *(__half2*)&sA[so]     = p0;
            *(__half2*)&sA[so + 2] = p1;
        }
        {
            int row = tid >> 2, q = tid & 3;
            size_t g = ((size_t)z * DEPTH + row) * SS + k0 + q * 8;
            *(uint4*)&sBh[row * SPAD + q * 8] = *(const uint4*)&vth[g];
            *(uint4*)&sBl[row * SPAD + q * 8] = *(const uint4*)&vtl[g];
        }
        __syncthreads();

        const uint32_t aBase = (uint32_t)(((warpM + lmRow) * SPAD + lmK) * 2);
        const uint32_t bBase = (uint32_t)(((warpN + lmRow) * SPAD + lmK) * 2);

#pragma unroll
        for (int ks = 0; ks < 2; ks++) {
            const uint32_t kOff = (uint32_t)(ks * 16 * 2);
            uint32_t aF[2][4], bH[4][2], bL[4][2];
#pragma unroll
            for (int mt = 0; mt < 2; mt++) {
                uint32_t ad = aBase + kOff + (uint32_t)(mt * 16 * SPAD * 2);
                LDSM4(aF[mt][0], aF[mt][1], aF[mt][2], aF[mt][3], aA + ad);
            }
#pragma unroll
            for (int ntp = 0; ntp < 2; ntp++) {
                uint32_t bd = bBase + kOff + (uint32_t)(ntp * 16 * SPAD * 2);
                uint32_t r0, r1, r2, r3;
                LDSM4(r0, r1, r2, r3, aBh + bd);
                bH[2 * ntp][0] = r0; bH[2 * ntp + 1][0] = r1;
                bH[2 * ntp][1] = r2; bH[2 * ntp + 1][1] = r3;
                LDSM4(r0, r1, r2, r3, aBl + bd);
                bL[2 * ntp][0] = r0; bL[2 * ntp + 1][0] = r1;
                bL[2 * ntp][1] = r2; bL[2 * ntp + 1][1] = r3;
            }
#pragma unroll
            for (int mt = 0; mt < 2; mt++)
#pragma unroll
                for (int nt = 0; nt < 4; nt++) {
                    MMAH(acc[mt][nt], aF[mt], bH[nt]);
                    MMAH(acc[mt][nt], aF[mt], bL[nt]);
                }
        }
        __syncthreads();
    }

#pragma unroll
    for (int mt = 0; mt < 2; mt++) {
#pragma unroll
        for (int nt = 0; nt < 4; nt++) {
            int row0 = rowbase + warpM + mt * 16 + (lane >> 2);
            int col  = warpN + nt * 8 + (lane & 3) * 2;
#pragma unroll
            for (int half = 0; half < 2; half++) {
                int r = row0 + half * 8;
                float vx = acc[mt][nt][half * 2 + 0];
                float vy = acc[mt][nt][half * 2 + 1];
                size_t o = ((size_t)b * SS + r) * D_MODEL + h * DEPTH + col;
                __nv_bfloat16 hx = __float2bfloat16(vx);
                __nv_bfloat16 hy = __float2bfloat16(vy);
                __nv_bfloat162 hp = {hx, hy};
                *(__nv_bfloat162*)&o_hi[o] = hp;
                __nv_bfloat162 lp = {__float2bfloat16(vx - __bfloat162float(hx)),
                                     __float2bfloat16(vy - __bfloat162float(hy))};
                *(__nv_bfloat162*)&o_lo[o] = lp;
            }
        }
    }
}

// =====================================================================
extern "C" void kernel_launch(void* const* d_in, const int* in_sizes, int n_in,
                              void* d_out, int out_size)
{
    const float* Q    = (const float*)d_in[0];
    const float* K    = (const float*)d_in[1];
    const float* V    = (const float*)d_in[2];
    const float* mask = (const float*)d_in[3];
    const float* Wq   = (const float*)d_in[4];
    const float* bq   = (const float*)d_in[5];
    const float* Wk   = (const float*)d_in[6];
    const float* bk   = (const float*)d_in[7];
    const float* Wv   = (const float*)d_in[8];
    const float* bv   = (const float*)d_in[9];
    const float* Wo   = (const float*)d_in[10];
    const float* bo   = (const float*)d_in[11];

    float* out = (float*)d_out;

    float *rowsum, *attn;
    __nv_bfloat16 *inh, *inl, *wh, *wl, *ohi, *olo;
    __half *qhi, *qlo, *kf, *vth, *vtl;
    cudaGetSymbolAddress((void**)&rowsum, g_rowsum);
    cudaGetSymbolAddress((void**)&inh, g_in_hi);
    cudaGetSymbolAddress((void**)&inl, g_in_lo);
    cudaGetSymbolAddress((void**)&wh, g_w_hi);
    cudaGetSymbolAddress((void**)&wl, g_w_lo);
    cudaGetSymbolAddress((void**)&qhi, g_q_hi);
    cudaGetSymbolAddress((void**)&qlo, g_q_lo);
    cudaGetSymbolAddress((void**)&kf, g_k_f);
    cudaGetSymbolAddress((void**)&vth, g_vt_hi);
    cudaGetSymbolAddress((void**)&vtl, g_vt_lo);
    cudaGetSymbolAddress((void**)&ohi, g_o_hi);
    cudaGetSymbolAddress((void**)&olo, g_o_lo);

    if ((size_t)out_size >= OUT_ELEMS + ATTN_ELEMS) {
        attn = out + OUT_ELEMS;
    } else {
        cudaGetSymbolAddress((void**)&attn, g_attn_fallback);
    }

    static bool attr_done = false;
    if (!attr_done) {
        cudaFuncSetAttribute(proj_qkv_kernel, cudaFuncAttributeMaxDynamicSharedMemorySize, 2 * STAGE_BYTES);
        cudaFuncSetAttribute(proj_out_kernel, cudaFuncAttributeMaxDynamicSharedMemorySize, 2 * STAGE_BYTES);
        cudaFuncSetAttribute(scores_mma_kernel, cudaFuncAttributeMaxDynamicSharedMemorySize, 3 * 128 * QPAD * 2);
        attr_done = true;
    }

    // 1. split all 4 weights (transposed) + all 3 inputs
    dim3 wtBlock(32, 8);
    split_w4_kernel<<<dim3(32, 32, 4), wtBlock>>>(Wq, Wk, Wv, Wo, wh, wl);
    split_in3_kernel<<<dim3(NELEM / 256, 3), 256>>>(Q, K, V, inh, inl);

    // 2. Q/K/V projections in one launch (epilogues emit fp16 attention operands)
    proj_qkv_kernel<<<dim3(8, 32, 3), 256, 2 * STAGE_BYTES>>>(
        inh, inl, wh, wl, bq, bk, bv, qhi, qlo, kf, vth, vtl);

    // 3. scores (fp16 2-term) + exp + rowsum partials
    scores_mma_kernel<<<dim3(16, 16, NZ), 256, 3 * 128 * QPAD * 2>>>(
        qhi, qlo, kf, mask, attn, rowsum);

    // 4. AV (fp16) + normalize + attn writeback; O emitted bf16 hi/lo
    av_mma_kernel<<<dim3(16, NZ), 256>>>(attn, vth, vtl, rowsum, ohi, olo);

    // 5. output projection (bf16 3-split)
    proj_out_kernel<<<dim3(8, 32), 256, 2 * STAGE_BYTES>>>(
        ohi, olo, wh + (size_t)3 * WELEM, wl + (size_t)3 * WELEM, bo, out);
}

// round 7
// speedup vs baseline: 2.4145x; 1.0245x over previous
#include <cuda_runtime.h>
#include <cuda_bf16.h>
#include <cuda_fp16.h>
#include <cstdint>
#include <math.h>

#define D_MODEL   1024
#define NUM_HEADS 16
#define DEPTH     64
#define BB        2
#define SS        2048
#define MROWS     (BB * SS)                              // 4096
#define ATTN_ELEMS ((size_t)BB * NUM_HEADS * SS * SS)    // 134,217,728
#define OUT_ELEMS  ((size_t)MROWS * D_MODEL)             // 4,194,304
#define NZ        (BB * NUM_HEADS)                       // 32
#define RS_W      64
#define NELEM     (MROWS * D_MODEL)                      // 4,194,304
#define WELEM     (D_MODEL * D_MODEL)                    // 1,048,576

// ---------------- scratch (static device globals; no allocations) ------------
__device__ float g_rowsum[(size_t)NZ * SS * RS_W];
__device__ __half g_e[ATTN_ELEMS];                       // unnormalized exp, fp16
__device__ __nv_bfloat16 g_in_hi[3 * (size_t)NELEM];
__device__ __nv_bfloat16 g_in_lo[3 * (size_t)NELEM];
__device__ __nv_bfloat16 g_w_hi[4 * (size_t)WELEM];      // Wq,Wk,Wv,Wo [n][k]
__device__ __nv_bfloat16 g_w_lo[4 * (size_t)WELEM];
__device__ __half g_q_hi[(size_t)NZ * SS * DEPTH];       // [z,s,d]
__device__ __half g_q_lo[(size_t)NZ * SS * DEPTH];
__device__ __half g_k_f[(size_t)NZ * SS * DEPTH];        // [z,s,d]
__device__ __half g_vt_hi[(size_t)NZ * SS * DEPTH];      // [z,d,s]
__device__ __half g_vt_lo[(size_t)NZ * SS * DEPTH];
__device__ __nv_bfloat16 g_o_hi[(size_t)NELEM];
__device__ __nv_bfloat16 g_o_lo[(size_t)NELEM];
__device__ float g_attn_fallback[ATTN_ELEMS];

// ============================ PTX helpers ====================================
#define MMABF(d, a, b)                                                        \
    asm volatile("mma.sync.aligned.m16n8k16.row.col.f32.bf16.bf16.f32 "       \
        "{%0,%1,%2,%3}, {%4,%5,%6,%7}, {%8,%9}, {%0,%1,%2,%3};"               \
        : "+f"((d)[0]), "+f"((d)[1]), "+f"((d)[2]), "+f"((d)[3])              \
        : "r"((a)[0]), "r"((a)[1]), "r"((a)[2]), "r"((a)[3]),                 \
          "r"((b)[0]), "r"((b)[1]))

#define MMAH(d, a, b)                                                         \
    asm volatile("mma.sync.aligned.m16n8k16.row.col.f32.f16.f16.f32 "         \
        "{%0,%1,%2,%3}, {%4,%5,%6,%7}, {%8,%9}, {%0,%1,%2,%3};"               \
        : "+f"((d)[0]), "+f"((d)[1]), "+f"((d)[2]), "+f"((d)[3])              \
        : "r"((a)[0]), "r"((a)[1]), "r"((a)[2]), "r"((a)[3]),                 \
          "r"((b)[0]), "r"((b)[1]))

#define LDSM4(R0, R1, R2, R3, ADDR)                                           \
    asm volatile("ldmatrix.sync.aligned.m8n8.x4.shared.b16 {%0,%1,%2,%3}, [%4];" \
        : "=r"(R0), "=r"(R1), "=r"(R2), "=r"(R3) : "r"(ADDR))

#define CP16(SADDR, GPTR)                                                     \
    asm volatile("cp.async.cg.shared.global [%0], [%1], 16;"                  \
        :: "r"(SADDR), "l"(GPTR))
#define CP_COMMIT() asm volatile("cp.async.commit_group;" ::: "memory")
#define CP_WAIT1()  asm volatile("cp.async.wait_group 1;" ::: "memory")
#define CP_WAIT0()  asm volatile("cp.async.wait_group 0;" ::: "memory")

__device__ __forceinline__ uint32_t smem_u32(const void* p) {
    uint32_t a;
    asm("{ .reg .u64 t; cvta.to.shared.u64 t, %1; cvt.u32.u64 %0, t; }" : "=r"(a) : "l"(p));
    return a;
}

// ============================ split kernels ==================================
__global__ __launch_bounds__(256)
void split_in3_kernel(const float* __restrict__ Q, const float* __restrict__ K,
                      const float* __restrict__ V,
                      __nv_bfloat16* __restrict__ hi, __nv_bfloat16* __restrict__ lo)
{
    int z = blockIdx.y;
    const float* A = (z == 0) ? Q : (z == 1) ? K : V;
    size_t i = (size_t)blockIdx.x * 256 + threadIdx.x;
    float x = A[i];
    __nv_bfloat16 h = __float2bfloat16(x);
    size_t o = (size_t)z * NELEM + i;
    hi[o] = h;
    lo[o] = __float2bfloat16(x - __bfloat162float(h));
}

__global__ __launch_bounds__(256)
void split_w4_kernel(const float* __restrict__ W0, const float* __restrict__ W1,
                     const float* __restrict__ W2, const float* __restrict__ W3,
                     __nv_bfloat16* __restrict__ hi, __nv_bfloat16* __restrict__ lo)
{
    __shared__ float t[32][33];
    int z = blockIdx.z;
    const float* W = (z == 0) ? W0 : (z == 1) ? W1 : (z == 2) ? W2 : W3;
    int tx = threadIdx.x, ty = threadIdx.y;
    int n0 = blockIdx.x * 32, k0 = blockIdx.y * 32;
#pragma unroll
    for (int j = 0; j < 4; j++)
        t[ty + j * 8][tx] = W[(size_t)(k0 + ty + j * 8) * D_MODEL + n0 + tx];
    __syncthreads();
#pragma unroll
    for (int j = 0; j < 4; j++) {
        float x = t[tx][ty + j * 8];
        __nv_bfloat16 h = __float2bfloat16(x);
        size_t o = (size_t)z * WELEM + (size_t)(n0 + ty + j * 8) * D_MODEL + k0 + tx;
        hi[o] = h;
        lo[o] = __float2bfloat16(x - __bfloat162float(h));
    }
}

// ==================== QKV projection (one launch, bf16 3-split) ==============
#define SPAD 40
#define STAGE_BYTES 40960
#define OFF_AH 0
#define OFF_AL 10240
#define OFF_BH 20480
#define OFF_BL 30720

__global__ __launch_bounds__(256, 1)
void proj_qkv_kernel(const __nv_bfloat16* __restrict__ in_hi, const __nv_bfloat16* __restrict__ in_lo,
                     const __nv_bfloat16* __restrict__ w_hi, const __nv_bfloat16* __restrict__ w_lo,
                     const float* __restrict__ bq, const float* __restrict__ bk,
                     const float* __restrict__ bv,
                     __half* __restrict__ qhi, __half* __restrict__ qlo,
                     __half* __restrict__ kf,
                     __half* __restrict__ vthi, __half* __restrict__ vtlo)
{
    extern __shared__ char smem[];
    const uint32_t sb0 = smem_u32(smem);

    const int zz = blockIdx.z;
    const __nv_bfloat16* a_hi = in_hi + (size_t)zz * NELEM;
    const __nv_bfloat16* a_lo = in_lo + (size_t)zz * NELEM;
    const __nv_bfloat16* wh   = w_hi + (size_t)zz * WELEM;
    const __nv_bfloat16* wl   = w_lo + (size_t)zz * WELEM;
    const float* bias = (zz == 0) ? bq : (zz == 1) ? bk : bv;

    const int tid  = threadIdx.x;
    const int lane = tid & 31;
    const int wid  = tid >> 5;
    const int warpM = (wid >> 2) * 64;
    const int warpN = (wid & 3) * 32;
    const int blockRow = blockIdx.y * 128;
    const int blockCol = blockIdx.x * 128;

    const int ldRow0 = tid >> 2;
    const int ldQ    = (tid & 3) * 16;
    const int lmRow = lane & 15;
    const int lmK   = (lane >> 4) * 8;

    float acc[4][4][4];
#pragma unroll
    for (int mt = 0; mt < 4; mt++)
#pragma unroll
        for (int nt = 0; nt < 4; nt++)
#pragma unroll
            for (int r = 0; r < 4; r++) acc[mt][nt][r] = 0.0f;

    auto load_stage = [&](int stage, int chunk) {
        const int k0 = chunk * 32;
        const uint32_t sb = sb0 + stage * STAGE_BYTES;
#pragma unroll
        for (int j = 0; j < 2; j++) {
            int row = ldRow0 + j * 64;
            uint32_t so = (uint32_t)(row * 80) + ldQ;
            CP16(sb + OFF_AH + so, &a_hi[(size_t)(blockRow + row) * D_MODEL + k0] + ldQ / 2);
            CP16(sb + OFF_AL + so, &a_lo[(size_t)(blockRow + row) * D_MODEL + k0] + ldQ / 2);
            CP16(sb + OFF_BH + so, &wh[(size_t)(blockCol + row) * D_MODEL + k0] + ldQ / 2);
            CP16(sb + OFF_BL + so, &wl[(size_t)(blockCol + row) * D_MODEL + k0] + ldQ / 2);
        }
        CP_COMMIT();
    };

    load_stage(0, 0);

    for (int chunk = 0; chunk < 32; chunk++) {
        if (chunk < 31) { load_stage((chunk + 1) & 1, chunk + 1); CP_WAIT1(); }
        else           { CP_WAIT0(); }
        __syncthreads();

        const uint32_t sb = sb0 + (chunk & 1) * STAGE_BYTES;
        const uint32_t aAddrBase = sb + (uint32_t)(((warpM + lmRow) * SPAD + lmK) * 2);
        const uint32_t bAddrBase = sb + (uint32_t)(((warpN + lmRow) * SPAD + lmK) * 2);

#pragma unroll
        for (int ks = 0; ks < 2; ks++) {
            const uint32_t kOff = (uint32_t)(ks * 16 * 2);
            uint32_t aH[4][4], aL[4][4], bH[4][2], bL[4][2];
#pragma unroll
            for (int mt = 0; mt < 4; mt++) {
                uint32_t ad = aAddrBase + kOff + (uint32_t)(mt * 16 * SPAD * 2);
                LDSM4(aH[mt][0], aH[mt][1], aH[mt][2], aH[mt][3], ad + OFF_AH);
                LDSM4(aL[mt][0], aL[mt][1], aL[mt][2], aL[mt][3], ad + OFF_AL);
            }
#pragma unroll
            for (int ntp = 0; ntp < 2; ntp++) {
                uint32_t bd = bAddrBase + kOff + (uint32_t)(ntp * 16 * SPAD * 2);
                uint32_t r0, r1, r2, r3;
                LDSM4(r0, r1, r2, r3, bd + OFF_BH);
                bH[2 * ntp][0] = r0; bH[2 * ntp + 1][0] = r1;
                bH[2 * ntp][1] = r2; bH[2 * ntp + 1][1] = r3;
                LDSM4(r0, r1, r2, r3, bd + OFF_BL);
                bL[2 * ntp][0] = r0; bL[2 * ntp + 1][0] = r1;
                bL[2 * ntp][1] = r2; bL[2 * ntp + 1][1] = r3;
            }
#pragma unroll
            for (int mt = 0; mt < 4; mt++)
#pragma unroll
                for (int nt = 0; nt < 4; nt++) {
                    MMABF(acc[mt][nt], aH[mt], bH[nt]);
                    MMABF(acc[mt][nt], aH[mt], bL[nt]);
                    MMABF(acc[mt][nt], aL[mt], bH[nt]);
                }
        }
        __syncthreads();
    }

#pragma unroll
    for (int mt = 0; mt < 4; mt++) {
#pragma unroll
        for (int nt = 0; nt < 4; nt++) {
            int row0 = blockRow + warpM + mt * 16 + (lane >> 2);
            int col  = blockCol + warpN + nt * 8 + (lane & 3) * 2;
            float b0 = bias[col], b1 = bias[col + 1];
#pragma unroll
            for (int half = 0; half < 2; half++) {
                int r = row0 + half * 8;
                float vx = acc[mt][nt][half * 2 + 0] + b0;
                float vy = acc[mt][nt][half * 2 + 1] + b1;
                int z = (r >> 11) * NUM_HEADS + (col >> 6);
                int s = r & (SS - 1);
                int d = col & (DEPTH - 1);
                if (zz == 0) {
                    size_t o = ((size_t)z * SS + s) * DEPTH + d;
                    __half hx = __float2half(vx);
                    __half hy = __float2half(vy);
                    __half2 hp = {hx, hy};
                    *(__half2*)&qhi[o] = hp;
                    __half2 lp = {__float2half(vx - __half2float(hx)),
                                  __float2half(vy - __half2float(hy))};
                    *(__half2*)&qlo[o] = lp;
                } else if (zz == 1) {
                    size_t o = ((size_t)z * SS + s) * DEPTH + d;
                    __half2 hp = {__float2half(vx), __float2half(vy)};
                    *(__half2*)&kf[o] = hp;
                } else {
                    size_t o = ((size_t)z * DEPTH + d) * SS + s;
                    __half hx = __float2half(vx);
                    __half hy = __float2half(vy);
                    vthi[o]      = hx;
                    vthi[o + SS] = hy;
                    vtlo[o]      = __float2half(vx - __half2float(hx));
                    vtlo[o + SS] = __float2half(vy - __half2float(hy));
                }
            }
        }
    }
}

// ==================== output projection (bf16 3-split, fp32 out) =============
__global__ __launch_bounds__(256, 1)
void proj_out_kernel(const __nv_bfloat16* __restrict__ a_hi, const __nv_bfloat16* __restrict__ a_lo,
                     const __nv_bfloat16* __restrict__ w_hi, const __nv_bfloat16* __restrict__ w_lo,
                     const float* __restrict__ bias, float* __restrict__ C)
{
    extern __shared__ char smem[];
    const uint32_t sb0 = smem_u32(smem);

    const int tid  = threadIdx.x;
    const int lane = tid & 31;
    const int wid  = tid >> 5;
    const int warpM = (wid >> 2) * 64;
    const int warpN = (wid & 3) * 32;
    const int blockRow = blockIdx.y * 128;
    const int blockCol = blockIdx.x * 128;

    const int ldRow0 = tid >> 2;
    const int ldQ    = (tid & 3) * 16;
    const int lmRow = lane & 15;
    const int lmK   = (lane >> 4) * 8;

    float acc[4][4][4];
#pragma unroll
    for (int mt = 0; mt < 4; mt++)
#pragma unroll
        for (int nt = 0; nt < 4; nt++)
#pragma unroll
            for (int r = 0; r < 4; r++) acc[mt][nt][r] = 0.0f;

    auto load_stage = [&](int stage, int chunk) {
        const int k0 = chunk * 32;
        const uint32_t sb = sb0 + stage * STAGE_BYTES;
#pragma unroll
        for (int j = 0; j < 2; j++) {
            int row = ldRow0 + j * 64;
            uint32_t so = (uint32_t)(row * 80) + ldQ;
            CP16(sb + OFF_AH + so, &a_hi[(size_t)(blockRow + row) * D_MODEL + k0] + ldQ / 2);
            CP16(sb + OFF_AL + so, &a_lo[(size_t)(blockRow + row) * D_MODEL + k0] + ldQ / 2);
            CP16(sb + OFF_BH + so, &w_hi[(size_t)(blockCol + row) * D_MODEL + k0] + ldQ / 2);
            CP16(sb + OFF_BL + so, &w_lo[(size_t)(blockCol + row) * D_MODEL + k0] + ldQ / 2);
        }
        CP_COMMIT();
    };

    load_stage(0, 0);

    for (int chunk = 0; chunk < 32; chunk++) {
        if (chunk < 31) { load_stage((chunk + 1) & 1, chunk + 1); CP_WAIT1(); }
        else           { CP_WAIT0(); }
        __syncthreads();

        const uint32_t sb = sb0 + (chunk & 1) * STAGE_BYTES;
        const uint32_t aAddrBase = sb + (uint32_t)(((warpM + lmRow) * SPAD + lmK) * 2);
        const uint32_t bAddrBase = sb + (uint32_t)(((warpN + lmRow) * SPAD + lmK) * 2);

#pragma unroll
        for (int ks = 0; ks < 2; ks++) {
            const uint32_t kOff = (uint32_t)(ks * 16 * 2);
            uint32_t aH[4][4], aL[4][4], bH[4][2], bL[4][2];
#pragma unroll
            for (int mt = 0; mt < 4; mt++) {
                uint32_t ad = aAddrBase + kOff + (uint32_t)(mt * 16 * SPAD * 2);
                LDSM4(aH[mt][0], aH[mt][1], aH[mt][2], aH[mt][3], ad + OFF_AH);
                LDSM4(aL[mt][0], aL[mt][1], aL[mt][2], aL[mt][3], ad + OFF_AL);
            }
#pragma unroll
            for (int ntp = 0; ntp < 2; ntp++) {
                uint32_t bd = bAddrBase + kOff + (uint32_t)(ntp * 16 * SPAD * 2);
                uint32_t r0, r1, r2, r3;
                LDSM4(r0, r1, r2, r3, bd + OFF_BH);
                bH[2 * ntp][0] = r0; bH[2 * ntp + 1][0] = r1;
                bH[2 * ntp][1] = r2; bH[2 * ntp + 1][1] = r3;
                LDSM4(r0, r1, r2, r3, bd + OFF_BL);
                bL[2 * ntp][0] = r0; bL[2 * ntp + 1][0] = r1;
                bL[2 * ntp][1] = r2; bL[2 * ntp + 1][1] = r3;
            }
#pragma unroll
            for (int mt = 0; mt < 4; mt++)
#pragma unroll
                for (int nt = 0; nt < 4; nt++) {
                    MMABF(acc[mt][nt], aH[mt], bH[nt]);
                    MMABF(acc[mt][nt], aH[mt], bL[nt]);
                    MMABF(acc[mt][nt], aL[mt], bH[nt]);
                }
        }
        __syncthreads();
    }

#pragma unroll
    for (int mt = 0; mt < 4; mt++) {
#pragma unroll
        for (int nt = 0; nt < 4; nt++) {
            int row0 = blockRow + warpM + mt * 16 + (lane >> 2);
            int col  = blockCol + warpN + nt * 8 + (lane & 3) * 2;
            float b0 = bias[col], b1 = bias[col + 1];
#pragma unroll
            for (int half = 0; half < 2; half++) {
                int r = row0 + half * 8;
                float2 v = {acc[mt][nt][half * 2 + 0] + b0, acc[mt][nt][half * 2 + 1] + b1};
                *(float2*)&C[(size_t)r * D_MODEL + col] = v;
            }
        }
    }
}

// ==================== scores: fp16 2-term mma -> e fp16 + rowsums ============
#define QPAD 72

__global__ __launch_bounds__(256, 2)
void scores_mma_kernel(const __half* __restrict__ qh, const __half* __restrict__ ql,
                       const __half* __restrict__ kf,
                       const float* __restrict__ mask, __half* __restrict__ eout,
                       float* __restrict__ rowsum)
{
    extern __shared__ char sm[];
    const uint32_t sq = smem_u32(sm);
    __half* sQh = (__half*)sm;
    __half* sQl = sQh + 128 * QPAD;
    __half* sKh = sQl + 128 * QPAD;
    const uint32_t OQH = 0, OQL = 128 * QPAD * 2, OKH = 2 * 128 * QPAD * 2;

    const int z = blockIdx.z;
    const int b = z / NUM_HEADS;
    const int tid = threadIdx.x, lane = tid & 31, wid = tid >> 5;
    const int warpM = (wid >> 2) * 64, warpN = (wid & 3) * 32;
    const int blockRow = blockIdx.y * 128, blockCol = blockIdx.x * 128;
    const int lmRow = lane & 15, lmK = (lane >> 4) * 8;

#pragma unroll
    for (int i = 0; i < 4; i++) {
        int id = tid + i * 256;
        int row = id >> 3, q = id & 7;
        size_t gq = ((size_t)z * SS + blockRow + row) * DEPTH + q * 8;
        size_t gk = ((size_t)z * SS + blockCol + row) * DEPTH + q * 8;
        int so = row * QPAD + q * 8;
        *(uint4*)&sQh[so] = *(const uint4*)&qh[gq];
        *(uint4*)&sQl[so] = *(const uint4*)&ql[gq];
        *(uint4*)&sKh[so] = *(const uint4*)&kf[gk];
    }
    __syncthreads();

    float acc[4][4][4];
#pragma unroll
    for (int mt = 0; mt < 4; mt++)
#pragma unroll
        for (int nt = 0; nt < 4; nt++)
#pragma unroll
            for (int r = 0; r < 4; r++) acc[mt][nt][r] = 0.0f;

    const uint32_t aAddrBase = sq + (uint32_t)(((warpM + lmRow) * QPAD + lmK) * 2);
    const uint32_t bAddrBase = sq + (uint32_t)(((warpN + lmRow) * QPAD + lmK) * 2);

#pragma unroll
    for (int ks = 0; ks < 4; ks++) {
        const uint32_t kOff = (uint32_t)(ks * 16 * 2);
        uint32_t aH[4][4], aL[4][4], bH[4][2];
#pragma unroll
        for (int mt = 0; mt < 4; mt++) {
            uint32_t ad = aAddrBase + kOff + (uint32_t)(mt * 16 * QPAD * 2);
            LDSM4(aH[mt][0], aH[mt][1], aH[mt][2], aH[mt][3], ad + OQH);
            LDSM4(aL[mt][0], aL[mt][1], aL[mt][2], aL[mt][3], ad + OQL);
        }
#pragma unroll
        for (int ntp = 0; ntp < 2; ntp++) {
            uint32_t bd = bAddrBase + kOff + (uint32_t)(ntp * 16 * QPAD * 2);
            uint32_t r0, r1, r2, r3;
            LDSM4(r0, r1, r2, r3, bd + OKH);
            bH[2 * ntp][0] = r0; bH[2 * ntp + 1][0] = r1;
            bH[2 * ntp][1] = r2; bH[2 * ntp + 1][1] = r3;
        }
#pragma unroll
        for (int mt = 0; mt < 4; mt++)
#pragma unroll
            for (int nt = 0; nt < 4; nt++) {
                MMAH(acc[mt][nt], aH[mt], bH[nt]);
                MMAH(acc[mt][nt], aL[mt], bH[nt]);
            }
    }

    float mcol[4][2];
#pragma unroll
    for (int nt = 0; nt < 4; nt++) {
        int col = blockCol + warpN + nt * 8 + (lane & 3) * 2;
        mcol[nt][0] = mask[(size_t)b * SS + col]     * (-1e9f);
        mcol[nt][1] = mask[(size_t)b * SS + col + 1] * (-1e9f);
    }
    __half* Ez = eout + (size_t)z * SS * SS;

#pragma unroll
    for (int mt = 0; mt < 4; mt++) {
#pragma unroll
        for (int half = 0; half < 2; half++) {
            int row = blockRow + warpM + mt * 16 + (lane >> 2) + half * 8;
            float rs = 0.0f;
#pragma unroll
            for (int nt = 0; nt < 4; nt++) {
                int col = blockCol + warpN + nt * 8 + (lane & 3) * 2;
                float e0 = __expf(acc[mt][nt][half * 2 + 0] * 0.125f + mcol[nt][0]);
                float e1 = __expf(acc[mt][nt][half * 2 + 1] * 0.125f + mcol[nt][1]);
                rs += e0 + e1;
                *(__half2*)&Ez[(size_t)row * SS + col] = __floats2half2_rn(e0, e1);
            }
            rs += __shfl_xor_sync(0xffffffffu, rs, 1);
            rs += __shfl_xor_sync(0xffffffffu, rs, 2);
            if ((lane & 3) == 0)
                rowsum[((size_t)z * SS + row) * RS_W + blockIdx.x * 4 + (wid & 3)] = rs;
        }
    }
}

// ==================== AV: e fp16 A-operand, V hi/lo, scale-at-end ============
__global__ __launch_bounds__(256, 2)
void av_mma_kernel(const __half* __restrict__ e,
                   const __half* __restrict__ vth, const __half* __restrict__ vtl,
                   const float* __restrict__ rowsum,
                   __nv_bfloat16* __restrict__ o_hi, __nv_bfloat16* __restrict__ o_lo)
{
    __shared__ alignas(16) __half sA[128 * SPAD];
    __shared__ alignas(16) __half sBh[64 * SPAD];
    __shared__ alignas(16) __half sBl[64 * SPAD];
    __shared__ float invs[128];

    const uint32_t aA = smem_u32(sA);
    const uint32_t aBh = smem_u32(sBh), aBl = smem_u32(sBl);

    const int z = blockIdx.y;
    const int b = z / NUM_HEADS, h = z % NUM_HEADS;
    const int rowbase = blockIdx.x * 128;
    const int tid = threadIdx.x, lane = tid & 31, wid = tid >> 5;
    const int warpM = (wid >> 1) * 32, warpN = (wid & 1) * 32;
    const int lmRow = lane & 15, lmK = (lane >> 4) * 8;

    if (tid < 128) {
        const float* rp = &rowsum[((size_t)z * SS + rowbase + tid) * RS_W];
        float s = 0.0f;
#pragma unroll
        for (int j = 0; j < RS_W; j++) s += rp[j];
        invs[tid] = 1.0f / s;
    }
    __syncthreads();

    const __half* Ez = e + (size_t)z * SS * SS;

    float acc[2][4][4];
#pragma unroll
    for (int mt = 0; mt < 2; mt++)
#pragma unroll
        for (int nt = 0; nt < 4; nt++)
#pragma unroll
            for (int r = 0; r < 4; r++) acc[mt][nt][r] = 0.0f;

    for (int k0 = 0; k0 < SS; k0 += 32) {
        // A: e rows 128 x 32 halves, straight copies
#pragma unroll
        for (int i = 0; i < 2; i++) {
            int id = tid + i * 256;
            int row = id >> 2, q = id & 3;
            *(uint4*)&sA[row * SPAD + q * 8] =
                *(const uint4*)&Ez[(size_t)(rowbase + row) * SS + k0 + q * 8];
        }
        {
            int row = tid >> 2, q = tid & 3;
            size_t g = ((size_t)z * DEPTH + row) * SS + k0 + q * 8;
            *(uint4*)&sBh[row * SPAD + q * 8] = *(const uint4*)&vth[g];
            *(uint4*)&sBl[row * SPAD + q * 8] = *(const uint4*)&vtl[g];
        }
        __syncthreads();

        const uint32_t aBase = (uint32_t)(((warpM + lmRow) * SPAD + lmK) * 2);
        const uint32_t bBase = (uint32_t)(((warpN + lmRow) * SPAD + lmK) * 2);

#pragma unroll
        for (int ks = 0; ks < 2; ks++) {
            const uint32_t kOff = (uint32_t)(ks * 16 * 2);
            uint32_t aF[2][4], bH[4][2], bL[4][2];
#pragma unroll
            for (int mt = 0; mt < 2; mt++) {
                uint32_t ad = aBase + kOff + (uint32_t)(mt * 16 * SPAD * 2);
                LDSM4(aF[mt][0], aF[mt][1], aF[mt][2], aF[mt][3], aA + ad);
            }
#pragma unroll
            for (int ntp = 0; ntp < 2; ntp++) {
                uint32_t bd = bBase + kOff + (uint32_t)(ntp * 16 * SPAD * 2);
                uint32_t r0, r1, r2, r3;
                LDSM4(r0, r1, r2, r3, aBh + bd);
                bH[2 * ntp][0] = r0; bH[2 * ntp + 1][0] = r1;
                bH[2 * ntp][1] = r2; bH[2 * ntp + 1][1] = r3;
                LDSM4(r0, r1, r2, r3, aBl + bd);
                bL[2 * ntp][0] = r0; bL[2 * ntp + 1][0] = r1;
                bL[2 * ntp][1] = r2; bL[2 * ntp + 1][1] = r3;
            }
#pragma unroll
            for (int mt = 0; mt < 2; mt++)
#pragma unroll
                for (int nt = 0; nt < 4; nt++) {
                    MMAH(acc[mt][nt], aF[mt], bH[nt]);
                    MMAH(acc[mt][nt], aF[mt], bL[nt]);
                }
        }
        __syncthreads();
    }

#pragma unroll
    for (int mt = 0; mt < 2; mt++) {
#pragma unroll
        for (int nt = 0; nt < 4; nt++) {
            int lrow0 = warpM + mt * 16 + (lane >> 2);
            int col   = warpN + nt * 8 + (lane & 3) * 2;
#pragma unroll
            for (int half = 0; half < 2; half++) {
                int lr = lrow0 + half * 8;
                float inv = invs[lr];
                int r = rowbase + lr;
                float vx = acc[mt][nt][half * 2 + 0] * inv;
                float vy = acc[mt][nt][half * 2 + 1] * inv;
                size_t o = ((size_t)b * SS + r) * D_MODEL + h * DEPTH + col;
                __nv_bfloat16 hx = __float2bfloat16(vx);
                __nv_bfloat16 hy = __float2bfloat16(vy);
                __nv_bfloat162 hp = {hx, hy};
                *(__nv_bfloat162*)&o_hi[o] = hp;
                __nv_bfloat162 lp = {__float2bfloat16(vx - __bfloat162float(hx)),
                                     __float2bfloat16(vy - __bfloat162float(hy))};
                *(__nv_bfloat162*)&o_lo[o] = lp;
            }
        }
    }
}

// ==================== normalize: attn = float(e) * inv_rowsum ================
// One block per attn row (65536 blocks); 256 threads x 8 elems.
__global__ __launch_bounds__(256)
void normalize_kernel(const __half* __restrict__ e, const float* __restrict__ rowsum,
                      float* __restrict__ attn)
{
    __shared__ float red[64];
    const size_t row = blockIdx.x;
    const int tid = threadIdx.x;

    if (tid < 64) red[tid] = rowsum[row * RS_W + tid];
    __syncthreads();
    if (tid < 32) {
        float s = red[tid] + red[tid + 32];
#pragma unroll
        for (int off = 16; off > 0; off >>= 1)
            s += __shfl_xor_sync(0xffffffffu, s, off);
        if (tid == 0) red[0] = 1.0f / s;
    }
    __syncthreads();
    const float inv = red[0];

    const __half* ez = e + row * SS;
    float* az = attn + row * SS;

    const int i = tid * 8;
    uint4 ev = *(const uint4*)&ez[i];
    const __half2* hp = (const __half2*)&ev;
    float4 v0, v1;
    float2 f0 = __half22float2(hp[0]);
    float2 f1 = __half22float2(hp[1]);
    float2 f2 = __half22float2(hp[2]);
    float2 f3 = __half22float2(hp[3]);
    v0.x = f0.x * inv; v0.y = f0.y * inv; v0.z = f1.x * inv; v0.w = f1.y * inv;
    v1.x = f2.x * inv; v1.y = f2.y * inv; v1.z = f3.x * inv; v1.w = f3.y * inv;
    *(float4*)&az[i]     = v0;
    *(float4*)&az[i + 4] = v1;
}

// =====================================================================
extern "C" void kernel_launch(void* const* d_in, const int* in_sizes, int n_in,
                              void* d_out, int out_size)
{
    const float* Q    = (const float*)d_in[0];
    const float* K    = (const float*)d_in[1];
    const float* V    = (const float*)d_in[2];
    const float* mask = (const float*)d_in[3];
    const float* Wq   = (const float*)d_in[4];
    const float* bq   = (const float*)d_in[5];
    const float* Wk   = (const float*)d_in[6];
    const float* bk   = (const float*)d_in[7];
    const float* Wv   = (const float*)d_in[8];
    const float* bv   = (const float*)d_in[9];
    const float* Wo   = (const float*)d_in[10];
    const float* bo   = (const float*)d_in[11];

    float* out = (float*)d_out;

    float *rowsum, *attn;
    __nv_bfloat16 *inh, *inl, *wh, *wl, *ohi, *olo;
    __half *qhi, *qlo, *kf, *vth, *vtl, *ebuf;
    cudaGetSymbolAddress((void**)&rowsum, g_rowsum);
    cudaGetSymbolAddress((void**)&ebuf, g_e);
    cudaGetSymbolAddress((void**)&inh, g_in_hi);
    cudaGetSymbolAddress((void**)&inl, g_in_lo);
    cudaGetSymbolAddress((void**)&wh, g_w_hi);
    cudaGetSymbolAddress((void**)&wl, g_w_lo);
    cudaGetSymbolAddress((void**)&qhi, g_q_hi);
    cudaGetSymbolAddress((void**)&qlo, g_q_lo);
    cudaGetSymbolAddress((void**)&kf, g_k_f);
    cudaGetSymbolAddress((void**)&vth, g_vt_hi);
    cudaGetSymbolAddress((void**)&vtl, g_vt_lo);
    cudaGetSymbolAddress((void**)&ohi, g_o_hi);
    cudaGetSymbolAddress((void**)&olo, g_o_lo);

    if ((size_t)out_size >= OUT_ELEMS + ATTN_ELEMS) {
        attn = out + OUT_ELEMS;
    } else {
        cudaGetSymbolAddress((void**)&attn, g_attn_fallback);
    }

    static bool attr_done = false;
    if (!attr_done) {
        cudaFuncSetAttribute(proj_qkv_kernel, cudaFuncAttributeMaxDynamicSharedMemorySize, 2 * STAGE_BYTES);
        cudaFuncSetAttribute(proj_out_kernel, cudaFuncAttributeMaxDynamicSharedMemorySize, 2 * STAGE_BYTES);
        cudaFuncSetAttribute(scores_mma_kernel, cudaFuncAttributeMaxDynamicSharedMemorySize, 3 * 128 * QPAD * 2);
        attr_done = true;
    }

    // 1. splits
    dim3 wtBlock(32, 8);
    split_w4_kernel<<<dim3(32, 32, 4), wtBlock>>>(Wq, Wk, Wv, Wo, wh, wl);
    split_in3_kernel<<<dim3(NELEM / 256, 3), 256>>>(Q, K, V, inh, inl);

    // 2. QKV projections (epilogues emit fp16 attention operands)
    proj_qkv_kernel<<<dim3(8, 32, 3), 256, 2 * STAGE_BYTES>>>(
        inh, inl, wh, wl, bq, bk, bv, qhi, qlo, kf, vth, vtl);

    // 3. scores -> e fp16 + rowsum partials
    scores_mma_kernel<<<dim3(16, 16, NZ), 256, 3 * 128 * QPAD * 2>>>(
        qhi, qlo, kf, mask, ebuf, rowsum);

    // 4. AV from e, scale at end; O -> bf16 hi/lo
    av_mma_kernel<<<dim3(16, NZ), 256>>>(ebuf, vth, vtl, rowsum, ohi, olo);

    // 5. normalize -> attn fp32 output
    normalize_kernel<<<(unsigned)(NZ * SS), 256>>>(ebuf, rowsum, attn);

    // 6. output projection
    proj_out_kernel<<<dim3(8, 32), 256, 2 * STAGE_BYTES>>>(
        ohi, olo, wh + (size_t)3 * WELEM, wl + (size_t)3 * WELEM, bo, out);
}

// round 8
// speedup vs baseline: 2.6270x; 1.0880x over previous
#include <cuda_runtime.h>
#include <cuda_bf16.h>
#include <cuda_fp16.h>
#include <cstdint>
#include <math.h>

#define D_MODEL   1024
#define NUM_HEADS 16
#define DEPTH     64
#define BB        2
#define SS        2048
#define MROWS     (BB * SS)                              // 4096
#define ATTN_ELEMS ((size_t)BB * NUM_HEADS * SS * SS)    // 134,217,728
#define OUT_ELEMS  ((size_t)MROWS * D_MODEL)             // 4,194,304
#define NZ        (BB * NUM_HEADS)                       // 32
#define RS_W      64
#define NELEM     (MROWS * D_MODEL)                      // 4,194,304
#define WELEM     (D_MODEL * D_MODEL)                    // 1,048,576

// ---------------- scratch (static device globals; no allocations) ------------
__device__ float g_rowsum[(size_t)NZ * SS * RS_W];
__device__ __half g_e[ATTN_ELEMS];                       // unnormalized exp, fp16
__device__ __nv_bfloat16 g_in_hi[3 * (size_t)NELEM];
__device__ __nv_bfloat16 g_in_lo[3 * (size_t)NELEM];
__device__ __nv_bfloat16 g_w_hi[4 * (size_t)WELEM];      // Wq,Wk,Wv,Wo [n][k]
__device__ __nv_bfloat16 g_w_lo[4 * (size_t)WELEM];
__device__ __half g_q_hi[(size_t)NZ * SS * DEPTH];       // [z,s,d]
__device__ __half g_q_lo[(size_t)NZ * SS * DEPTH];
__device__ __half g_k_f[(size_t)NZ * SS * DEPTH];        // [z,s,d]
__device__ __half g_vt_hi[(size_t)NZ * SS * DEPTH];      // [z,d,s]
__device__ __half g_vt_lo[(size_t)NZ * SS * DEPTH];
__device__ __nv_bfloat16 g_o_hi[(size_t)NELEM];
__device__ __nv_bfloat16 g_o_lo[(size_t)NELEM];
__device__ float g_attn_fallback[ATTN_ELEMS];

// ============================ PTX helpers ====================================
#define MMABF(d, a, b)                                                        \
    asm volatile("mma.sync.aligned.m16n8k16.row.col.f32.bf16.bf16.f32 "       \
        "{%0,%1,%2,%3}, {%4,%5,%6,%7}, {%8,%9}, {%0,%1,%2,%3};"               \
        : "+f"((d)[0]), "+f"((d)[1]), "+f"((d)[2]), "+f"((d)[3])              \
        : "r"((a)[0]), "r"((a)[1]), "r"((a)[2]), "r"((a)[3]),                 \
          "r"((b)[0]), "r"((b)[1]))

#define MMAH(d, a, b)                                                         \
    asm volatile("mma.sync.aligned.m16n8k16.row.col.f32.f16.f16.f32 "         \
        "{%0,%1,%2,%3}, {%4,%5,%6,%7}, {%8,%9}, {%0,%1,%2,%3};"               \
        : "+f"((d)[0]), "+f"((d)[1]), "+f"((d)[2]), "+f"((d)[3])              \
        : "r"((a)[0]), "r"((a)[1]), "r"((a)[2]), "r"((a)[3]),                 \
          "r"((b)[0]), "r"((b)[1]))

#define LDSM4(R0, R1, R2, R3, ADDR)                                           \
    asm volatile("ldmatrix.sync.aligned.m8n8.x4.shared.b16 {%0,%1,%2,%3}, [%4];" \
        : "=r"(R0), "=r"(R1), "=r"(R2), "=r"(R3) : "r"(ADDR))

#define CP16(SADDR, GPTR)                                                     \
    asm volatile("cp.async.cg.shared.global [%0], [%1], 16;"                  \
        :: "r"(SADDR), "l"(GPTR))
#define CP_COMMIT() asm volatile("cp.async.commit_group;" ::: "memory")
#define CP_WAIT1()  asm volatile("cp.async.wait_group 1;" ::: "memory")
#define CP_WAIT0()  asm volatile("cp.async.wait_group 0;" ::: "memory")

__device__ __forceinline__ uint32_t smem_u32(const void* p) {
    uint32_t a;
    asm("{ .reg .u64 t; cvta.to.shared.u64 t, %1; cvt.u32.u64 %0, t; }" : "=r"(a) : "l"(p));
    return a;
}

// ============================ split kernels ==================================
__global__ __launch_bounds__(256)
void split_in3_kernel(const float* __restrict__ Q, const float* __restrict__ K,
                      const float* __restrict__ V,
                      __nv_bfloat16* __restrict__ hi, __nv_bfloat16* __restrict__ lo)
{
    int z = blockIdx.y;
    const float* A = (z == 0) ? Q : (z == 1) ? K : V;
    size_t i = (size_t)blockIdx.x * 256 + threadIdx.x;
    float x = A[i];
    __nv_bfloat16 h = __float2bfloat16(x);
    size_t o = (size_t)z * NELEM + i;
    hi[o] = h;
    lo[o] = __float2bfloat16(x - __bfloat162float(h));
}

__global__ __launch_bounds__(256)
void split_w4_kernel(const float* __restrict__ W0, const float* __restrict__ W1,
                     const float* __restrict__ W2, const float* __restrict__ W3,
                     __nv_bfloat16* __restrict__ hi, __nv_bfloat16* __restrict__ lo)
{
    __shared__ float t[32][33];
    int z = blockIdx.z;
    const float* W = (z == 0) ? W0 : (z == 1) ? W1 : (z == 2) ? W2 : W3;
    int tx = threadIdx.x, ty = threadIdx.y;
    int n0 = blockIdx.x * 32, k0 = blockIdx.y * 32;
#pragma unroll
    for (int j = 0; j < 4; j++)
        t[ty + j * 8][tx] = W[(size_t)(k0 + ty + j * 8) * D_MODEL + n0 + tx];
    __syncthreads();
#pragma unroll
    for (int j = 0; j < 4; j++) {
        float x = t[tx][ty + j * 8];
        __nv_bfloat16 h = __float2bfloat16(x);
        size_t o = (size_t)z * WELEM + (size_t)(n0 + ty + j * 8) * D_MODEL + k0 + tx;
        hi[o] = h;
        lo[o] = __float2bfloat16(x - __bfloat162float(h));
    }
}

// ==================== QKV projection (one launch, bf16 3-split) ==============
#define SPAD 40
#define STAGE_BYTES 40960
#define OFF_AH 0
#define OFF_AL 10240
#define OFF_BH 20480
#define OFF_BL 30720

__global__ __launch_bounds__(256, 1)
void proj_qkv_kernel(const __nv_bfloat16* __restrict__ in_hi, const __nv_bfloat16* __restrict__ in_lo,
                     const __nv_bfloat16* __restrict__ w_hi, const __nv_bfloat16* __restrict__ w_lo,
                     const float* __restrict__ bq, const float* __restrict__ bk,
                     const float* __restrict__ bv,
                     __half* __restrict__ qhi, __half* __restrict__ qlo,
                     __half* __restrict__ kf,
                     __half* __restrict__ vthi, __half* __restrict__ vtlo)
{
    extern __shared__ char smem[];
    const uint32_t sb0 = smem_u32(smem);

    const int zz = blockIdx.z;
    const __nv_bfloat16* a_hi = in_hi + (size_t)zz * NELEM;
    const __nv_bfloat16* a_lo = in_lo + (size_t)zz * NELEM;
    const __nv_bfloat16* wh   = w_hi + (size_t)zz * WELEM;
    const __nv_bfloat16* wl   = w_lo + (size_t)zz * WELEM;
    const float* bias = (zz == 0) ? bq : (zz == 1) ? bk : bv;

    const int tid  = threadIdx.x;
    const int lane = tid & 31;
    const int wid  = tid >> 5;
    const int warpM = (wid >> 2) * 64;
    const int warpN = (wid & 3) * 32;
    const int blockRow = blockIdx.y * 128;
    const int blockCol = blockIdx.x * 128;

    const int ldRow0 = tid >> 2;
    const int ldQ    = (tid & 3) * 16;
    const int lmRow = lane & 15;
    const int lmK   = (lane >> 4) * 8;

    float acc[4][4][4];
#pragma unroll
    for (int mt = 0; mt < 4; mt++)
#pragma unroll
        for (int nt = 0; nt < 4; nt++)
#pragma unroll
            for (int r = 0; r < 4; r++) acc[mt][nt][r] = 0.0f;

    auto load_stage = [&](int stage, int chunk) {
        const int k0 = chunk * 32;
        const uint32_t sb = sb0 + stage * STAGE_BYTES;
#pragma unroll
        for (int j = 0; j < 2; j++) {
            int row = ldRow0 + j * 64;
            uint32_t so = (uint32_t)(row * 80) + ldQ;
            CP16(sb + OFF_AH + so, &a_hi[(size_t)(blockRow + row) * D_MODEL + k0] + ldQ / 2);
            CP16(sb + OFF_AL + so, &a_lo[(size_t)(blockRow + row) * D_MODEL + k0] + ldQ / 2);
            CP16(sb + OFF_BH + so, &wh[(size_t)(blockCol + row) * D_MODEL + k0] + ldQ / 2);
            CP16(sb + OFF_BL + so, &wl[(size_t)(blockCol + row) * D_MODEL + k0] + ldQ / 2);
        }
        CP_COMMIT();
    };

    load_stage(0, 0);

    for (int chunk = 0; chunk < 32; chunk++) {
        if (chunk < 31) { load_stage((chunk + 1) & 1, chunk + 1); CP_WAIT1(); }
        else           { CP_WAIT0(); }
        __syncthreads();

        const uint32_t sb = sb0 + (chunk & 1) * STAGE_BYTES;
        const uint32_t aAddrBase = sb + (uint32_t)(((warpM + lmRow) * SPAD + lmK) * 2);
        const uint32_t bAddrBase = sb + (uint32_t)(((warpN + lmRow) * SPAD + lmK) * 2);

#pragma unroll
        for (int ks = 0; ks < 2; ks++) {
            const uint32_t kOff = (uint32_t)(ks * 16 * 2);
            uint32_t aH[4][4], aL[4][4], bH[4][2], bL[4][2];
#pragma unroll
            for (int mt = 0; mt < 4; mt++) {
                uint32_t ad = aAddrBase + kOff + (uint32_t)(mt * 16 * SPAD * 2);
                LDSM4(aH[mt][0], aH[mt][1], aH[mt][2], aH[mt][3], ad + OFF_AH);
                LDSM4(aL[mt][0], aL[mt][1], aL[mt][2], aL[mt][3], ad + OFF_AL);
            }
#pragma unroll
            for (int ntp = 0; ntp < 2; ntp++) {
                uint32_t bd = bAddrBase + kOff + (uint32_t)(ntp * 16 * SPAD * 2);
                uint32_t r0, r1, r2, r3;
                LDSM4(r0, r1, r2, r3, bd + OFF_BH);
                bH[2 * ntp][0] = r0; bH[2 * ntp + 1][0] = r1;
                bH[2 * ntp][1] = r2; bH[2 * ntp + 1][1] = r3;
                LDSM4(r0, r1, r2, r3, bd + OFF_BL);
                bL[2 * ntp][0] = r0; bL[2 * ntp + 1][0] = r1;
                bL[2 * ntp][1] = r2; bL[2 * ntp + 1][1] = r3;
            }
#pragma unroll
            for (int mt = 0; mt < 4; mt++)
#pragma unroll
                for (int nt = 0; nt < 4; nt++) {
                    MMABF(acc[mt][nt], aH[mt], bH[nt]);
                    MMABF(acc[mt][nt], aH[mt], bL[nt]);
                    MMABF(acc[mt][nt], aL[mt], bH[nt]);
                }
        }
        __syncthreads();
    }

#pragma unroll
    for (int mt = 0; mt < 4; mt++) {
#pragma unroll
        for (int nt = 0; nt < 4; nt++) {
            int row0 = blockRow + warpM + mt * 16 + (lane >> 2);
            int col  = blockCol + warpN + nt * 8 + (lane & 3) * 2;
            float b0 = bias[col], b1 = bias[col + 1];
#pragma unroll
            for (int half = 0; half < 2; half++) {
                int r = row0 + half * 8;
                float vx = acc[mt][nt][half * 2 + 0] + b0;
                float vy = acc[mt][nt][half * 2 + 1] + b1;
                int z = (r >> 11) * NUM_HEADS + (col >> 6);
                int s = r & (SS - 1);
                int d = col & (DEPTH - 1);
                if (zz == 0) {
                    size_t o = ((size_t)z * SS + s) * DEPTH + d;
                    __half hx = __float2half(vx);
                    __half hy = __float2half(vy);
                    __half2 hp = {hx, hy};
                    *(__half2*)&qhi[o] = hp;
                    __half2 lp = {__float2half(vx - __half2float(hx)),
                                  __float2half(vy - __half2float(hy))};
                    *(__half2*)&qlo[o] = lp;
                } else if (zz == 1) {
                    size_t o = ((size_t)z * SS + s) * DEPTH + d;
                    __half2 hp = {__float2half(vx), __float2half(vy)};
                    *(__half2*)&kf[o] = hp;
                } else {
                    size_t o = ((size_t)z * DEPTH + d) * SS + s;
                    __half hx = __float2half(vx);
                    __half hy = __float2half(vy);
                    vthi[o]      = hx;
                    vthi[o + SS] = hy;
                    vtlo[o]      = __float2half(vx - __half2float(hx));
                    vtlo[o + SS] = __float2half(vy - __half2float(hy));
                }
            }
        }
    }
}

// ==================== output projection (bf16 3-split, fp32 out) =============
__global__ __launch_bounds__(256, 1)
void proj_out_kernel(const __nv_bfloat16* __restrict__ a_hi, const __nv_bfloat16* __restrict__ a_lo,
                     const __nv_bfloat16* __restrict__ w_hi, const __nv_bfloat16* __restrict__ w_lo,
                     const float* __restrict__ bias, float* __restrict__ C)
{
    extern __shared__ char smem[];
    const uint32_t sb0 = smem_u32(smem);

    const int tid  = threadIdx.x;
    const int lane = tid & 31;
    const int wid  = tid >> 5;
    const int warpM = (wid >> 2) * 64;
    const int warpN = (wid & 3) * 32;
    const int blockRow = blockIdx.y * 128;
    const int blockCol = blockIdx.x * 128;

    const int ldRow0 = tid >> 2;
    const int ldQ    = (tid & 3) * 16;
    const int lmRow = lane & 15;
    const int lmK   = (lane >> 4) * 8;

    float acc[4][4][4];
#pragma unroll
    for (int mt = 0; mt < 4; mt++)
#pragma unroll
        for (int nt = 0; nt < 4; nt++)
#pragma unroll
            for (int r = 0; r < 4; r++) acc[mt][nt][r] = 0.0f;

    auto load_stage = [&](int stage, int chunk) {
        const int k0 = chunk * 32;
        const uint32_t sb = sb0 + stage * STAGE_BYTES;
#pragma unroll
        for (int j = 0; j < 2; j++) {
            int row = ldRow0 + j * 64;
            uint32_t so = (uint32_t)(row * 80) + ldQ;
            CP16(sb + OFF_AH + so, &a_hi[(size_t)(blockRow + row) * D_MODEL + k0] + ldQ / 2);
            CP16(sb + OFF_AL + so, &a_lo[(size_t)(blockRow + row) * D_MODEL + k0] + ldQ / 2);
            CP16(sb + OFF_BH + so, &w_hi[(size_t)(blockCol + row) * D_MODEL + k0] + ldQ / 2);
            CP16(sb + OFF_BL + so, &w_lo[(size_t)(blockCol + row) * D_MODEL + k0] + ldQ / 2);
        }
        CP_COMMIT();
    };

    load_stage(0, 0);

    for (int chunk = 0; chunk < 32; chunk++) {
        if (chunk < 31) { load_stage((chunk + 1) & 1, chunk + 1); CP_WAIT1(); }
        else           { CP_WAIT0(); }
        __syncthreads();

        const uint32_t sb = sb0 + (chunk & 1) * STAGE_BYTES;
        const uint32_t aAddrBase = sb + (uint32_t)(((warpM + lmRow) * SPAD + lmK) * 2);
        const uint32_t bAddrBase = sb + (uint32_t)(((warpN + lmRow) * SPAD + lmK) * 2);

#pragma unroll
        for (int ks = 0; ks < 2; ks++) {
            const uint32_t kOff = (uint32_t)(ks * 16 * 2);
            uint32_t aH[4][4], aL[4][4], bH[4][2], bL[4][2];
#pragma unroll
            for (int mt = 0; mt < 4; mt++) {
                uint32_t ad = aAddrBase + kOff + (uint32_t)(mt * 16 * SPAD * 2);
                LDSM4(aH[mt][0], aH[mt][1], aH[mt][2], aH[mt][3], ad + OFF_AH);
                LDSM4(aL[mt][0], aL[mt][1], aL[mt][2], aL[mt][3], ad + OFF_AL);
            }
#pragma unroll
            for (int ntp = 0; ntp < 2; ntp++) {
                uint32_t bd = bAddrBase + kOff + (uint32_t)(ntp * 16 * SPAD * 2);
                uint32_t r0, r1, r2, r3;
                LDSM4(r0, r1, r2, r3, bd + OFF_BH);
                bH[2 * ntp][0] = r0; bH[2 * ntp + 1][0] = r1;
                bH[2 * ntp][1] = r2; bH[2 * ntp + 1][1] = r3;
                LDSM4(r0, r1, r2, r3, bd + OFF_BL);
                bL[2 * ntp][0] = r0; bL[2 * ntp + 1][0] = r1;
                bL[2 * ntp][1] = r2; bL[2 * ntp + 1][1] = r3;
            }
#pragma unroll
            for (int mt = 0; mt < 4; mt++)
#pragma unroll
                for (int nt = 0; nt < 4; nt++) {
                    MMABF(acc[mt][nt], aH[mt], bH[nt]);
                    MMABF(acc[mt][nt], aH[mt], bL[nt]);
                    MMABF(acc[mt][nt], aL[mt], bH[nt]);
                }
        }
        __syncthreads();
    }

#pragma unroll
    for (int mt = 0; mt < 4; mt++) {
#pragma unroll
        for (int nt = 0; nt < 4; nt++) {
            int row0 = blockRow + warpM + mt * 16 + (lane >> 2);
            int col  = blockCol + warpN + nt * 8 + (lane & 3) * 2;
            float b0 = bias[col], b1 = bias[col + 1];
#pragma unroll
            for (int half = 0; half < 2; half++) {
                int r = row0 + half * 8;
                float2 v = {acc[mt][nt][half * 2 + 0] + b0, acc[mt][nt][half * 2 + 1] + b1};
                *(float2*)&C[(size_t)r * D_MODEL + col] = v;
            }
        }
    }
}

// ==================== scores: fp16 2-term mma -> e fp16 (staged) =============
#define QPAD 72
#define EPAD 136

__global__ __launch_bounds__(256, 2)
void scores_mma_kernel(const __half* __restrict__ qh, const __half* __restrict__ ql,
                       const __half* __restrict__ kf,
                       const float* __restrict__ mask, __half* __restrict__ eout,
                       float* __restrict__ rowsum)
{
    extern __shared__ char sm[];
    const uint32_t sq = smem_u32(sm);
    __half* sQh = (__half*)sm;
    __half* sQl = sQh + 128 * QPAD;
    __half* sKh = sQl + 128 * QPAD;
    const uint32_t OQH = 0, OQL = 128 * QPAD * 2, OKH = 2 * 128 * QPAD * 2;

    const int z = blockIdx.z;
    const int b = z / NUM_HEADS;
    const int tid = threadIdx.x, lane = tid & 31, wid = tid >> 5;
    const int warpM = (wid >> 2) * 64, warpN = (wid & 3) * 32;
    const int blockRow = blockIdx.y * 128, blockCol = blockIdx.x * 128;
    const int lmRow = lane & 15, lmK = (lane >> 4) * 8;

#pragma unroll
    for (int i = 0; i < 4; i++) {
        int id = tid + i * 256;
        int row = id >> 3, q = id & 7;
        size_t gq = ((size_t)z * SS + blockRow + row) * DEPTH + q * 8;
        size_t gk = ((size_t)z * SS + blockCol + row) * DEPTH + q * 8;
        int so = row * QPAD + q * 8;
        *(uint4*)&sQh[so] = *(const uint4*)&qh[gq];
        *(uint4*)&sQl[so] = *(const uint4*)&ql[gq];
        *(uint4*)&sKh[so] = *(const uint4*)&kf[gk];
    }
    __syncthreads();

    float acc[4][4][4];
#pragma unroll
    for (int mt = 0; mt < 4; mt++)
#pragma unroll
        for (int nt = 0; nt < 4; nt++)
#pragma unroll
            for (int r = 0; r < 4; r++) acc[mt][nt][r] = 0.0f;

    const uint32_t aAddrBase = sq + (uint32_t)(((warpM + lmRow) * QPAD + lmK) * 2);
    const uint32_t bAddrBase = sq + (uint32_t)(((warpN + lmRow) * QPAD + lmK) * 2);

#pragma unroll
    for (int ks = 0; ks < 4; ks++) {
        const uint32_t kOff = (uint32_t)(ks * 16 * 2);
        uint32_t aH[4][4], aL[4][4], bH[4][2];
#pragma unroll
        for (int mt = 0; mt < 4; mt++) {
            uint32_t ad = aAddrBase + kOff + (uint32_t)(mt * 16 * QPAD * 2);
            LDSM4(aH[mt][0], aH[mt][1], aH[mt][2], aH[mt][3], ad + OQH);
            LDSM4(aL[mt][0], aL[mt][1], aL[mt][2], aL[mt][3], ad + OQL);
        }
#pragma unroll
        for (int ntp = 0; ntp < 2; ntp++) {
            uint32_t bd = bAddrBase + kOff + (uint32_t)(ntp * 16 * QPAD * 2);
            uint32_t r0, r1, r2, r3;
            LDSM4(r0, r1, r2, r3, bd + OKH);
            bH[2 * ntp][0] = r0; bH[2 * ntp + 1][0] = r1;
            bH[2 * ntp][1] = r2; bH[2 * ntp + 1][1] = r3;
        }
#pragma unroll
        for (int mt = 0; mt < 4; mt++)
#pragma unroll
            for (int nt = 0; nt < 4; nt++) {
                MMAH(acc[mt][nt], aH[mt], bH[nt]);
                MMAH(acc[mt][nt], aL[mt], bH[nt]);
            }
    }

    float mcol[4][2];
#pragma unroll
    for (int nt = 0; nt < 4; nt++) {
        int col = blockCol + warpN + nt * 8 + (lane & 3) * 2;
        mcol[nt][0] = mask[(size_t)b * SS + col]     * (-1e9f);
        mcol[nt][1] = mask[(size_t)b * SS + col + 1] * (-1e9f);
    }

    // epilogue: exp + rowsum + stage into smem (conflict-free, stride 136)
    __syncthreads();                      // all warps done reading operands
    __half* sE = (__half*)sm;             // 128 x EPAD halves = 34816 B

#pragma unroll
    for (int mt = 0; mt < 4; mt++) {
#pragma unroll
        for (int half = 0; half < 2; half++) {
            int lrow = warpM + mt * 16 + (lane >> 2) + half * 8;
            float rs = 0.0f;
#pragma unroll
            for (int nt = 0; nt < 4; nt++) {
                int lcol = warpN + nt * 8 + (lane & 3) * 2;
                float e0 = __expf(acc[mt][nt][half * 2 + 0] * 0.125f + mcol[nt][0]);
                float e1 = __expf(acc[mt][nt][half * 2 + 1] * 0.125f + mcol[nt][1]);
                rs += e0 + e1;
                *(__half2*)&sE[lrow * EPAD + lcol] = __floats2half2_rn(e0, e1);
            }
            rs += __shfl_xor_sync(0xffffffffu, rs, 1);
            rs += __shfl_xor_sync(0xffffffffu, rs, 2);
            if ((lane & 3) == 0)
                rowsum[((size_t)z * SS + blockRow + lrow) * RS_W + blockIdx.x * 4 + (wid & 3)] = rs;
        }
    }
    __syncthreads();

    // coalesced 128B-line stores
    __half* Ez = eout + (size_t)z * SS * SS;
#pragma unroll
    for (int i = 0; i < 8; i++) {
        int id = tid + i * 256;
        int row = id >> 4, q = id & 15;
        *(uint4*)&Ez[(size_t)(blockRow + row) * SS + blockCol + q * 8] =
            *(const uint4*)&sE[row * EPAD + q * 8];
    }
}

// ==================== AV: e fp16 A-operand + fused attn normalize ============
__global__ __launch_bounds__(256, 2)
void av_mma_kernel(const __half* __restrict__ e,
                   const __half* __restrict__ vth, const __half* __restrict__ vtl,
                   const float* __restrict__ rowsum, float* __restrict__ attn,
                   __nv_bfloat16* __restrict__ o_hi, __nv_bfloat16* __restrict__ o_lo)
{
    __shared__ alignas(16) __half sA[128 * SPAD];
    __shared__ alignas(16) __half sBh[64 * SPAD];
    __shared__ alignas(16) __half sBl[64 * SPAD];
    __shared__ float invs[128];

    const uint32_t aA = smem_u32(sA);
    const uint32_t aBh = smem_u32(sBh), aBl = smem_u32(sBl);

    const int z = blockIdx.y;
    const int b = z / NUM_HEADS, h = z % NUM_HEADS;
    const int rowbase = blockIdx.x * 128;
    const int tid = threadIdx.x, lane = tid & 31, wid = tid >> 5;
    const int warpM = (wid >> 1) * 32, warpN = (wid & 1) * 32;
    const int lmRow = lane & 15, lmK = (lane >> 4) * 8;

    if (tid < 128) {
        const float* rp = &rowsum[((size_t)z * SS + rowbase + tid) * RS_W];
        float s = 0.0f;
#pragma unroll
        for (int j = 0; j < RS_W; j++) s += rp[j];
        invs[tid] = 1.0f / s;
    }
    __syncthreads();

    const __half* Ez = e + (size_t)z * SS * SS;
    float* Az = attn + (size_t)z * SS * SS;

    float acc[2][4][4];
#pragma unroll
    for (int mt = 0; mt < 2; mt++)
#pragma unroll
        for (int nt = 0; nt < 4; nt++)
#pragma unroll
            for (int r = 0; r < 4; r++) acc[mt][nt][r] = 0.0f;

    for (int k0 = 0; k0 < SS; k0 += 32) {
        // A: e rows 128 x 32 halves; also emit normalized fp32 attn
#pragma unroll
        for (int i = 0; i < 2; i++) {
            int id = tid + i * 256;
            int row = id >> 2, q = id & 3;
            uint4 ev = *(const uint4*)&Ez[(size_t)(rowbase + row) * SS + k0 + q * 8];
            *(uint4*)&sA[row * SPAD + q * 8] = ev;
            const float inv = invs[row];
            const __half2* hp = (const __half2*)&ev;
            float2 f0 = __half22float2(hp[0]);
            float2 f1 = __half22float2(hp[1]);
            float2 f2 = __half22float2(hp[2]);
            float2 f3 = __half22float2(hp[3]);
            float4 v0 = {f0.x * inv, f0.y * inv, f1.x * inv, f1.y * inv};
            float4 v1 = {f2.x * inv, f2.y * inv, f3.x * inv, f3.y * inv};
            size_t ao = (size_t)(rowbase + row) * SS + k0 + q * 8;
            *(float4*)&Az[ao]     = v0;
            *(float4*)&Az[ao + 4] = v1;
        }
        {
            int row = tid >> 2, q = tid & 3;
            size_t g = ((size_t)z * DEPTH + row) * SS + k0 + q * 8;
            *(uint4*)&sBh[row * SPAD + q * 8] = *(const uint4*)&vth[g];
            *(uint4*)&sBl[row * SPAD + q * 8] = *(const uint4*)&vtl[g];
        }
        __syncthreads();

        const uint32_t aBase = (uint32_t)(((warpM + lmRow) * SPAD + lmK) * 2);
        const uint32_t bBase = (uint32_t)(((warpN + lmRow) * SPAD + lmK) * 2);

#pragma unroll
        for (int ks = 0; ks < 2; ks++) {
            const uint32_t kOff = (uint32_t)(ks * 16 * 2);
            uint32_t aF[2][4], bH[4][2], bL[4][2];
#pragma unroll
            for (int mt = 0; mt < 2; mt++) {
                uint32_t ad = aBase + kOff + (uint32_t)(mt * 16 * SPAD * 2);
                LDSM4(aF[mt][0], aF[mt][1], aF[mt][2], aF[mt][3], aA + ad);
            }
#pragma unroll
            for (int ntp = 0; ntp < 2; ntp++) {
                uint32_t bd = bBase + kOff + (uint32_t)(ntp * 16 * SPAD * 2);
                uint32_t r0, r1, r2, r3;
                LDSM4(r0, r1, r2, r3, aBh + bd);
                bH[2 * ntp][0] = r0; bH[2 * ntp + 1][0] = r1;
                bH[2 * ntp][1] = r2; bH[2 * ntp + 1][1] = r3;
                LDSM4(r0, r1, r2, r3, aBl + bd);
                bL[2 * ntp][0] = r0; bL[2 * ntp + 1][0] = r1;
                bL[2 * ntp][1] = r2; bL[2 * ntp + 1][1] = r3;
            }
#pragma unroll
            for (int mt = 0; mt < 2; mt++)
#pragma unroll
                for (int nt = 0; nt < 4; nt++) {
                    MMAH(acc[mt][nt], aF[mt], bH[nt]);
                    MMAH(acc[mt][nt], aF[mt], bL[nt]);
                }
        }
        __syncthreads();
    }

#pragma unroll
    for (int mt = 0; mt < 2; mt++) {
#pragma unroll
        for (int nt = 0; nt < 4; nt++) {
            int lrow0 = warpM + mt * 16 + (lane >> 2);
            int col   = warpN + nt * 8 + (lane & 3) * 2;
#pragma unroll
            for (int half = 0; half < 2; half++) {
                int lr = lrow0 + half * 8;
                float inv = invs[lr];
                int r = rowbase + lr;
                float vx = acc[mt][nt][half * 2 + 0] * inv;
                float vy = acc[mt][nt][half * 2 + 1] * inv;
                size_t o = ((size_t)b * SS + r) * D_MODEL + h * DEPTH + col;
                __nv_bfloat16 hx = __float2bfloat16(vx);
                __nv_bfloat16 hy = __float2bfloat16(vy);
                __nv_bfloat162 hp = {hx, hy};
                *(__nv_bfloat162*)&o_hi[o] = hp;
                __nv_bfloat162 lp = {__float2bfloat16(vx - __bfloat162float(hx)),
                                     __float2bfloat16(vy - __bfloat162float(hy))};
                *(__nv_bfloat162*)&o_lo[o] = lp;
            }
        }
    }
}

// =====================================================================
extern "C" void kernel_launch(void* const* d_in, const int* in_sizes, int n_in,
                              void* d_out, int out_size)
{
    const float* Q    = (const float*)d_in[0];
    const float* K    = (const float*)d_in[1];
    const float* V    = (const float*)d_in[2];
    const float* mask = (const float*)d_in[3];
    const float* Wq   = (const float*)d_in[4];
    const float* bq   = (const float*)d_in[5];
    const float* Wk   = (const float*)d_in[6];
    const float* bk   = (const float*)d_in[7];
    const float* Wv   = (const float*)d_in[8];
    const float* bv   = (const float*)d_in[9];
    const float* Wo   = (const float*)d_in[10];
    const float* bo   = (const float*)d_in[11];

    float* out = (float*)d_out;

    float *rowsum, *attn;
    __nv_bfloat16 *inh, *inl, *wh, *wl, *ohi, *olo;
    __half *qhi, *qlo, *kf, *vth, *vtl, *ebuf;
    cudaGetSymbolAddress((void**)&rowsum, g_rowsum);
    cudaGetSymbolAddress((void**)&ebuf, g_e);
    cudaGetSymbolAddress((void**)&inh, g_in_hi);
    cudaGetSymbolAddress((void**)&inl, g_in_lo);
    cudaGetSymbolAddress((void**)&wh, g_w_hi);
    cudaGetSymbolAddress((void**)&wl, g_w_lo);
    cudaGetSymbolAddress((void**)&qhi, g_q_hi);
    cudaGetSymbolAddress((void**)&qlo, g_q_lo);
    cudaGetSymbolAddress((void**)&kf, g_k_f);
    cudaGetSymbolAddress((void**)&vth, g_vt_hi);
    cudaGetSymbolAddress((void**)&vtl, g_vt_lo);
    cudaGetSymbolAddress((void**)&ohi, g_o_hi);
    cudaGetSymbolAddress((void**)&olo, g_o_lo);

    if ((size_t)out_size >= OUT_ELEMS + ATTN_ELEMS) {
        attn = out + OUT_ELEMS;
    } else {
        cudaGetSymbolAddress((void**)&attn, g_attn_fallback);
    }

    static bool attr_done = false;
    if (!attr_done) {
        cudaFuncSetAttribute(proj_qkv_kernel, cudaFuncAttributeMaxDynamicSharedMemorySize, 2 * STAGE_BYTES);
        cudaFuncSetAttribute(proj_out_kernel, cudaFuncAttributeMaxDynamicSharedMemorySize, 2 * STAGE_BYTES);
        cudaFuncSetAttribute(scores_mma_kernel, cudaFuncAttributeMaxDynamicSharedMemorySize, 3 * 128 * QPAD * 2);
        attr_done = true;
    }

    // 1. splits
    dim3 wtBlock(32, 8);
    split_w4_kernel<<<dim3(32, 32, 4), wtBlock>>>(Wq, Wk, Wv, Wo, wh, wl);
    split_in3_kernel<<<dim3(NELEM / 256, 3), 256>>>(Q, K, V, inh, inl);

    // 2. QKV projections
    proj_qkv_kernel<<<dim3(8, 32, 3), 256, 2 * STAGE_BYTES>>>(
        inh, inl, wh, wl, bq, bk, bv, qhi, qlo, kf, vth, vtl);

    // 3. scores -> e fp16 (staged, coalesced) + rowsum partials
    scores_mma_kernel<<<dim3(16, 16, NZ), 256, 3 * 128 * QPAD * 2>>>(
        qhi, qlo, kf, mask, ebuf, rowsum);

    // 4. AV + fused attn normalize; O -> bf16 hi/lo
    av_mma_kernel<<<dim3(16, NZ), 256>>>(ebuf, vth, vtl, rowsum, attn, ohi, olo);

    // 5. output projection
    proj_out_kernel<<<dim3(8, 32), 256, 2 * STAGE_BYTES>>>(
        ohi, olo, wh + (size_t)3 * WELEM, wl + (size_t)3 * WELEM, bo, out);
}

// round 9
// speedup vs baseline: 3.3260x; 1.2661x over previous
#include <cuda_runtime.h>
#include <cuda_bf16.h>
#include <cuda_fp16.h>
#include <cstdint>
#include <math.h>

#define D_MODEL   1024
#define NUM_HEADS 16
#define DEPTH     64
#define BB        2
#define SS        2048
#define MROWS     (BB * SS)                              // 4096
#define ATTN_ELEMS ((size_t)BB * NUM_HEADS * SS * SS)    // 134,217,728
#define OUT_ELEMS  ((size_t)MROWS * D_MODEL)             // 4,194,304
#define NZ        (BB * NUM_HEADS)                       // 32
#define RS_W      64
#define NELEM     (MROWS * D_MODEL)                      // 4,194,304
#define WELEM     (D_MODEL * D_MODEL)                    // 1,048,576

// ---------------- scratch (static device globals; no allocations) ------------
__device__ float g_rowsum[(size_t)NZ * SS * RS_W];
__device__ __half g_e[ATTN_ELEMS];                       // unnormalized exp
__device__ __half g_in_hi[3 * (size_t)NELEM];            // QKV inputs fp16 hi/lo
__device__ __half g_in_lo[3 * (size_t)NELEM];
__device__ __half g_w[4 * (size_t)WELEM];                // Wq,Wk,Wv,Wo [n][k] fp16
__device__ __half g_q_hi[(size_t)NZ * SS * DEPTH];       // [z,s,d]
__device__ __half g_q_lo[(size_t)NZ * SS * DEPTH];
__device__ __half g_k_f[(size_t)NZ * SS * DEPTH];        // [z,s,d]
__device__ __half g_vt_hi[(size_t)NZ * SS * DEPTH];      // [z,d,s]
__device__ __half g_vt_lo[(size_t)NZ * SS * DEPTH];
__device__ __half g_o_hi[(size_t)NELEM];                 // O fp16 hi/lo
__device__ __half g_o_lo[(size_t)NELEM];
__device__ float g_attn_fallback[ATTN_ELEMS];

// ============================ PTX helpers ====================================
#define MMAH(d, a, b)                                                         \
    asm volatile("mma.sync.aligned.m16n8k16.row.col.f32.f16.f16.f32 "         \
        "{%0,%1,%2,%3}, {%4,%5,%6,%7}, {%8,%9}, {%0,%1,%2,%3};"               \
        : "+f"((d)[0]), "+f"((d)[1]), "+f"((d)[2]), "+f"((d)[3])              \
        : "r"((a)[0]), "r"((a)[1]), "r"((a)[2]), "r"((a)[3]),                 \
          "r"((b)[0]), "r"((b)[1]))

#define LDSM4(R0, R1, R2, R3, ADDR)                                           \
    asm volatile("ldmatrix.sync.aligned.m8n8.x4.shared.b16 {%0,%1,%2,%3}, [%4];" \
        : "=r"(R0), "=r"(R1), "=r"(R2), "=r"(R3) : "r"(ADDR))

#define CP16(SADDR, GPTR)                                                     \
    asm volatile("cp.async.cg.shared.global [%0], [%1], 16;"                  \
        :: "r"(SADDR), "l"(GPTR))
#define CP_COMMIT() asm volatile("cp.async.commit_group;" ::: "memory")
#define CP_WAIT1()  asm volatile("cp.async.wait_group 1;" ::: "memory")
#define CP_WAIT0()  asm volatile("cp.async.wait_group 0;" ::: "memory")

__device__ __forceinline__ uint32_t smem_u32(const void* p) {
    uint32_t a;
    asm("{ .reg .u64 t; cvta.to.shared.u64 t, %1; cvt.u32.u64 %0, t; }" : "=r"(a) : "l"(p));
    return a;
}

// ============================ split kernels ==================================
__global__ __launch_bounds__(256)
void split_in3_kernel(const float* __restrict__ Q, const float* __restrict__ K,
                      const float* __restrict__ V,
                      __half* __restrict__ hi, __half* __restrict__ lo)
{
    int z = blockIdx.y;
    const float* A = (z == 0) ? Q : (z == 1) ? K : V;
    size_t i = (size_t)blockIdx.x * 256 + threadIdx.x;
    float x = A[i];
    __half h = __float2half(x);
    size_t o = (size_t)z * NELEM + i;
    hi[o] = h;
    lo[o] = __float2half(x - __half2float(h));
}

// 4 weights -> fp16 [n][k] transposed, one launch
__global__ __launch_bounds__(256)
void split_w4_kernel(const float* __restrict__ W0, const float* __restrict__ W1,
                     const float* __restrict__ W2, const float* __restrict__ W3,
                     __half* __restrict__ wt)
{
    __shared__ float t[32][33];
    int z = blockIdx.z;
    const float* W = (z == 0) ? W0 : (z == 1) ? W1 : (z == 2) ? W2 : W3;
    int tx = threadIdx.x, ty = threadIdx.y;
    int n0 = blockIdx.x * 32, k0 = blockIdx.y * 32;
#pragma unroll
    for (int j = 0; j < 4; j++)
        t[ty + j * 8][tx] = W[(size_t)(k0 + ty + j * 8) * D_MODEL + n0 + tx];
    __syncthreads();
#pragma unroll
    for (int j = 0; j < 4; j++) {
        size_t o = (size_t)z * WELEM + (size_t)(n0 + ty + j * 8) * D_MODEL + k0 + tx;
        wt[o] = __float2half(t[tx][ty + j * 8]);
    }
}

// ==================== projection GEMMs (fp16 2-term) =========================
// A = fp16 hi/lo [M][1024], B = W fp16 [n][k]. 2 MMAs per tile.
#define SPAD 40
#define PSTAGE 30720       // 3 arrays * 128*40*2
#define OFF_AH 0
#define OFF_AL 10240
#define OFF_BH 20480

__global__ __launch_bounds__(256, 2)
void proj_qkv_kernel(const __half* __restrict__ in_hi, const __half* __restrict__ in_lo,
                     const __half* __restrict__ w,
                     const float* __restrict__ bq, const float* __restrict__ bk,
                     const float* __restrict__ bv,
                     __half* __restrict__ qhi, __half* __restrict__ qlo,
                     __half* __restrict__ kf,
                     __half* __restrict__ vthi, __half* __restrict__ vtlo)
{
    extern __shared__ char smem[];
    const uint32_t sb0 = smem_u32(smem);

    const int zz = blockIdx.z;
    const __half* a_hi = in_hi + (size_t)zz * NELEM;
    const __half* a_lo = in_lo + (size_t)zz * NELEM;
    const __half* wh   = w + (size_t)zz * WELEM;
    const float* bias = (zz == 0) ? bq : (zz == 1) ? bk : bv;

    const int tid  = threadIdx.x;
    const int lane = tid & 31;
    const int wid  = tid >> 5;
    const int warpM = (wid >> 2) * 64;
    const int warpN = (wid & 3) * 32;
    const int blockRow = blockIdx.y * 128;
    const int blockCol = blockIdx.x * 128;

    const int ldRow0 = tid >> 2;
    const int ldQ    = (tid & 3) * 16;
    const int lmRow = lane & 15;
    const int lmK   = (lane >> 4) * 8;

    float acc[4][4][4];
#pragma unroll
    for (int mt = 0; mt < 4; mt++)
#pragma unroll
        for (int nt = 0; nt < 4; nt++)
#pragma unroll
            for (int r = 0; r < 4; r++) acc[mt][nt][r] = 0.0f;

    auto load_stage = [&](int stage, int chunk) {
        const int k0 = chunk * 32;
        const uint32_t sb = sb0 + stage * PSTAGE;
#pragma unroll
        for (int j = 0; j < 2; j++) {
            int row = ldRow0 + j * 64;
            uint32_t so = (uint32_t)(row * 80) + ldQ;
            CP16(sb + OFF_AH + so, &a_hi[(size_t)(blockRow + row) * D_MODEL + k0] + ldQ / 2);
            CP16(sb + OFF_AL + so, &a_lo[(size_t)(blockRow + row) * D_MODEL + k0] + ldQ / 2);
            CP16(sb + OFF_BH + so, &wh[(size_t)(blockCol + row) * D_MODEL + k0] + ldQ / 2);
        }
        CP_COMMIT();
    };

    load_stage(0, 0);

    for (int chunk = 0; chunk < 32; chunk++) {
        if (chunk < 31) { load_stage((chunk + 1) & 1, chunk + 1); CP_WAIT1(); }
        else           { CP_WAIT0(); }
        __syncthreads();

        const uint32_t sb = sb0 + (chunk & 1) * PSTAGE;
        const uint32_t aAddrBase = sb + (uint32_t)(((warpM + lmRow) * SPAD + lmK) * 2);
        const uint32_t bAddrBase = sb + (uint32_t)(((warpN + lmRow) * SPAD + lmK) * 2);

#pragma unroll
        for (int ks = 0; ks < 2; ks++) {
            const uint32_t kOff = (uint32_t)(ks * 16 * 2);
            uint32_t aH[4][4], aL[4][4], bH[4][2];
#pragma unroll
            for (int mt = 0; mt < 4; mt++) {
                uint32_t ad = aAddrBase + kOff + (uint32_t)(mt * 16 * SPAD * 2);
                LDSM4(aH[mt][0], aH[mt][1], aH[mt][2], aH[mt][3], ad + OFF_AH);
                LDSM4(aL[mt][0], aL[mt][1], aL[mt][2], aL[mt][3], ad + OFF_AL);
            }
#pragma unroll
            for (int ntp = 0; ntp < 2; ntp++) {
                uint32_t bd = bAddrBase + kOff + (uint32_t)(ntp * 16 * SPAD * 2);
                uint32_t r0, r1, r2, r3;
                LDSM4(r0, r1, r2, r3, bd + OFF_BH);
                bH[2 * ntp][0] = r0; bH[2 * ntp + 1][0] = r1;
                bH[2 * ntp][1] = r2; bH[2 * ntp + 1][1] = r3;
            }
#pragma unroll
            for (int mt = 0; mt < 4; mt++)
#pragma unroll
                for (int nt = 0; nt < 4; nt++) {
                    MMAH(acc[mt][nt], aH[mt], bH[nt]);
                    MMAH(acc[mt][nt], aL[mt], bH[nt]);
                }
        }
        __syncthreads();
    }

#pragma unroll
    for (int mt = 0; mt < 4; mt++) {
#pragma unroll
        for (int nt = 0; nt < 4; nt++) {
            int row0 = blockRow + warpM + mt * 16 + (lane >> 2);
            int col  = blockCol + warpN + nt * 8 + (lane & 3) * 2;
            float b0 = bias[col], b1 = bias[col + 1];
#pragma unroll
            for (int half = 0; half < 2; half++) {
                int r = row0 + half * 8;
                float vx = acc[mt][nt][half * 2 + 0] + b0;
                float vy = acc[mt][nt][half * 2 + 1] + b1;
                int z = (r >> 11) * NUM_HEADS + (col >> 6);
                int s = r & (SS - 1);
                int d = col & (DEPTH - 1);
                if (zz == 0) {
                    size_t o = ((size_t)z * SS + s) * DEPTH + d;
                    __half hx = __float2half(vx);
                    __half hy = __float2half(vy);
                    __half2 hp = {hx, hy};
                    *(__half2*)&qhi[o] = hp;
                    __half2 lp = {__float2half(vx - __half2float(hx)),
                                  __float2half(vy - __half2float(hy))};
                    *(__half2*)&qlo[o] = lp;
                } else if (zz == 1) {
                    size_t o = ((size_t)z * SS + s) * DEPTH + d;
                    __half2 hp = {__float2half(vx), __float2half(vy)};
                    *(__half2*)&kf[o] = hp;
                } else {
                    size_t o = ((size_t)z * DEPTH + d) * SS + s;
                    __half hx = __float2half(vx);
                    __half hy = __float2half(vy);
                    vthi[o]      = hx;
                    vthi[o + SS] = hy;
                    vtlo[o]      = __float2half(vx - __half2float(hx));
                    vtlo[o + SS] = __float2half(vy - __half2float(hy));
                }
            }
        }
    }
}

__global__ __launch_bounds__(256, 2)
void proj_out_kernel(const __half* __restrict__ a_hi, const __half* __restrict__ a_lo,
                     const __half* __restrict__ w,
                     const float* __restrict__ bias, float* __restrict__ C)
{
    extern __shared__ char smem[];
    const uint32_t sb0 = smem_u32(smem);

    const int tid  = threadIdx.x;
    const int lane = tid & 31;
    const int wid  = tid >> 5;
    const int warpM = (wid >> 2) * 64;
    const int warpN = (wid & 3) * 32;
    const int blockRow = blockIdx.y * 128;
    const int blockCol = blockIdx.x * 128;

    const int ldRow0 = tid >> 2;
    const int ldQ    = (tid & 3) * 16;
    const int lmRow = lane & 15;
    const int lmK   = (lane >> 4) * 8;

    float acc[4][4][4];
#pragma unroll
    for (int mt = 0; mt < 4; mt++)
#pragma unroll
        for (int nt = 0; nt < 4; nt++)
#pragma unroll
            for (int r = 0; r < 4; r++) acc[mt][nt][r] = 0.0f;

    auto load_stage = [&](int stage, int chunk) {
        const int k0 = chunk * 32;
        const uint32_t sb = sb0 + stage * PSTAGE;
#pragma unroll
        for (int j = 0; j < 2; j++) {
            int row = ldRow0 + j * 64;
            uint32_t so = (uint32_t)(row * 80) + ldQ;
            CP16(sb + OFF_AH + so, &a_hi[(size_t)(blockRow + row) * D_MODEL + k0] + ldQ / 2);
            CP16(sb + OFF_AL + so, &a_lo[(size_t)(blockRow + row) * D_MODEL + k0] + ldQ / 2);
            CP16(sb + OFF_BH + so, &w[(size_t)(blockCol + row) * D_MODEL + k0] + ldQ / 2);
        }
        CP_COMMIT();
    };

    load_stage(0, 0);

    for (int chunk = 0; chunk < 32; chunk++) {
        if (chunk < 31) { load_stage((chunk + 1) & 1, chunk + 1); CP_WAIT1(); }
        else           { CP_WAIT0(); }
        __syncthreads();

        const uint32_t sb = sb0 + (chunk & 1) * PSTAGE;
        const uint32_t aAddrBase = sb + (uint32_t)(((warpM + lmRow) * SPAD + lmK) * 2);
        const uint32_t bAddrBase = sb + (uint32_t)(((warpN + lmRow) * SPAD + lmK) * 2);

#pragma unroll
        for (int ks = 0; ks < 2; ks++) {
            const uint32_t kOff = (uint32_t)(ks * 16 * 2);
            uint32_t aH[4][4], aL[4][4], bH[4][2];
#pragma unroll
            for (int mt = 0; mt < 4; mt++) {
                uint32_t ad = aAddrBase + kOff + (uint32_t)(mt * 16 * SPAD * 2);
                LDSM4(aH[mt][0], aH[mt][1], aH[mt][2], aH[mt][3], ad + OFF_AH);
                LDSM4(aL[mt][0], aL[mt][1], aL[mt][2], aL[mt][3], ad + OFF_AL);
            }
#pragma unroll
            for (int ntp = 0; ntp < 2; ntp++) {
                uint32_t bd = bAddrBase + kOff + (uint32_t)(ntp * 16 * SPAD * 2);
                uint32_t r0, r1, r2, r3;
                LDSM4(r0, r1, r2, r3, bd + OFF_BH);
                bH[2 * ntp][0] = r0; bH[2 * ntp + 1][0] = r1;
                bH[2 * ntp][1] = r2; bH[2 * ntp + 1][1] = r3;
            }
#pragma unroll
            for (int mt = 0; mt < 4; mt++)
#pragma unroll
                for (int nt = 0; nt < 4; nt++) {
                    MMAH(acc[mt][nt], aH[mt], bH[nt]);
                    MMAH(acc[mt][nt], aL[mt], bH[nt]);
                }
        }
        __syncthreads();
    }

#pragma unroll
    for (int mt = 0; mt < 4; mt++) {
#pragma unroll
        for (int nt = 0; nt < 4; nt++) {
            int row0 = blockRow + warpM + mt * 16 + (lane >> 2);
            int col  = blockCol + warpN + nt * 8 + (lane & 3) * 2;
            float b0 = bias[col], b1 = bias[col + 1];
#pragma unroll
            for (int half = 0; half < 2; half++) {
                int r = row0 + half * 8;
                float2 v = {acc[mt][nt][half * 2 + 0] + b0, acc[mt][nt][half * 2 + 1] + b1};
                *(float2*)&C[(size_t)r * D_MODEL + col] = v;
            }
        }
    }
}

// ==================== scores: fp16 2-term mma -> e fp16 (staged) =============
#define QPAD 72
#define EPAD 136

__global__ __launch_bounds__(256, 2)
void scores_mma_kernel(const __half* __restrict__ qh, const __half* __restrict__ ql,
                       const __half* __restrict__ kf,
                       const float* __restrict__ mask, __half* __restrict__ eout,
                       float* __restrict__ rowsum)
{
    extern __shared__ char sm[];
    const uint32_t sq = smem_u32(sm);
    __half* sQh = (__half*)sm;
    __half* sQl = sQh + 128 * QPAD;
    __half* sKh = sQl + 128 * QPAD;
    const uint32_t OQH = 0, OQL = 128 * QPAD * 2, OKH = 2 * 128 * QPAD * 2;

    const int z = blockIdx.z;
    const int b = z / NUM_HEADS;
    const int tid = threadIdx.x, lane = tid & 31, wid = tid >> 5;
    const int warpM = (wid >> 2) * 64, warpN = (wid & 3) * 32;
    const int blockRow = blockIdx.y * 128, blockCol = blockIdx.x * 128;
    const int lmRow = lane & 15, lmK = (lane >> 4) * 8;

#pragma unroll
    for (int i = 0; i < 4; i++) {
        int id = tid + i * 256;
        int row = id >> 3, q = id & 7;
        size_t gq = ((size_t)z * SS + blockRow + row) * DEPTH + q * 8;
        size_t gk = ((size_t)z * SS + blockCol + row) * DEPTH + q * 8;
        int so = row * QPAD + q * 8;
        *(uint4*)&sQh[so] = *(const uint4*)&qh[gq];
        *(uint4*)&sQl[so] = *(const uint4*)&ql[gq];
        *(uint4*)&sKh[so] = *(const uint4*)&kf[gk];
    }
    __syncthreads();

    float acc[4][4][4];
#pragma unroll
    for (int mt = 0; mt < 4; mt++)
#pragma unroll
        for (int nt = 0; nt < 4; nt++)
#pragma unroll
            for (int r = 0; r < 4; r++) acc[mt][nt][r] = 0.0f;

    const uint32_t aAddrBase = sq + (uint32_t)(((warpM + lmRow) * QPAD + lmK) * 2);
    const uint32_t bAddrBase = sq + (uint32_t)(((warpN + lmRow) * QPAD + lmK) * 2);

#pragma unroll
    for (int ks = 0; ks < 4; ks++) {
        const uint32_t kOff = (uint32_t)(ks * 16 * 2);
        uint32_t aH[4][4], aL[4][4], bH[4][2];
#pragma unroll
        for (int mt = 0; mt < 4; mt++) {
            uint32_t ad = aAddrBase + kOff + (uint32_t)(mt * 16 * QPAD * 2);
            LDSM4(aH[mt][0], aH[mt][1], aH[mt][2], aH[mt][3], ad + OQH);
            LDSM4(aL[mt][0], aL[mt][1], aL[mt][2], aL[mt][3], ad + OQL);
        }
#pragma unroll
        for (int ntp = 0; ntp < 2; ntp++) {
            uint32_t bd = bAddrBase + kOff + (uint32_t)(ntp * 16 * QPAD * 2);
            uint32_t r0, r1, r2, r3;
            LDSM4(r0, r1, r2, r3, bd + OKH);
            bH[2 * ntp][0] = r0; bH[2 * ntp + 1][0] = r1;
            bH[2 * ntp][1] = r2; bH[2 * ntp + 1][1] = r3;
        }
#pragma unroll
        for (int mt = 0; mt < 4; mt++)
#pragma unroll
            for (int nt = 0; nt < 4; nt++) {
                MMAH(acc[mt][nt], aH[mt], bH[nt]);
                MMAH(acc[mt][nt], aL[mt], bH[nt]);
            }
    }

    float mcol[4][2];
#pragma unroll
    for (int nt = 0; nt < 4; nt++) {
        int col = blockCol + warpN + nt * 8 + (lane & 3) * 2;
        mcol[nt][0] = mask[(size_t)b * SS + col]     * (-1e9f);
        mcol[nt][1] = mask[(size_t)b * SS + col + 1] * (-1e9f);
    }

    __syncthreads();
    __half* sE = (__half*)sm;   // 128 x EPAD

#pragma unroll
    for (int mt = 0; mt < 4; mt++) {
#pragma unroll
        for (int half = 0; half < 2; half++) {
            int lrow = warpM + mt * 16 + (lane >> 2) + half * 8;
            float rs = 0.0f;
#pragma unroll
            for (int nt = 0; nt < 4; nt++) {
                int lcol = warpN + nt * 8 + (lane & 3) * 2;
                float e0 = __expf(acc[mt][nt][half * 2 + 0] * 0.125f + mcol[nt][0]);
                float e1 = __expf(acc[mt][nt][half * 2 + 1] * 0.125f + mcol[nt][1]);
                rs += e0 + e1;
                *(__half2*)&sE[lrow * EPAD + lcol] = __floats2half2_rn(e0, e1);
            }
            rs += __shfl_xor_sync(0xffffffffu, rs, 1);
            rs += __shfl_xor_sync(0xffffffffu, rs, 2);
            if ((lane & 3) == 0)
                rowsum[((size_t)z * SS + blockRow + lrow) * RS_W + blockIdx.x * 4 + (wid & 3)] = rs;
        }
    }
    __syncthreads();

    __half* Ez = eout + (size_t)z * SS * SS;
#pragma unroll
    for (int i = 0; i < 8; i++) {
        int id = tid + i * 256;
        int row = id >> 4, q = id & 15;
        *(uint4*)&Ez[(size_t)(blockRow + row) * SS + blockCol + q * 8] =
            *(const uint4*)&sE[row * EPAD + q * 8];
    }
}

// ==================== AV: K-chunk 64, fused attn normalize ===================
#define AVPAD 72

__global__ __launch_bounds__(256, 2)
void av_mma_kernel(const __half* __restrict__ e,
                   const __half* __restrict__ vth, const __half* __restrict__ vtl,
                   const float* __restrict__ rowsum, float* __restrict__ attn,
                   __half* __restrict__ o_hi, __half* __restrict__ o_lo)
{
    __shared__ alignas(16) __half sA[128 * AVPAD];
    __shared__ alignas(16) __half sBh[64 * AVPAD];
    __shared__ alignas(16) __half sBl[64 * AVPAD];
    __shared__ float invs[128];

    const uint32_t aA = smem_u32(sA);
    const uint32_t aBh = smem_u32(sBh), aBl = smem_u32(sBl);

    const int z = blockIdx.y;
    const int b = z / NUM_HEADS, h = z % NUM_HEADS;
    const int rowbase = blockIdx.x * 128;
    const int tid = threadIdx.x, lane = tid & 31, wid = tid >> 5;
    const int warpM = (wid >> 1) * 32, warpN = (wid & 1) * 32;
    const int lmRow = lane & 15, lmK = (lane >> 4) * 8;

    if (tid < 128) {
        const float* rp = &rowsum[((size_t)z * SS + rowbase + tid) * RS_W];
        float s = 0.0f;
#pragma unroll
        for (int j = 0; j < RS_W; j++) s += rp[j];
        invs[tid] = 1.0f / s;
    }
    __syncthreads();

    const __half* Ez = e + (size_t)z * SS * SS;
    float* Az = attn + (size_t)z * SS * SS;

    float acc[2][4][4];
#pragma unroll
    for (int mt = 0; mt < 2; mt++)
#pragma unroll
        for (int nt = 0; nt < 4; nt++)
#pragma unroll
            for (int r = 0; r < 4; r++) acc[mt][nt][r] = 0.0f;

    for (int k0 = 0; k0 < SS; k0 += 64) {
        // e: 128 rows x 64 halves; also emit normalized fp32 attn
#pragma unroll
        for (int i = 0; i < 4; i++) {
            int id = tid + i * 256;            // 0..1023
            int row = id >> 3, q = id & 7;
            uint4 ev = *(const uint4*)&Ez[(size_t)(rowbase + row) * SS + k0 + q * 8];
            *(uint4*)&sA[row * AVPAD + q * 8] = ev;
            const float inv = invs[row];
            const __half2* hp = (const __half2*)&ev;
            float2 f0 = __half22float2(hp[0]);
            float2 f1 = __half22float2(hp[1]);
            float2 f2 = __half22float2(hp[2]);
            float2 f3 = __half22float2(hp[3]);
            float4 v0 = {f0.x * inv, f0.y * inv, f1.x * inv, f1.y * inv};
            float4 v1 = {f2.x * inv, f2.y * inv, f3.x * inv, f3.y * inv};
            size_t ao = (size_t)(rowbase + row) * SS + k0 + q * 8;
            *(float4*)&Az[ao]     = v0;
            *(float4*)&Az[ao + 4] = v1;
        }
        // V: 64 rows x 64 halves x2 arrays
#pragma unroll
        for (int i = 0; i < 2; i++) {
            int id = tid + i * 256;            // 0..511
            int row = id >> 3, q = id & 7;
            size_t g = ((size_t)z * DEPTH + row) * SS + k0 + q * 8;
            *(uint4*)&sBh[row * AVPAD + q * 8] = *(const uint4*)&vth[g];
            *(uint4*)&sBl[row * AVPAD + q * 8] = *(const uint4*)&vtl[g];
        }
        __syncthreads();

        const uint32_t aBase = (uint32_t)(((warpM + lmRow) * AVPAD + lmK) * 2);
        const uint32_t bBase = (uint32_t)(((warpN + lmRow) * AVPAD + lmK) * 2);

#pragma unroll
        for (int ks = 0; ks < 4; ks++) {
            const uint32_t kOff = (uint32_t)(ks * 16 * 2);
            uint32_t aF[2][4], bH[4][2], bL[4][2];
#pragma unroll
            for (int mt = 0; mt < 2; mt++) {
                uint32_t ad = aBase + kOff + (uint32_t)(mt * 16 * AVPAD * 2);
                LDSM4(aF[mt][0], aF[mt][1], aF[mt][2], aF[mt][3], aA + ad);
            }
#pragma unroll
            for (int ntp = 0; ntp < 2; ntp++) {
                uint32_t bd = bBase + kOff + (uint32_t)(ntp * 16 * AVPAD * 2);
                uint32_t r0, r1, r2, r3;
                LDSM4(r0, r1, r2, r3, aBh + bd);
                bH[2 * ntp][0] = r0; bH[2 * ntp + 1][0] = r1;
                bH[2 * ntp][1] = r2; bH[2 * ntp + 1][1] = r3;
                LDSM4(r0, r1, r2, r3, aBl + bd);
                bL[2 * ntp][0] = r0; bL[2 * ntp + 1][0] = r1;
                bL[2 * ntp][1] = r2; bL[2 * ntp + 1][1] = r3;
            }
#pragma unroll
            for (int mt = 0; mt < 2; mt++)
#pragma unroll
                for (int nt = 0; nt < 4; nt++) {
                    MMAH(acc[mt][nt], aF[mt], bH[nt]);
                    MMAH(acc[mt][nt], aF[mt], bL[nt]);
                }
        }
        __syncthreads();
    }

#pragma unroll
    for (int mt = 0; mt < 2; mt++) {
#pragma unroll
        for (int nt = 0; nt < 4; nt++) {
            int lrow0 = warpM + mt * 16 + (lane >> 2);
            int col   = warpN + nt * 8 + (lane & 3) * 2;
#pragma unroll
            for (int half = 0; half < 2; half++) {
                int lr = lrow0 + half * 8;
                float inv = invs[lr];
                int r = rowbase + lr;
                float vx = acc[mt][nt][half * 2 + 0] * inv;
                float vy = acc[mt][nt][half * 2 + 1] * inv;
                size_t o = ((size_t)b * SS + r) * D_MODEL + h * DEPTH + col;
                __half hx = __float2half(vx);
                __half hy = __float2half(vy);
                __half2 hp = {hx, hy};
                *(__half2*)&o_hi[o] = hp;
                __half2 lp = {__float2half(vx - __half2float(hx)),
                              __float2half(vy - __half2float(hy))};
                *(__half2*)&o_lo[o] = lp;
            }
        }
    }
}

// =====================================================================
extern "C" void kernel_launch(void* const* d_in, const int* in_sizes, int n_in,
                              void* d_out, int out_size)
{
    const float* Q    = (const float*)d_in[0];
    const float* K    = (const float*)d_in[1];
    const float* V    = (const float*)d_in[2];
    const float* mask = (const float*)d_in[3];
    const float* Wq   = (const float*)d_in[4];
    const float* bq   = (const float*)d_in[5];
    const float* Wk   = (const float*)d_in[6];
    const float* bk   = (const float*)d_in[7];
    const float* Wv   = (const float*)d_in[8];
    const float* bv   = (const float*)d_in[9];
    const float* Wo   = (const float*)d_in[10];
    const float* bo   = (const float*)d_in[11];

    float* out = (float*)d_out;

    float *rowsum, *attn;
    __half *inh, *inl, *w, *qhi, *qlo, *kf, *vth, *vtl, *ohi, *olo, *ebuf;
    cudaGetSymbolAddress((void**)&rowsum, g_rowsum);
    cudaGetSymbolAddress((void**)&ebuf, g_e);
    cudaGetSymbolAddress((void**)&inh, g_in_hi);
    cudaGetSymbolAddress((void**)&inl, g_in_lo);
    cudaGetSymbolAddress((void**)&w, g_w);
    cudaGetSymbolAddress((void**)&qhi, g_q_hi);
    cudaGetSymbolAddress((void**)&qlo, g_q_lo);
    cudaGetSymbolAddress((void**)&kf, g_k_f);
    cudaGetSymbolAddress((void**)&vth, g_vt_hi);
    cudaGetSymbolAddress((void**)&vtl, g_vt_lo);
    cudaGetSymbolAddress((void**)&ohi, g_o_hi);
    cudaGetSymbolAddress((void**)&olo, g_o_lo);

    if ((size_t)out_size >= OUT_ELEMS + ATTN_ELEMS) {
        attn = out + OUT_ELEMS;
    } else {
        cudaGetSymbolAddress((void**)&attn, g_attn_fallback);
    }

    static bool attr_done = false;
    if (!attr_done) {
        cudaFuncSetAttribute(proj_qkv_kernel, cudaFuncAttributeMaxDynamicSharedMemorySize, 2 * PSTAGE);
        cudaFuncSetAttribute(proj_out_kernel, cudaFuncAttributeMaxDynamicSharedMemorySize, 2 * PSTAGE);
        cudaFuncSetAttribute(scores_mma_kernel, cudaFuncAttributeMaxDynamicSharedMemorySize, 3 * 128 * QPAD * 2);
        attr_done = true;
    }

    // 1. splits
    dim3 wtBlock(32, 8);
    split_w4_kernel<<<dim3(32, 32, 4), wtBlock>>>(Wq, Wk, Wv, Wo, w);
    split_in3_kernel<<<dim3(NELEM / 256, 3), 256>>>(Q, K, V, inh, inl);

    // 2. QKV projections (fp16 2-term)
    proj_qkv_kernel<<<dim3(8, 32, 3), 256, 2 * PSTAGE>>>(
        inh, inl, w, bq, bk, bv, qhi, qlo, kf, vth, vtl);

    // 3. scores -> e fp16 + rowsum partials
    scores_mma_kernel<<<dim3(16, 16, NZ), 256, 3 * 128 * QPAD * 2>>>(
        qhi, qlo, kf, mask, ebuf, rowsum);

    // 4. AV + fused attn normalize; O -> fp16 hi/lo
    av_mma_kernel<<<dim3(16, NZ), 256>>>(ebuf, vth, vtl, rowsum, attn, ohi, olo);

    // 5. output projection (fp16 2-term)
    proj_out_kernel<<<dim3(8, 32), 256, 2 * PSTAGE>>>(
        ohi, olo, w + (size_t)3 * WELEM, bo, out);
}

// round 10
// speedup vs baseline: 3.8884x; 1.1691x over previous
#include <cuda_runtime.h>
#include <cuda_bf16.h>
#include <cuda_fp16.h>
#include <cstdint>
#include <math.h>

#define D_MODEL   1024
#define NUM_HEADS 16
#define DEPTH     64
#define BB        2
#define SS        2048
#define MROWS     (BB * SS)                              // 4096
#define ATTN_ELEMS ((size_t)BB * NUM_HEADS * SS * SS)    // 134,217,728
#define OUT_ELEMS  ((size_t)MROWS * D_MODEL)             // 4,194,304
#define NZ        (BB * NUM_HEADS)                       // 32
#define RS_W      64
#define NELEM     (MROWS * D_MODEL)                      // 4,194,304
#define WELEM     (D_MODEL * D_MODEL)                    // 1,048,576

// ---------------- scratch (static device globals; no allocations) ------------
__device__ float g_rowsum[(size_t)NZ * SS * RS_W];
__device__ __half g_e[ATTN_ELEMS];                       // unnormalized exp
__device__ __half g_in[3 * (size_t)NELEM];               // QKV inputs fp16
__device__ __half g_w[4 * (size_t)WELEM];                // Wq,Wk,Wv,Wo [n][k] fp16
__device__ __half g_q_hi[(size_t)NZ * SS * DEPTH];       // [z,s,d]
__device__ __half g_q_lo[(size_t)NZ * SS * DEPTH];
__device__ __half g_k_f[(size_t)NZ * SS * DEPTH];        // [z,s,d]
__device__ __half g_vt_hi[(size_t)NZ * SS * DEPTH];      // [z,d,s]
__device__ __half g_vt_lo[(size_t)NZ * SS * DEPTH];
__device__ __half g_o_hi[(size_t)NELEM];                 // O fp16 hi/lo
__device__ __half g_o_lo[(size_t)NELEM];
__device__ float g_attn_fallback[ATTN_ELEMS];

// ============================ PTX helpers ====================================
#define MMAH(d, a, b)                                                         \
    asm volatile("mma.sync.aligned.m16n8k16.row.col.f32.f16.f16.f32 "         \
        "{%0,%1,%2,%3}, {%4,%5,%6,%7}, {%8,%9}, {%0,%1,%2,%3};"               \
        : "+f"((d)[0]), "+f"((d)[1]), "+f"((d)[2]), "+f"((d)[3])              \
        : "r"((a)[0]), "r"((a)[1]), "r"((a)[2]), "r"((a)[3]),                 \
          "r"((b)[0]), "r"((b)[1]))

#define LDSM4(R0, R1, R2, R3, ADDR)                                           \
    asm volatile("ldmatrix.sync.aligned.m8n8.x4.shared.b16 {%0,%1,%2,%3}, [%4];" \
        : "=r"(R0), "=r"(R1), "=r"(R2), "=r"(R3) : "r"(ADDR))

#define CP16(SADDR, GPTR)                                                     \
    asm volatile("cp.async.cg.shared.global [%0], [%1], 16;"                  \
        :: "r"(SADDR), "l"(GPTR))
#define CP_COMMIT() asm volatile("cp.async.commit_group;" ::: "memory")
#define CP_WAIT1()  asm volatile("cp.async.wait_group 1;" ::: "memory")
#define CP_WAIT0()  asm volatile("cp.async.wait_group 0;" ::: "memory")

__device__ __forceinline__ uint32_t smem_u32(const void* p) {
    uint32_t a;
    asm("{ .reg .u64 t; cvta.to.shared.u64 t, %1; cvt.u32.u64 %0, t; }" : "=r"(a) : "l"(p));
    return a;
}

// ============================ split kernels ==================================
__global__ __launch_bounds__(256)
void split_in3_kernel(const float* __restrict__ Q, const float* __restrict__ K,
                      const float* __restrict__ V, __half* __restrict__ dst)
{
    int z = blockIdx.y;
    const float* A = (z == 0) ? Q : (z == 1) ? K : V;
    size_t i = (size_t)blockIdx.x * 256 + threadIdx.x;
    dst[(size_t)z * NELEM + i] = __float2half(A[i]);
}

__global__ __launch_bounds__(256)
void split_w4_kernel(const float* __restrict__ W0, const float* __restrict__ W1,
                     const float* __restrict__ W2, const float* __restrict__ W3,
                     __half* __restrict__ wt)
{
    __shared__ float t[32][33];
    int z = blockIdx.z;
    const float* W = (z == 0) ? W0 : (z == 1) ? W1 : (z == 2) ? W2 : W3;
    int tx = threadIdx.x, ty = threadIdx.y;
    int n0 = blockIdx.x * 32, k0 = blockIdx.y * 32;
#pragma unroll
    for (int j = 0; j < 4; j++)
        t[ty + j * 8][tx] = W[(size_t)(k0 + ty + j * 8) * D_MODEL + n0 + tx];
    __syncthreads();
#pragma unroll
    for (int j = 0; j < 4; j++) {
        size_t o = (size_t)z * WELEM + (size_t)(n0 + ty + j * 8) * D_MODEL + k0 + tx;
        wt[o] = __float2half(t[tx][ty + j * 8]);
    }
}

// ==================== QKV projection: fp16 x fp16, K-chunk 64 ================
#define P2PAD 72
#define P2STAGE 36864     // 2 arrays * 128*72*2
#define P2_OFF_A 0
#define P2_OFF_B 18432

__global__ __launch_bounds__(256, 2)
void proj_qkv_kernel(const __half* __restrict__ in, const __half* __restrict__ w,
                     const float* __restrict__ bq, const float* __restrict__ bk,
                     const float* __restrict__ bv,
                     __half* __restrict__ qhi, __half* __restrict__ qlo,
                     __half* __restrict__ kf,
                     __half* __restrict__ vthi, __half* __restrict__ vtlo)
{
    extern __shared__ char smem[];
    const uint32_t sb0 = smem_u32(smem);

    const int zz = blockIdx.z;
    const __half* a  = in + (size_t)zz * NELEM;
    const __half* wh = w + (size_t)zz * WELEM;
    const float* bias = (zz == 0) ? bq : (zz == 1) ? bk : bv;

    const int tid  = threadIdx.x;
    const int lane = tid & 31;
    const int wid  = tid >> 5;
    const int warpM = (wid >> 2) * 64;
    const int warpN = (wid & 3) * 32;
    const int blockRow = blockIdx.y * 128;
    const int blockCol = blockIdx.x * 128;

    const int lmRow = lane & 15;
    const int lmK   = (lane >> 4) * 8;

    float acc[4][4][4];
#pragma unroll
    for (int mt = 0; mt < 4; mt++)
#pragma unroll
        for (int nt = 0; nt < 4; nt++)
#pragma unroll
            for (int r = 0; r < 4; r++) acc[mt][nt][r] = 0.0f;

    auto load_stage = [&](int stage, int chunk) {
        const int k0 = chunk * 64;
        const uint32_t sb = sb0 + stage * P2STAGE;
#pragma unroll
        for (int j = 0; j < 4; j++) {
            int id = tid + j * 256;            // 0..1023
            int row = id >> 3, q = id & 7;
            uint32_t so = (uint32_t)(row * 144 + q * 16);
            CP16(sb + P2_OFF_A + so, &a[(size_t)(blockRow + row) * D_MODEL + k0 + q * 8]);
            CP16(sb + P2_OFF_B + so, &wh[(size_t)(blockCol + row) * D_MODEL + k0 + q * 8]);
        }
        CP_COMMIT();
    };

    load_stage(0, 0);

    for (int chunk = 0; chunk < 16; chunk++) {
        if (chunk < 15) { load_stage((chunk + 1) & 1, chunk + 1); CP_WAIT1(); }
        else           { CP_WAIT0(); }
        __syncthreads();

        const uint32_t sb = sb0 + (chunk & 1) * P2STAGE;
        const uint32_t aBase = sb + P2_OFF_A + (uint32_t)(((warpM + lmRow) * P2PAD + lmK) * 2);
        const uint32_t bBase = sb + P2_OFF_B + (uint32_t)(((warpN + lmRow) * P2PAD + lmK) * 2);

#pragma unroll
        for (int ks = 0; ks < 4; ks++) {
            const uint32_t kOff = (uint32_t)(ks * 16 * 2);
            uint32_t aF[4][4], bH[4][2];
#pragma unroll
            for (int mt = 0; mt < 4; mt++) {
                uint32_t ad = aBase + kOff + (uint32_t)(mt * 16 * P2PAD * 2);
                LDSM4(aF[mt][0], aF[mt][1], aF[mt][2], aF[mt][3], ad);
            }
#pragma unroll
            for (int ntp = 0; ntp < 2; ntp++) {
                uint32_t bd = bBase + kOff + (uint32_t)(ntp * 16 * P2PAD * 2);
                uint32_t r0, r1, r2, r3;
                LDSM4(r0, r1, r2, r3, bd);
                bH[2 * ntp][0] = r0; bH[2 * ntp + 1][0] = r1;
                bH[2 * ntp][1] = r2; bH[2 * ntp + 1][1] = r3;
            }
#pragma unroll
            for (int mt = 0; mt < 4; mt++)
#pragma unroll
                for (int nt = 0; nt < 4; nt++)
                    MMAH(acc[mt][nt], aF[mt], bH[nt]);
        }
        __syncthreads();
    }

#pragma unroll
    for (int mt = 0; mt < 4; mt++) {
#pragma unroll
        for (int nt = 0; nt < 4; nt++) {
            int row0 = blockRow + warpM + mt * 16 + (lane >> 2);
            int col  = blockCol + warpN + nt * 8 + (lane & 3) * 2;
            float b0 = bias[col], b1 = bias[col + 1];
#pragma unroll
            for (int half = 0; half < 2; half++) {
                int r = row0 + half * 8;
                float vx = acc[mt][nt][half * 2 + 0] + b0;
                float vy = acc[mt][nt][half * 2 + 1] + b1;
                int z = (r >> 11) * NUM_HEADS + (col >> 6);
                int s = r & (SS - 1);
                int d = col & (DEPTH - 1);
                if (zz == 0) {
                    size_t o = ((size_t)z * SS + s) * DEPTH + d;
                    __half hx = __float2half(vx);
                    __half hy = __float2half(vy);
                    __half2 hp = {hx, hy};
                    *(__half2*)&qhi[o] = hp;
                    __half2 lp = {__float2half(vx - __half2float(hx)),
                                  __float2half(vy - __half2float(hy))};
                    *(__half2*)&qlo[o] = lp;
                } else if (zz == 1) {
                    size_t o = ((size_t)z * SS + s) * DEPTH + d;
                    __half2 hp = {__float2half(vx), __float2half(vy)};
                    *(__half2*)&kf[o] = hp;
                } else {
                    size_t o = ((size_t)z * DEPTH + d) * SS + s;
                    __half hx = __float2half(vx);
                    __half hy = __float2half(vy);
                    vthi[o]      = hx;
                    vthi[o + SS] = hy;
                    vtlo[o]      = __float2half(vx - __half2float(hx));
                    vtlo[o + SS] = __float2half(vy - __half2float(hy));
                }
            }
        }
    }
}

// ==================== output projection: O(hi/lo) x W fp16, 2 MMA ============
#define SPAD 40
#define PSTAGE 30720
#define OFF_AH 0
#define OFF_AL 10240
#define OFF_BH 20480

__global__ __launch_bounds__(256, 2)
void proj_out_kernel(const __half* __restrict__ a_hi, const __half* __restrict__ a_lo,
                     const __half* __restrict__ w,
                     const float* __restrict__ bias, float* __restrict__ C)
{
    extern __shared__ char smem[];
    const uint32_t sb0 = smem_u32(smem);

    const int tid  = threadIdx.x;
    const int lane = tid & 31;
    const int wid  = tid >> 5;
    const int warpM = (wid >> 2) * 64;
    const int warpN = (wid & 3) * 32;
    const int blockRow = blockIdx.y * 128;
    const int blockCol = blockIdx.x * 128;

    const int ldRow0 = tid >> 2;
    const int ldQ    = (tid & 3) * 16;
    const int lmRow = lane & 15;
    const int lmK   = (lane >> 4) * 8;

    float acc[4][4][4];
#pragma unroll
    for (int mt = 0; mt < 4; mt++)
#pragma unroll
        for (int nt = 0; nt < 4; nt++)
#pragma unroll
            for (int r = 0; r < 4; r++) acc[mt][nt][r] = 0.0f;

    auto load_stage = [&](int stage, int chunk) {
        const int k0 = chunk * 32;
        const uint32_t sb = sb0 + stage * PSTAGE;
#pragma unroll
        for (int j = 0; j < 2; j++) {
            int row = ldRow0 + j * 64;
            uint32_t so = (uint32_t)(row * 80) + ldQ;
            CP16(sb + OFF_AH + so, &a_hi[(size_t)(blockRow + row) * D_MODEL + k0] + ldQ / 2);
            CP16(sb + OFF_AL + so, &a_lo[(size_t)(blockRow + row) * D_MODEL + k0] + ldQ / 2);
            CP16(sb + OFF_BH + so, &w[(size_t)(blockCol + row) * D_MODEL + k0] + ldQ / 2);
        }
        CP_COMMIT();
    };

    load_stage(0, 0);

    for (int chunk = 0; chunk < 32; chunk++) {
        if (chunk < 31) { load_stage((chunk + 1) & 1, chunk + 1); CP_WAIT1(); }
        else           { CP_WAIT0(); }
        __syncthreads();

        const uint32_t sb = sb0 + (chunk & 1) * PSTAGE;
        const uint32_t aAddrBase = sb + (uint32_t)(((warpM + lmRow) * SPAD + lmK) * 2);
        const uint32_t bAddrBase = sb + (uint32_t)(((warpN + lmRow) * SPAD + lmK) * 2);

#pragma unroll
        for (int ks = 0; ks < 2; ks++) {
            const uint32_t kOff = (uint32_t)(ks * 16 * 2);
            uint32_t aH[4][4], aL[4][4], bH[4][2];
#pragma unroll
            for (int mt = 0; mt < 4; mt++) {
                uint32_t ad = aAddrBase + kOff + (uint32_t)(mt * 16 * SPAD * 2);
                LDSM4(aH[mt][0], aH[mt][1], aH[mt][2], aH[mt][3], ad + OFF_AH);
                LDSM4(aL[mt][0], aL[mt][1], aL[mt][2], aL[mt][3], ad + OFF_AL);
            }
#pragma unroll
            for (int ntp = 0; ntp < 2; ntp++) {
                uint32_t bd = bAddrBase + kOff + (uint32_t)(ntp * 16 * SPAD * 2);
                uint32_t r0, r1, r2, r3;
                LDSM4(r0, r1, r2, r3, bd + OFF_BH);
                bH[2 * ntp][0] = r0; bH[2 * ntp + 1][0] = r1;
                bH[2 * ntp][1] = r2; bH[2 * ntp + 1][1] = r3;
            }
#pragma unroll
            for (int mt = 0; mt < 4; mt++)
#pragma unroll
                for (int nt = 0; nt < 4; nt++) {
                    MMAH(acc[mt][nt], aH[mt], bH[nt]);
                    MMAH(acc[mt][nt], aL[mt], bH[nt]);
                }
        }
        __syncthreads();
    }

#pragma unroll
    for (int mt = 0; mt < 4; mt++) {
#pragma unroll
        for (int nt = 0; nt < 4; nt++) {
            int row0 = blockRow + warpM + mt * 16 + (lane >> 2);
            int col  = blockCol + warpN + nt * 8 + (lane & 3) * 2;
            float b0 = bias[col], b1 = bias[col + 1];
#pragma unroll
            for (int half = 0; half < 2; half++) {
                int r = row0 + half * 8;
                float2 v = {acc[mt][nt][half * 2 + 0] + b0, acc[mt][nt][half * 2 + 1] + b1};
                *(float2*)&C[(size_t)r * D_MODEL + col] = v;
            }
        }
    }
}

// ==================== scores: fp16 2-term mma -> e fp16 (staged) =============
#define QPAD 72
#define EPAD 136

__global__ __launch_bounds__(256, 2)
void scores_mma_kernel(const __half* __restrict__ qh, const __half* __restrict__ ql,
                       const __half* __restrict__ kf,
                       const float* __restrict__ mask, __half* __restrict__ eout,
                       float* __restrict__ rowsum)
{
    extern __shared__ char sm[];
    const uint32_t sq = smem_u32(sm);
    __half* sQh = (__half*)sm;
    __half* sQl = sQh + 128 * QPAD;
    __half* sKh = sQl + 128 * QPAD;
    const uint32_t OQH = 0, OQL = 128 * QPAD * 2, OKH = 2 * 128 * QPAD * 2;

    const int z = blockIdx.z;
    const int b = z / NUM_HEADS;
    const int tid = threadIdx.x, lane = tid & 31, wid = tid >> 5;
    const int warpM = (wid >> 2) * 64, warpN = (wid & 3) * 32;
    const int blockRow = blockIdx.y * 128, blockCol = blockIdx.x * 128;
    const int lmRow = lane & 15, lmK = (lane >> 4) * 8;

#pragma unroll
    for (int i = 0; i < 4; i++) {
        int id = tid + i * 256;
        int row = id >> 3, q = id & 7;
        size_t gq = ((size_t)z * SS + blockRow + row) * DEPTH + q * 8;
        size_t gk = ((size_t)z * SS + blockCol + row) * DEPTH + q * 8;
        int so = row * QPAD + q * 8;
        *(uint4*)&sQh[so] = *(const uint4*)&qh[gq];
        *(uint4*)&sQl[so] = *(const uint4*)&ql[gq];
        *(uint4*)&sKh[so] = *(const uint4*)&kf[gk];
    }
    __syncthreads();

    float acc[4][4][4];
#pragma unroll
    for (int mt = 0; mt < 4; mt++)
#pragma unroll
        for (int nt = 0; nt < 4; nt++)
#pragma unroll
            for (int r = 0; r < 4; r++) acc[mt][nt][r] = 0.0f;

    const uint32_t aAddrBase = sq + (uint32_t)(((warpM + lmRow) * QPAD + lmK) * 2);
    const uint32_t bAddrBase = sq + (uint32_t)(((warpN + lmRow) * QPAD + lmK) * 2);

#pragma unroll
    for (int ks = 0; ks < 4; ks++) {
        const uint32_t kOff = (uint32_t)(ks * 16 * 2);
        uint32_t aH[4][4], aL[4][4], bH[4][2];
#pragma unroll
        for (int mt = 0; mt < 4; mt++) {
            uint32_t ad = aAddrBase + kOff + (uint32_t)(mt * 16 * QPAD * 2);
            LDSM4(aH[mt][0], aH[mt][1], aH[mt][2], aH[mt][3], ad + OQH);
            LDSM4(aL[mt][0], aL[mt][1], aL[mt][2], aL[mt][3], ad + OQL);
        }
#pragma unroll
        for (int ntp = 0; ntp < 2; ntp++) {
            uint32_t bd = bAddrBase + kOff + (uint32_t)(ntp * 16 * QPAD * 2);
            uint32_t r0, r1, r2, r3;
            LDSM4(r0, r1, r2, r3, bd + OKH);
            bH[2 * ntp][0] = r0; bH[2 * ntp + 1][0] = r1;
            bH[2 * ntp][1] = r2; bH[2 * ntp + 1][1] = r3;
        }
#pragma unroll
        for (int mt = 0; mt < 4; mt++)
#pragma unroll
            for (int nt = 0; nt < 4; nt++) {
                MMAH(acc[mt][nt], aH[mt], bH[nt]);
                MMAH(acc[mt][nt], aL[mt], bH[nt]);
            }
    }

    float mcol[4][2];
#pragma unroll
    for (int nt = 0; nt < 4; nt++) {
        int col = blockCol + warpN + nt * 8 + (lane & 3) * 2;
        mcol[nt][0] = mask[(size_t)b * SS + col]     * (-1e9f);
        mcol[nt][1] = mask[(size_t)b * SS + col + 1] * (-1e9f);
    }

    __syncthreads();
    __half* sE = (__half*)sm;

#pragma unroll
    for (int mt = 0; mt < 4; mt++) {
#pragma unroll
        for (int half = 0; half < 2; half++) {
            int lrow = warpM + mt * 16 + (lane >> 2) + half * 8;
            float rs = 0.0f;
#pragma unroll
            for (int nt = 0; nt < 4; nt++) {
                int lcol = warpN + nt * 8 + (lane & 3) * 2;
                float e0 = __expf(acc[mt][nt][half * 2 + 0] * 0.125f + mcol[nt][0]);
                float e1 = __expf(acc[mt][nt][half * 2 + 1] * 0.125f + mcol[nt][1]);
                rs += e0 + e1;
                *(__half2*)&sE[lrow * EPAD + lcol] = __floats2half2_rn(e0, e1);
            }
            rs += __shfl_xor_sync(0xffffffffu, rs, 1);
            rs += __shfl_xor_sync(0xffffffffu, rs, 2);
            if ((lane & 3) == 0)
                rowsum[((size_t)z * SS + blockRow + lrow) * RS_W + blockIdx.x * 4 + (wid & 3)] = rs;
        }
    }
    __syncthreads();

    __half* Ez = eout + (size_t)z * SS * SS;
#pragma unroll
    for (int i = 0; i < 8; i++) {
        int id = tid + i * 256;
        int row = id >> 4, q = id & 15;
        *(uint4*)&Ez[(size_t)(blockRow + row) * SS + blockCol + q * 8] =
            *(const uint4*)&sE[row * EPAD + q * 8];
    }
}

// ==================== AV: K-chunk 64, fused attn normalize ===================
#define AVPAD 72

__global__ __launch_bounds__(256, 2)
void av_mma_kernel(const __half* __restrict__ e,
                   const __half* __restrict__ vth, const __half* __restrict__ vtl,
                   const float* __restrict__ rowsum, float* __restrict__ attn,
                   __half* __restrict__ o_hi, __half* __restrict__ o_lo)
{
    __shared__ alignas(16) __half sA[128 * AVPAD];
    __shared__ alignas(16) __half sBh[64 * AVPAD];
    __shared__ alignas(16) __half sBl[64 * AVPAD];
    __shared__ float invs[128];

    const uint32_t aA = smem_u32(sA);
    const uint32_t aBh = smem_u32(sBh), aBl = smem_u32(sBl);

    const int z = blockIdx.y;
    const int b = z / NUM_HEADS, h = z % NUM_HEADS;
    const int rowbase = blockIdx.x * 128;
    const int tid = threadIdx.x, lane = tid & 31, wid = tid >> 5;
    const int warpM = (wid >> 1) * 32, warpN = (wid & 1) * 32;
    const int lmRow = lane & 15, lmK = (lane >> 4) * 8;

    if (tid < 128) {
        const float* rp = &rowsum[((size_t)z * SS + rowbase + tid) * RS_W];
        float s = 0.0f;
#pragma unroll
        for (int j = 0; j < RS_W; j++) s += rp[j];
        invs[tid] = 1.0f / s;
    }
    __syncthreads();

    const __half* Ez = e + (size_t)z * SS * SS;
    float* Az = attn + (size_t)z * SS * SS;

    float acc[2][4][4];
#pragma unroll
    for (int mt = 0; mt < 2; mt++)
#pragma unroll
        for (int nt = 0; nt < 4; nt++)
#pragma unroll
            for (int r = 0; r < 4; r++) acc[mt][nt][r] = 0.0f;

    for (int k0 = 0; k0 < SS; k0 += 64) {
#pragma unroll
        for (int i = 0; i < 4; i++) {
            int id = tid + i * 256;
            int row = id >> 3, q = id & 7;
            uint4 ev = *(const uint4*)&Ez[(size_t)(rowbase + row) * SS + k0 + q * 8];
            *(uint4*)&sA[row * AVPAD + q * 8] = ev;
            const float inv = invs[row];
            const __half2* hp = (const __half2*)&ev;
            float2 f0 = __half22float2(hp[0]);
            float2 f1 = __half22float2(hp[1]);
            float2 f2 = __half22float2(hp[2]);
            float2 f3 = __half22float2(hp[3]);
            float4 v0 = {f0.x * inv, f0.y * inv, f1.x * inv, f1.y * inv};
            float4 v1 = {f2.x * inv, f2.y * inv, f3.x * inv, f3.y * inv};
            size_t ao = (size_t)(rowbase + row) * SS + k0 + q * 8;
            *(float4*)&Az[ao]     = v0;
            *(float4*)&Az[ao + 4] = v1;
        }
#pragma unroll
        for (int i = 0; i < 2; i++) {
            int id = tid + i * 256;
            int row = id >> 3, q = id & 7;
            size_t g = ((size_t)z * DEPTH + row) * SS + k0 + q * 8;
            *(uint4*)&sBh[row * AVPAD + q * 8] = *(const uint4*)&vth[g];
            *(uint4*)&sBl[row * AVPAD + q * 8] = *(const uint4*)&vtl[g];
        }
        __syncthreads();

        const uint32_t aBase = (uint32_t)(((warpM + lmRow) * AVPAD + lmK) * 2);
        const uint32_t bBase = (uint32_t)(((warpN + lmRow) * AVPAD + lmK) * 2);

#pragma unroll
        for (int ks = 0; ks < 4; ks++) {
            const uint32_t kOff = (uint32_t)(ks * 16 * 2);
            uint32_t aF[2][4], bH[4][2], bL[4][2];
#pragma unroll
            for (int mt = 0; mt < 2; mt++) {
                uint32_t ad = aBase + kOff + (uint32_t)(mt * 16 * AVPAD * 2);
                LDSM4(aF[mt][0], aF[mt][1], aF[mt][2], aF[mt][3], aA + ad);
            }
#pragma unroll
            for (int ntp = 0; ntp < 2; ntp++) {
                uint32_t bd = bBase + kOff + (uint32_t)(ntp * 16 * AVPAD * 2);
                uint32_t r0, r1, r2, r3;
                LDSM4(r0, r1, r2, r3, aBh + bd);
                bH[2 * ntp][0] = r0; bH[2 * ntp + 1][0] = r1;
                bH[2 * ntp][1] = r2; bH[2 * ntp + 1][1] = r3;
                LDSM4(r0, r1, r2, r3, aBl + bd);
                bL[2 * ntp][0] = r0; bL[2 * ntp + 1][0] = r1;
                bL[2 * ntp][1] = r2; bL[2 * ntp + 1][1] = r3;
            }
#pragma unroll
            for (int mt = 0; mt < 2; mt++)
#pragma unroll
                for (int nt = 0; nt < 4; nt++) {
                    MMAH(acc[mt][nt], aF[mt], bH[nt]);
                    MMAH(acc[mt][nt], aF[mt], bL[nt]);
                }
        }
        __syncthreads();
    }

#pragma unroll
    for (int mt = 0; mt < 2; mt++) {
#pragma unroll
        for (int nt = 0; nt < 4; nt++) {
            int lrow0 = warpM + mt * 16 + (lane >> 2);
            int col   = warpN + nt * 8 + (lane & 3) * 2;
#pragma unroll
            for (int half = 0; half < 2; half++) {
                int lr = lrow0 + half * 8;
                float inv = invs[lr];
                int r = rowbase + lr;
                float vx = acc[mt][nt][half * 2 + 0] * inv;
                float vy = acc[mt][nt][half * 2 + 1] * inv;
                size_t o = ((size_t)b * SS + r) * D_MODEL + h * DEPTH + col;
                __half hx = __float2half(vx);
                __half hy = __float2half(vy);
                __half2 hp = {hx, hy};
                *(__half2*)&o_hi[o] = hp;
                __half2 lp = {__float2half(vx - __half2float(hx)),
                              __float2half(vy - __half2float(hy))};
                *(__half2*)&o_lo[o] = lp;
            }
        }
    }
}

// =====================================================================
extern "C" void kernel_launch(void* const* d_in, const int* in_sizes, int n_in,
                              void* d_out, int out_size)
{
    const float* Q    = (const float*)d_in[0];
    const float* K    = (const float*)d_in[1];
    const float* V    = (const float*)d_in[2];
    const float* mask = (const float*)d_in[3];
    const float* Wq   = (const float*)d_in[4];
    const float* bq   = (const float*)d_in[5];
    const float* Wk   = (const float*)d_in[6];
    const float* bk   = (const float*)d_in[7];
    const float* Wv   = (const float*)d_in[8];
    const float* bv   = (const float*)d_in[9];
    const float* Wo   = (const float*)d_in[10];
    const float* bo   = (const float*)d_in[11];

    float* out = (float*)d_out;

    float *rowsum, *attn;
    __half *inb, *w, *qhi, *qlo, *kf, *vth, *vtl, *ohi, *olo, *ebuf;
    cudaGetSymbolAddress((void**)&rowsum, g_rowsum);
    cudaGetSymbolAddress((void**)&ebuf, g_e);
    cudaGetSymbolAddress((void**)&inb, g_in);
    cudaGetSymbolAddress((void**)&w, g_w);
    cudaGetSymbolAddress((void**)&qhi, g_q_hi);
    cudaGetSymbolAddress((void**)&qlo, g_q_lo);
    cudaGetSymbolAddress((void**)&kf, g_k_f);
    cudaGetSymbolAddress((void**)&vth, g_vt_hi);
    cudaGetSymbolAddress((void**)&vtl, g_vt_lo);
    cudaGetSymbolAddress((void**)&ohi, g_o_hi);
    cudaGetSymbolAddress((void**)&olo, g_o_lo);

    if ((size_t)out_size >= OUT_ELEMS + ATTN_ELEMS) {
        attn = out + OUT_ELEMS;
    } else {
        cudaGetSymbolAddress((void**)&attn, g_attn_fallback);
    }

    static bool attr_done = false;
    if (!attr_done) {
        cudaFuncSetAttribute(proj_qkv_kernel, cudaFuncAttributeMaxDynamicSharedMemorySize, 2 * P2STAGE);
        cudaFuncSetAttribute(proj_out_kernel, cudaFuncAttributeMaxDynamicSharedMemorySize, 2 * PSTAGE);
        cudaFuncSetAttribute(scores_mma_kernel, cudaFuncAttributeMaxDynamicSharedMemorySize, 3 * 128 * QPAD * 2);
        attr_done = true;
    }

    // 1. splits
    dim3 wtBlock(32, 8);
    split_w4_kernel<<<dim3(32, 32, 4), wtBlock>>>(Wq, Wk, Wv, Wo, w);
    split_in3_kernel<<<dim3(NELEM / 256, 3), 256>>>(Q, K, V, inb);

    // 2. QKV projections (fp16 x fp16, 1 MMA, K-chunk 64)
    proj_qkv_kernel<<<dim3(8, 32, 3), 256, 2 * P2STAGE>>>(
        inb, w, bq, bk, bv, qhi, qlo, kf, vth, vtl);

    // 3. scores -> e fp16 + rowsum partials
    scores_mma_kernel<<<dim3(16, 16, NZ), 256, 3 * 128 * QPAD * 2>>>(
        qhi, qlo, kf, mask, ebuf, rowsum);

    // 4. AV + fused attn normalize; O -> fp16 hi/lo
    av_mma_kernel<<<dim3(16, NZ), 256>>>(ebuf, vth, vtl, rowsum, attn, ohi, olo);

    // 5. output projection (O hi/lo exact x W fp16)
    proj_out_kernel<<<dim3(8, 32), 256, 2 * PSTAGE>>>(
        ohi, olo, w + (size_t)3 * WELEM, bo, out);
}

// round 11
// speedup vs baseline: 4.1238x; 1.0605x over previous
#include <cuda_runtime.h>
#include <cuda_bf16.h>
#include <cuda_fp16.h>
#include <cstdint>
#include <math.h>

#define D_MODEL   1024
#define NUM_HEADS 16
#define DEPTH     64
#define BB        2
#define SS        2048
#define MROWS     (BB * SS)                              // 4096
#define ATTN_ELEMS ((size_t)BB * NUM_HEADS * SS * SS)    // 134,217,728
#define OUT_ELEMS  ((size_t)MROWS * D_MODEL)             // 4,194,304
#define NZ        (BB * NUM_HEADS)                       // 32
#define RS_W      64
#define NELEM     (MROWS * D_MODEL)                      // 4,194,304
#define WELEM     (D_MODEL * D_MODEL)                    // 1,048,576

// ---------------- scratch (static device globals; no allocations) ------------
__device__ float g_rowsum[(size_t)NZ * SS * RS_W];
__device__ __half g_e[ATTN_ELEMS];                       // unnormalized exp
__device__ __half g_in[3 * (size_t)NELEM];               // QKV inputs fp16
__device__ __half g_w[4 * (size_t)WELEM];                // Wq,Wk,Wv,Wo [n][k] fp16
__device__ __half g_q_f[(size_t)NZ * SS * DEPTH];        // [z,s,d] fp16
__device__ __half g_k_f[(size_t)NZ * SS * DEPTH];        // [z,s,d] fp16
__device__ __half g_vt_hi[(size_t)NZ * SS * DEPTH];      // [z,d,s]
__device__ __half g_vt_lo[(size_t)NZ * SS * DEPTH];
__device__ __half g_o_hi[(size_t)NELEM];                 // O fp16 hi/lo
__device__ __half g_o_lo[(size_t)NELEM];
__device__ float g_attn_fallback[ATTN_ELEMS];

// ============================ PTX helpers ====================================
#define MMAH(d, a, b)                                                         \
    asm volatile("mma.sync.aligned.m16n8k16.row.col.f32.f16.f16.f32 "         \
        "{%0,%1,%2,%3}, {%4,%5,%6,%7}, {%8,%9}, {%0,%1,%2,%3};"               \
        : "+f"((d)[0]), "+f"((d)[1]), "+f"((d)[2]), "+f"((d)[3])              \
        : "r"((a)[0]), "r"((a)[1]), "r"((a)[2]), "r"((a)[3]),                 \
          "r"((b)[0]), "r"((b)[1]))

#define LDSM4(R0, R1, R2, R3, ADDR)                                           \
    asm volatile("ldmatrix.sync.aligned.m8n8.x4.shared.b16 {%0,%1,%2,%3}, [%4];" \
        : "=r"(R0), "=r"(R1), "=r"(R2), "=r"(R3) : "r"(ADDR))

#define CP16(SADDR, GPTR)                                                     \
    asm volatile("cp.async.cg.shared.global [%0], [%1], 16;"                  \
        :: "r"(SADDR), "l"(GPTR))
#define CP_COMMIT() asm volatile("cp.async.commit_group;" ::: "memory")
#define CP_WAIT1()  asm volatile("cp.async.wait_group 1;" ::: "memory")
#define CP_WAIT0()  asm volatile("cp.async.wait_group 0;" ::: "memory")

__device__ __forceinline__ uint32_t smem_u32(const void* p) {
    uint32_t a;
    asm("{ .reg .u64 t; cvta.to.shared.u64 t, %1; cvt.u32.u64 %0, t; }" : "=r"(a) : "l"(p));
    return a;
}

// ============================ split kernels ==================================
__global__ __launch_bounds__(256)
void split_in3_kernel(const float* __restrict__ Q, const float* __restrict__ K,
                      const float* __restrict__ V, __half* __restrict__ dst)
{
    int z = blockIdx.y;
    const float* A = (z == 0) ? Q : (z == 1) ? K : V;
    size_t i = (size_t)blockIdx.x * 256 + threadIdx.x;
    dst[(size_t)z * NELEM + i] = __float2half(A[i]);
}

__global__ __launch_bounds__(256)
void split_w4_kernel(const float* __restrict__ W0, const float* __restrict__ W1,
                     const float* __restrict__ W2, const float* __restrict__ W3,
                     __half* __restrict__ wt)
{
    __shared__ float t[32][33];
    int z = blockIdx.z;
    const float* W = (z == 0) ? W0 : (z == 1) ? W1 : (z == 2) ? W2 : W3;
    int tx = threadIdx.x, ty = threadIdx.y;
    int n0 = blockIdx.x * 32, k0 = blockIdx.y * 32;
#pragma unroll
    for (int j = 0; j < 4; j++)
        t[ty + j * 8][tx] = W[(size_t)(k0 + ty + j * 8) * D_MODEL + n0 + tx];
    __syncthreads();
#pragma unroll
    for (int j = 0; j < 4; j++) {
        size_t o = (size_t)z * WELEM + (size_t)(n0 + ty + j * 8) * D_MODEL + k0 + tx;
        wt[o] = __float2half(t[tx][ty + j * 8]);
    }
}

// ==================== QKV projection: fp16 x fp16, K-chunk 64 ================
#define P2PAD 72
#define P2STAGE 36864     // 2 arrays * 128*72*2
#define P2_OFF_A 0
#define P2_OFF_B 18432

__global__ __launch_bounds__(256, 2)
void proj_qkv_kernel(const __half* __restrict__ in, const __half* __restrict__ w,
                     const float* __restrict__ bq, const float* __restrict__ bk,
                     const float* __restrict__ bv,
                     __half* __restrict__ qf, __half* __restrict__ kf,
                     __half* __restrict__ vthi, __half* __restrict__ vtlo)
{
    extern __shared__ char smem[];
    const uint32_t sb0 = smem_u32(smem);

    const int zz = blockIdx.z;
    const __half* a  = in + (size_t)zz * NELEM;
    const __half* wh = w + (size_t)zz * WELEM;
    const float* bias = (zz == 0) ? bq : (zz == 1) ? bk : bv;

    const int tid  = threadIdx.x;
    const int lane = tid & 31;
    const int wid  = tid >> 5;
    const int warpM = (wid >> 2) * 64;
    const int warpN = (wid & 3) * 32;
    const int blockRow = blockIdx.y * 128;
    const int blockCol = blockIdx.x * 128;

    const int lmRow = lane & 15;
    const int lmK   = (lane >> 4) * 8;

    float acc[4][4][4];
#pragma unroll
    for (int mt = 0; mt < 4; mt++)
#pragma unroll
        for (int nt = 0; nt < 4; nt++)
#pragma unroll
            for (int r = 0; r < 4; r++) acc[mt][nt][r] = 0.0f;

    auto load_stage = [&](int stage, int chunk) {
        const int k0 = chunk * 64;
        const uint32_t sb = sb0 + stage * P2STAGE;
#pragma unroll
        for (int j = 0; j < 4; j++) {
            int id = tid + j * 256;
            int row = id >> 3, q = id & 7;
            uint32_t so = (uint32_t)(row * 144 + q * 16);
            CP16(sb + P2_OFF_A + so, &a[(size_t)(blockRow + row) * D_MODEL + k0 + q * 8]);
            CP16(sb + P2_OFF_B + so, &wh[(size_t)(blockCol + row) * D_MODEL + k0 + q * 8]);
        }
        CP_COMMIT();
    };

    load_stage(0, 0);

    for (int chunk = 0; chunk < 16; chunk++) {
        if (chunk < 15) { load_stage((chunk + 1) & 1, chunk + 1); CP_WAIT1(); }
        else           { CP_WAIT0(); }
        __syncthreads();

        const uint32_t sb = sb0 + (chunk & 1) * P2STAGE;
        const uint32_t aBase = sb + P2_OFF_A + (uint32_t)(((warpM + lmRow) * P2PAD + lmK) * 2);
        const uint32_t bBase = sb + P2_OFF_B + (uint32_t)(((warpN + lmRow) * P2PAD + lmK) * 2);

#pragma unroll
        for (int ks = 0; ks < 4; ks++) {
            const uint32_t kOff = (uint32_t)(ks * 16 * 2);
            uint32_t aF[4][4], bH[4][2];
#pragma unroll
            for (int mt = 0; mt < 4; mt++) {
                uint32_t ad = aBase + kOff + (uint32_t)(mt * 16 * P2PAD * 2);
                LDSM4(aF[mt][0], aF[mt][1], aF[mt][2], aF[mt][3], ad);
            }
#pragma unroll
            for (int ntp = 0; ntp < 2; ntp++) {
                uint32_t bd = bBase + kOff + (uint32_t)(ntp * 16 * P2PAD * 2);
                uint32_t r0, r1, r2, r3;
                LDSM4(r0, r1, r2, r3, bd);
                bH[2 * ntp][0] = r0; bH[2 * ntp + 1][0] = r1;
                bH[2 * ntp][1] = r2; bH[2 * ntp + 1][1] = r3;
            }
#pragma unroll
            for (int mt = 0; mt < 4; mt++)
#pragma unroll
                for (int nt = 0; nt < 4; nt++)
                    MMAH(acc[mt][nt], aF[mt], bH[nt]);
        }
        __syncthreads();
    }

#pragma unroll
    for (int mt = 0; mt < 4; mt++) {
#pragma unroll
        for (int nt = 0; nt < 4; nt++) {
            int row0 = blockRow + warpM + mt * 16 + (lane >> 2);
            int col  = blockCol + warpN + nt * 8 + (lane & 3) * 2;
            float b0 = bias[col], b1 = bias[col + 1];
#pragma unroll
            for (int half = 0; half < 2; half++) {
                int r = row0 + half * 8;
                float vx = acc[mt][nt][half * 2 + 0] + b0;
                float vy = acc[mt][nt][half * 2 + 1] + b1;
                int z = (r >> 11) * NUM_HEADS + (col >> 6);
                int s = r & (SS - 1);
                int d = col & (DEPTH - 1);
                if (zz == 0) {
                    size_t o = ((size_t)z * SS + s) * DEPTH + d;
                    __half2 hp = {__float2half(vx), __float2half(vy)};
                    *(__half2*)&qf[o] = hp;
                } else if (zz == 1) {
                    size_t o = ((size_t)z * SS + s) * DEPTH + d;
                    __half2 hp = {__float2half(vx), __float2half(vy)};
                    *(__half2*)&kf[o] = hp;
                } else {
                    size_t o = ((size_t)z * DEPTH + d) * SS + s;
                    __half hx = __float2half(vx);
                    __half hy = __float2half(vy);
                    vthi[o]      = hx;
                    vthi[o + SS] = hy;
                    vtlo[o]      = __float2half(vx - __half2float(hx));
                    vtlo[o + SS] = __float2half(vy - __half2float(hy));
                }
            }
        }
    }
}

// ==================== output projection: O(hi/lo) x W fp16, 2 MMA ============
#define SPAD 40
#define PSTAGE 30720
#define OFF_AH 0
#define OFF_AL 10240
#define OFF_BH 20480

__global__ __launch_bounds__(256, 2)
void proj_out_kernel(const __half* __restrict__ a_hi, const __half* __restrict__ a_lo,
                     const __half* __restrict__ w,
                     const float* __restrict__ bias, float* __restrict__ C)
{
    extern __shared__ char smem[];
    const uint32_t sb0 = smem_u32(smem);

    const int tid  = threadIdx.x;
    const int lane = tid & 31;
    const int wid  = tid >> 5;
    const int warpM = (wid >> 2) * 64;
    const int warpN = (wid & 3) * 32;
    const int blockRow = blockIdx.y * 128;
    const int blockCol = blockIdx.x * 128;

    const int ldRow0 = tid >> 2;
    const int ldQ    = (tid & 3) * 16;
    const int lmRow = lane & 15;
    const int lmK   = (lane >> 4) * 8;

    float acc[4][4][4];
#pragma unroll
    for (int mt = 0; mt < 4; mt++)
#pragma unroll
        for (int nt = 0; nt < 4; nt++)
#pragma unroll
            for (int r = 0; r < 4; r++) acc[mt][nt][r] = 0.0f;

    auto load_stage = [&](int stage, int chunk) {
        const int k0 = chunk * 32;
        const uint32_t sb = sb0 + stage * PSTAGE;
#pragma unroll
        for (int j = 0; j < 2; j++) {
            int row = ldRow0 + j * 64;
            uint32_t so = (uint32_t)(row * 80) + ldQ;
            CP16(sb + OFF_AH + so, &a_hi[(size_t)(blockRow + row) * D_MODEL + k0] + ldQ / 2);
            CP16(sb + OFF_AL + so, &a_lo[(size_t)(blockRow + row) * D_MODEL + k0] + ldQ / 2);
            CP16(sb + OFF_BH + so, &w[(size_t)(blockCol + row) * D_MODEL + k0] + ldQ / 2);
        }
        CP_COMMIT();
    };

    load_stage(0, 0);

    for (int chunk = 0; chunk < 32; chunk++) {
        if (chunk < 31) { load_stage((chunk + 1) & 1, chunk + 1); CP_WAIT1(); }
        else           { CP_WAIT0(); }
        __syncthreads();

        const uint32_t sb = sb0 + (chunk & 1) * PSTAGE;
        const uint32_t aAddrBase = sb + (uint32_t)(((warpM + lmRow) * SPAD + lmK) * 2);
        const uint32_t bAddrBase = sb + (uint32_t)(((warpN + lmRow) * SPAD + lmK) * 2);

#pragma unroll
        for (int ks = 0; ks < 2; ks++) {
            const uint32_t kOff = (uint32_t)(ks * 16 * 2);
            uint32_t aH[4][4], aL[4][4], bH[4][2];
#pragma unroll
            for (int mt = 0; mt < 4; mt++) {
                uint32_t ad = aAddrBase + kOff + (uint32_t)(mt * 16 * SPAD * 2);
                LDSM4(aH[mt][0], aH[mt][1], aH[mt][2], aH[mt][3], ad + OFF_AH);
                LDSM4(aL[mt][0], aL[mt][1], aL[mt][2], aL[mt][3], ad + OFF_AL);
            }
#pragma unroll
            for (int ntp = 0; ntp < 2; ntp++) {
                uint32_t bd = bAddrBase + kOff + (uint32_t)(ntp * 16 * SPAD * 2);
                uint32_t r0, r1, r2, r3;
                LDSM4(r0, r1, r2, r3, bd + OFF_BH);
                bH[2 * ntp][0] = r0; bH[2 * ntp + 1][0] = r1;
                bH[2 * ntp][1] = r2; bH[2 * ntp + 1][1] = r3;
            }
#pragma unroll
            for (int mt = 0; mt < 4; mt++)
#pragma unroll
                for (int nt = 0; nt < 4; nt++) {
                    MMAH(acc[mt][nt], aH[mt], bH[nt]);
                    MMAH(acc[mt][nt], aL[mt], bH[nt]);
                }
        }
        __syncthreads();
    }

#pragma unroll
    for (int mt = 0; mt < 4; mt++) {
#pragma unroll
        for (int nt = 0; nt < 4; nt++) {
            int row0 = blockRow + warpM + mt * 16 + (lane >> 2);
            int col  = blockCol + warpN + nt * 8 + (lane & 3) * 2;
            float b0 = bias[col], b1 = bias[col + 1];
#pragma unroll
            for (int half = 0; half < 2; half++) {
                int r = row0 + half * 8;
                float2 v = {acc[mt][nt][half * 2 + 0] + b0, acc[mt][nt][half * 2 + 1] + b1};
                *(float2*)&C[(size_t)r * D_MODEL + col] = v;
            }
        }
    }
}

// ==================== scores: single-fp16 mma -> e fp16 (staged) =============
#define QPAD 72
#define EPAD 136

__global__ __launch_bounds__(256, 2)
void scores_mma_kernel(const __half* __restrict__ qf, const __half* __restrict__ kf,
                       const float* __restrict__ mask, __half* __restrict__ eout,
                       float* __restrict__ rowsum)
{
    extern __shared__ char sm[];
    const uint32_t sq = smem_u32(sm);
    __half* sQh = (__half*)sm;
    __half* sKh = sQh + 128 * QPAD;
    const uint32_t OQH = 0, OKH = 128 * QPAD * 2;

    const int z = blockIdx.z;
    const int b = z / NUM_HEADS;
    const int tid = threadIdx.x, lane = tid & 31, wid = tid >> 5;
    const int warpM = (wid >> 2) * 64, warpN = (wid & 3) * 32;
    const int blockRow = blockIdx.y * 128, blockCol = blockIdx.x * 128;
    const int lmRow = lane & 15, lmK = (lane >> 4) * 8;

#pragma unroll
    for (int i = 0; i < 4; i++) {
        int id = tid + i * 256;
        int row = id >> 3, q = id & 7;
        size_t gq = ((size_t)z * SS + blockRow + row) * DEPTH + q * 8;
        size_t gk = ((size_t)z * SS + blockCol + row) * DEPTH + q * 8;
        int so = row * QPAD + q * 8;
        *(uint4*)&sQh[so] = *(const uint4*)&qf[gq];
        *(uint4*)&sKh[so] = *(const uint4*)&kf[gk];
    }
    __syncthreads();

    float acc[4][4][4];
#pragma unroll
    for (int mt = 0; mt < 4; mt++)
#pragma unroll
        for (int nt = 0; nt < 4; nt++)
#pragma unroll
            for (int r = 0; r < 4; r++) acc[mt][nt][r] = 0.0f;

    const uint32_t aAddrBase = sq + (uint32_t)(((warpM + lmRow) * QPAD + lmK) * 2);
    const uint32_t bAddrBase = sq + (uint32_t)(((warpN + lmRow) * QPAD + lmK) * 2);

#pragma unroll
    for (int ks = 0; ks < 4; ks++) {
        const uint32_t kOff = (uint32_t)(ks * 16 * 2);
        uint32_t aH[4][4], bH[4][2];
#pragma unroll
        for (int mt = 0; mt < 4; mt++) {
            uint32_t ad = aAddrBase + kOff + (uint32_t)(mt * 16 * QPAD * 2);
            LDSM4(aH[mt][0], aH[mt][1], aH[mt][2], aH[mt][3], ad + OQH);
        }
#pragma unroll
        for (int ntp = 0; ntp < 2; ntp++) {
            uint32_t bd = bAddrBase + kOff + (uint32_t)(ntp * 16 * QPAD * 2);
            uint32_t r0, r1, r2, r3;
            LDSM4(r0, r1, r2, r3, bd + OKH);
            bH[2 * ntp][0] = r0; bH[2 * ntp + 1][0] = r1;
            bH[2 * ntp][1] = r2; bH[2 * ntp + 1][1] = r3;
        }
#pragma unroll
        for (int mt = 0; mt < 4; mt++)
#pragma unroll
            for (int nt = 0; nt < 4; nt++)
                MMAH(acc[mt][nt], aH[mt], bH[nt]);
    }

    float mcol[4][2];
#pragma unroll
    for (int nt = 0; nt < 4; nt++) {
        int col = blockCol + warpN + nt * 8 + (lane & 3) * 2;
        mcol[nt][0] = mask[(size_t)b * SS + col]     * (-1e9f);
        mcol[nt][1] = mask[(size_t)b * SS + col + 1] * (-1e9f);
    }

    __syncthreads();
    __half* sE = (__half*)sm;

#pragma unroll
    for (int mt = 0; mt < 4; mt++) {
#pragma unroll
        for (int half = 0; half < 2; half++) {
            int lrow = warpM + mt * 16 + (lane >> 2) + half * 8;
            float rs = 0.0f;
#pragma unroll
            for (int nt = 0; nt < 4; nt++) {
                int lcol = warpN + nt * 8 + (lane & 3) * 2;
                float e0 = __expf(acc[mt][nt][half * 2 + 0] * 0.125f + mcol[nt][0]);
                float e1 = __expf(acc[mt][nt][half * 2 + 1] * 0.125f + mcol[nt][1]);
                rs += e0 + e1;
                *(__half2*)&sE[lrow * EPAD + lcol] = __floats2half2_rn(e0, e1);
            }
            rs += __shfl_xor_sync(0xffffffffu, rs, 1);
            rs += __shfl_xor_sync(0xffffffffu, rs, 2);
            if ((lane & 3) == 0)
                rowsum[((size_t)z * SS + blockRow + lrow) * RS_W + blockIdx.x * 4 + (wid & 3)] = rs;
        }
    }
    __syncthreads();

    __half* Ez = eout + (size_t)z * SS * SS;
#pragma unroll
    for (int i = 0; i < 8; i++) {
        int id = tid + i * 256;
        int row = id >> 4, q = id & 15;
        *(uint4*)&Ez[(size_t)(blockRow + row) * SS + blockCol + q * 8] =
            *(const uint4*)&sE[row * EPAD + q * 8];
    }
}

// ==================== AV: 256-row blocks, single wave ========================
#define AVPAD 72
#define AV_OFF_A   0
#define AV_OFF_BH  36864      // 256*72*2
#define AV_OFF_BL  46080      // + 64*72*2
#define AV_OFF_INV 55296      // + 64*72*2
#define AV_SMEM    56320      // + 256*4

__global__ __launch_bounds__(256, 2)
void av_mma_kernel(const __half* __restrict__ e,
                   const __half* __restrict__ vth, const __half* __restrict__ vtl,
                   const float* __restrict__ rowsum, float* __restrict__ attn,
                   __half* __restrict__ o_hi, __half* __restrict__ o_lo)
{
    extern __shared__ char avsm[];
    __half* sA  = (__half*)(avsm + AV_OFF_A);
    __half* sBh = (__half*)(avsm + AV_OFF_BH);
    __half* sBl = (__half*)(avsm + AV_OFF_BL);
    float* invs = (float*)(avsm + AV_OFF_INV);

    const uint32_t aA  = smem_u32(sA);
    const uint32_t aBh = smem_u32(sBh), aBl = smem_u32(sBl);

    const int z = blockIdx.y;
    const int b = z / NUM_HEADS, h = z % NUM_HEADS;
    const int rowbase = blockIdx.x * 256;
    const int tid = threadIdx.x, lane = tid & 31, wid = tid >> 5;
    const int warpM = wid * 32;                  // 8 warps x 32 rows
    const int lmRow = lane & 15, lmK = (lane >> 4) * 8;

    {
        const float* rp = &rowsum[((size_t)z * SS + rowbase + tid) * RS_W];
        float s = 0.0f;
#pragma unroll
        for (int j = 0; j < RS_W; j++) s += rp[j];
        invs[tid] = 1.0f / s;
    }
    __syncthreads();

    const __half* Ez = e + (size_t)z * SS * SS;
    float* Az = attn + (size_t)z * SS * SS;

    float acc[2][8][4];
#pragma unroll
    for (int mt = 0; mt < 2; mt++)
#pragma unroll
        for (int nt = 0; nt < 8; nt++)
#pragma unroll
            for (int r = 0; r < 4; r++) acc[mt][nt][r] = 0.0f;

    for (int k0 = 0; k0 < SS; k0 += 64) {
        // e: 256 rows x 64 halves = 2048 uint4; also emit normalized fp32 attn
#pragma unroll
        for (int i = 0; i < 8; i++) {
            int id = tid + i * 256;
            int row = id >> 3, q = id & 7;
            uint4 ev = *(const uint4*)&Ez[(size_t)(rowbase + row) * SS + k0 + q * 8];
            *(uint4*)&sA[row * AVPAD + q * 8] = ev;
            const float inv = invs[row];
            const __half2* hp = (const __half2*)&ev;
            float2 f0 = __half22float2(hp[0]);
            float2 f1 = __half22float2(hp[1]);
            float2 f2 = __half22float2(hp[2]);
            float2 f3 = __half22float2(hp[3]);
            float4 v0 = {f0.x * inv, f0.y * inv, f1.x * inv, f1.y * inv};
            float4 v1 = {f2.x * inv, f2.y * inv, f3.x * inv, f3.y * inv};
            size_t ao = (size_t)(rowbase + row) * SS + k0 + q * 8;
            *(float4*)&Az[ao]     = v0;
            *(float4*)&Az[ao + 4] = v1;
        }
        // V: 64 rows x 64 halves x2 arrays
#pragma unroll
        for (int i = 0; i < 2; i++) {
            int id = tid + i * 256;
            int row = id >> 3, q = id & 7;
            size_t g = ((size_t)z * DEPTH + row) * SS + k0 + q * 8;
            *(uint4*)&sBh[row * AVPAD + q * 8] = *(const uint4*)&vth[g];
            *(uint4*)&sBl[row * AVPAD + q * 8] = *(const uint4*)&vtl[g];
        }
        __syncthreads();

        const uint32_t aBase = (uint32_t)(((warpM + lmRow) * AVPAD + lmK) * 2);
        const uint32_t bBase = (uint32_t)((lmRow * AVPAD + lmK) * 2);

#pragma unroll
        for (int ks = 0; ks < 4; ks++) {
            const uint32_t kOff = (uint32_t)(ks * 16 * 2);
            uint32_t aF[2][4], bH[8][2], bL[8][2];
#pragma unroll
            for (int mt = 0; mt < 2; mt++) {
                uint32_t ad = aBase + kOff + (uint32_t)(mt * 16 * AVPAD * 2);
                LDSM4(aF[mt][0], aF[mt][1], aF[mt][2], aF[mt][3], aA + ad);
            }
#pragma unroll
            for (int ntp = 0; ntp < 4; ntp++) {
                uint32_t bd = bBase + kOff + (uint32_t)(ntp * 16 * AVPAD * 2);
                uint32_t r0, r1, r2, r3;
                LDSM4(r0, r1, r2, r3, aBh + bd);
                bH[2 * ntp][0] = r0; bH[2 * ntp + 1][0] = r1;
                bH[2 * ntp][1] = r2; bH[2 * ntp + 1][1] = r3;
                LDSM4(r0, r1, r2, r3, aBl + bd);
                bL[2 * ntp][0] = r0; bL[2 * ntp + 1][0] = r1;
                bL[2 * ntp][1] = r2; bL[2 * ntp + 1][1] = r3;
            }
#pragma unroll
            for (int mt = 0; mt < 2; mt++)
#pragma unroll
                for (int nt = 0; nt < 8; nt++) {
                    MMAH(acc[mt][nt], aF[mt], bH[nt]);
                    MMAH(acc[mt][nt], aF[mt], bL[nt]);
                }
        }
        __syncthreads();
    }

#pragma unroll
    for (int mt = 0; mt < 2; mt++) {
#pragma unroll
        for (int nt = 0; nt < 8; nt++) {
            int lrow0 = warpM + mt * 16 + (lane >> 2);
            int col   = nt * 8 + (lane & 3) * 2;
#pragma unroll
            for (int half = 0; half < 2; half++) {
                int lr = lrow0 + half * 8;
                float inv = invs[lr];
                int r = rowbase + lr;
                float vx = acc[mt][nt][half * 2 + 0] * inv;
                float vy = acc[mt][nt][half * 2 + 1] * inv;
                size_t o = ((size_t)b * SS + r) * D_MODEL + h * DEPTH + col;
                __half hx = __float2half(vx);
                __half hy = __float2half(vy);
                __half2 hp = {hx, hy};
                *(__half2*)&o_hi[o] = hp;
                __half2 lp = {__float2half(vx - __half2float(hx)),
                              __float2half(vy - __half2float(hy))};
                *(__half2*)&o_lo[o] = lp;
            }
        }
    }
}

// =====================================================================
extern "C" void kernel_launch(void* const* d_in, const int* in_sizes, int n_in,
                              void* d_out, int out_size)
{
    const float* Q    = (const float*)d_in[0];
    const float* K    = (const float*)d_in[1];
    const float* V    = (const float*)d_in[2];
    const float* mask = (const float*)d_in[3];
    const float* Wq   = (const float*)d_in[4];
    const float* bq   = (const float*)d_in[5];
    const float* Wk   = (const float*)d_in[6];
    const float* bk   = (const float*)d_in[7];
    const float* Wv   = (const float*)d_in[8];
    const float* bv   = (const float*)d_in[9];
    const float* Wo   = (const float*)d_in[10];
    const float* bo   = (const float*)d_in[11];

    float* out = (float*)d_out;

    float *rowsum, *attn;
    __half *inb, *w, *qf, *kf, *vth, *vtl, *ohi, *olo, *ebuf;
    cudaGetSymbolAddress((void**)&rowsum, g_rowsum);
    cudaGetSymbolAddress((void**)&ebuf, g_e);
    cudaGetSymbolAddress((void**)&inb, g_in);
    cudaGetSymbolAddress((void**)&w, g_w);
    cudaGetSymbolAddress((void**)&qf, g_q_f);
    cudaGetSymbolAddress((void**)&kf, g_k_f);
    cudaGetSymbolAddress((void**)&vth, g_vt_hi);
    cudaGetSymbolAddress((void**)&vtl, g_vt_lo);
    cudaGetSymbolAddress((void**)&ohi, g_o_hi);
    cudaGetSymbolAddress((void**)&olo, g_o_lo);

    if ((size_t)out_size >= OUT_ELEMS + ATTN_ELEMS) {
        attn = out + OUT_ELEMS;
    } else {
        cudaGetSymbolAddress((void**)&attn, g_attn_fallback);
    }

    static bool attr_done = false;
    if (!attr_done) {
        cudaFuncSetAttribute(proj_qkv_kernel, cudaFuncAttributeMaxDynamicSharedMemorySize, 2 * P2STAGE);
        cudaFuncSetAttribute(proj_out_kernel, cudaFuncAttributeMaxDynamicSharedMemorySize, 2 * PSTAGE);
        cudaFuncSetAttribute(scores_mma_kernel, cudaFuncAttributeMaxDynamicSharedMemorySize, 2 * 128 * QPAD * 2);
        cudaFuncSetAttribute(av_mma_kernel, cudaFuncAttributeMaxDynamicSharedMemorySize, AV_SMEM);
        attr_done = true;
    }

    // 1. splits
    dim3 wtBlock(32, 8);
    split_w4_kernel<<<dim3(32, 32, 4), wtBlock>>>(Wq, Wk, Wv, Wo, w);
    split_in3_kernel<<<dim3(NELEM / 256, 3), 256>>>(Q, K, V, inb);

    // 2. QKV projections (fp16 x fp16, 1 MMA, K-chunk 64)
    proj_qkv_kernel<<<dim3(8, 32, 3), 256, 2 * P2STAGE>>>(
        inb, w, bq, bk, bv, qf, kf, vth, vtl);

    // 3. scores (single fp16 q,k) -> e fp16 + rowsum partials
    scores_mma_kernel<<<dim3(16, 16, NZ), 256, 2 * 128 * QPAD * 2>>>(
        qf, kf, mask, ebuf, rowsum);

    // 4. AV (256-row blocks, single wave) + fused attn normalize
    av_mma_kernel<<<dim3(8, NZ), 256, AV_SMEM>>>(ebuf, vth, vtl, rowsum, attn, ohi, olo);

    // 5. output projection
    proj_out_kernel<<<dim3(8, 32), 256, 2 * PSTAGE>>>(
        ohi, olo, w + (size_t)3 * WELEM, bo, out);
}

// round 12
// speedup vs baseline: 4.1592x; 1.0086x over previous
#include <cuda_runtime.h>
#include <cuda_bf16.h>
#include <cuda_fp16.h>
#include <cstdint>
#include <math.h>

#define D_MODEL   1024
#define NUM_HEADS 16
#define DEPTH     64
#define BB        2
#define SS        2048
#define MROWS     (BB * SS)                              // 4096
#define ATTN_ELEMS ((size_t)BB * NUM_HEADS * SS * SS)    // 134,217,728
#define OUT_ELEMS  ((size_t)MROWS * D_MODEL)             // 4,194,304
#define NZ        (BB * NUM_HEADS)                       // 32
#define RS_W      64
#define NELEM     (MROWS * D_MODEL)                      // 4,194,304
#define WELEM     (D_MODEL * D_MODEL)                    // 1,048,576

// ---------------- scratch (static device globals; no allocations) ------------
__device__ float g_rowsum[(size_t)NZ * SS * RS_W];
__device__ __half g_e[ATTN_ELEMS];                       // unnormalized exp
__device__ __half g_in[3 * (size_t)NELEM];               // QKV inputs fp16
__device__ __half g_w[4 * (size_t)WELEM];                // Wq,Wk,Wv,Wo [n][k] fp16
__device__ __half g_q_f[(size_t)NZ * SS * DEPTH];        // [z,s,d] fp16
__device__ __half g_k_f[(size_t)NZ * SS * DEPTH];        // [z,s,d] fp16
__device__ __half g_vt[(size_t)NZ * SS * DEPTH];         // [z,d,s] fp16 single
__device__ __half g_o_hi[(size_t)NELEM];                 // O fp16 hi/lo
__device__ __half g_o_lo[(size_t)NELEM];
__device__ float g_attn_fallback[ATTN_ELEMS];

// ============================ PTX helpers ====================================
#define MMAH(d, a, b)                                                         \
    asm volatile("mma.sync.aligned.m16n8k16.row.col.f32.f16.f16.f32 "         \
        "{%0,%1,%2,%3}, {%4,%5,%6,%7}, {%8,%9}, {%0,%1,%2,%3};"               \
        : "+f"((d)[0]), "+f"((d)[1]), "+f"((d)[2]), "+f"((d)[3])              \
        : "r"((a)[0]), "r"((a)[1]), "r"((a)[2]), "r"((a)[3]),                 \
          "r"((b)[0]), "r"((b)[1]))

#define LDSM4(R0, R1, R2, R3, ADDR)                                           \
    asm volatile("ldmatrix.sync.aligned.m8n8.x4.shared.b16 {%0,%1,%2,%3}, [%4];" \
        : "=r"(R0), "=r"(R1), "=r"(R2), "=r"(R3) : "r"(ADDR))

#define CP16(SADDR, GPTR)                                                     \
    asm volatile("cp.async.cg.shared.global [%0], [%1], 16;"                  \
        :: "r"(SADDR), "l"(GPTR))
#define CP_COMMIT() asm volatile("cp.async.commit_group;" ::: "memory")
#define CP_WAIT1()  asm volatile("cp.async.wait_group 1;" ::: "memory")
#define CP_WAIT0()  asm volatile("cp.async.wait_group 0;" ::: "memory")

__device__ __forceinline__ uint32_t smem_u32(const void* p) {
    uint32_t a;
    asm("{ .reg .u64 t; cvta.to.shared.u64 t, %1; cvt.u32.u64 %0, t; }" : "=r"(a) : "l"(p));
    return a;
}

// ============================ split kernels ==================================
__global__ __launch_bounds__(256)
void split_in3_kernel(const float* __restrict__ Q, const float* __restrict__ K,
                      const float* __restrict__ V, __half* __restrict__ dst)
{
    int z = blockIdx.y;
    const float* A = (z == 0) ? Q : (z == 1) ? K : V;
    size_t i = (size_t)blockIdx.x * 256 + threadIdx.x;
    dst[(size_t)z * NELEM + i] = __float2half(A[i]);
}

__global__ __launch_bounds__(256)
void split_w4_kernel(const float* __restrict__ W0, const float* __restrict__ W1,
                     const float* __restrict__ W2, const float* __restrict__ W3,
                     __half* __restrict__ wt)
{
    __shared__ float t[32][33];
    int z = blockIdx.z;
    const float* W = (z == 0) ? W0 : (z == 1) ? W1 : (z == 2) ? W2 : W3;
    int tx = threadIdx.x, ty = threadIdx.y;
    int n0 = blockIdx.x * 32, k0 = blockIdx.y * 32;
#pragma unroll
    for (int j = 0; j < 4; j++)
        t[ty + j * 8][tx] = W[(size_t)(k0 + ty + j * 8) * D_MODEL + n0 + tx];
    __syncthreads();
#pragma unroll
    for (int j = 0; j < 4; j++) {
        size_t o = (size_t)z * WELEM + (size_t)(n0 + ty + j * 8) * D_MODEL + k0 + tx;
        wt[o] = __float2half(t[tx][ty + j * 8]);
    }
}

// ==================== QKV projection: fp16 x fp16, K-chunk 64 ================
#define P2PAD 72
#define P2STAGE 36864     // 2 arrays * 128*72*2
#define P2_OFF_A 0
#define P2_OFF_B 18432

__global__ __launch_bounds__(256, 2)
void proj_qkv_kernel(const __half* __restrict__ in, const __half* __restrict__ w,
                     const float* __restrict__ bq, const float* __restrict__ bk,
                     const float* __restrict__ bv,
                     __half* __restrict__ qf, __half* __restrict__ kf,
                     __half* __restrict__ vt)
{
    extern __shared__ char smem[];
    const uint32_t sb0 = smem_u32(smem);

    const int zz = blockIdx.z;
    const __half* a  = in + (size_t)zz * NELEM;
    const __half* wh = w + (size_t)zz * WELEM;
    const float* bias = (zz == 0) ? bq : (zz == 1) ? bk : bv;

    const int tid  = threadIdx.x;
    const int lane = tid & 31;
    const int wid  = tid >> 5;
    const int warpM = (wid >> 2) * 64;
    const int warpN = (wid & 3) * 32;
    const int blockRow = blockIdx.y * 128;
    const int blockCol = blockIdx.x * 128;

    const int lmRow = lane & 15;
    const int lmK   = (lane >> 4) * 8;

    float acc[4][4][4];
#pragma unroll
    for (int mt = 0; mt < 4; mt++)
#pragma unroll
        for (int nt = 0; nt < 4; nt++)
#pragma unroll
            for (int r = 0; r < 4; r++) acc[mt][nt][r] = 0.0f;

    auto load_stage = [&](int stage, int chunk) {
        const int k0 = chunk * 64;
        const uint32_t sb = sb0 + stage * P2STAGE;
#pragma unroll
        for (int j = 0; j < 4; j++) {
            int id = tid + j * 256;
            int row = id >> 3, q = id & 7;
            uint32_t so = (uint32_t)(row * 144 + q * 16);
            CP16(sb + P2_OFF_A + so, &a[(size_t)(blockRow + row) * D_MODEL + k0 + q * 8]);
            CP16(sb + P2_OFF_B + so, &wh[(size_t)(blockCol + row) * D_MODEL + k0 + q * 8]);
        }
        CP_COMMIT();
    };

    load_stage(0, 0);

    for (int chunk = 0; chunk < 16; chunk++) {
        if (chunk < 15) { load_stage((chunk + 1) & 1, chunk + 1); CP_WAIT1(); }
        else           { CP_WAIT0(); }
        __syncthreads();

        const uint32_t sb = sb0 + (chunk & 1) * P2STAGE;
        const uint32_t aBase = sb + P2_OFF_A + (uint32_t)(((warpM + lmRow) * P2PAD + lmK) * 2);
        const uint32_t bBase = sb + P2_OFF_B + (uint32_t)(((warpN + lmRow) * P2PAD + lmK) * 2);

#pragma unroll
        for (int ks = 0; ks < 4; ks++) {
            const uint32_t kOff = (uint32_t)(ks * 16 * 2);
            uint32_t aF[4][4], bH[4][2];
#pragma unroll
            for (int mt = 0; mt < 4; mt++) {
                uint32_t ad = aBase + kOff + (uint32_t)(mt * 16 * P2PAD * 2);
                LDSM4(aF[mt][0], aF[mt][1], aF[mt][2], aF[mt][3], ad);
            }
#pragma unroll
            for (int ntp = 0; ntp < 2; ntp++) {
                uint32_t bd = bBase + kOff + (uint32_t)(ntp * 16 * P2PAD * 2);
                uint32_t r0, r1, r2, r3;
                LDSM4(r0, r1, r2, r3, bd);
                bH[2 * ntp][0] = r0; bH[2 * ntp + 1][0] = r1;
                bH[2 * ntp][1] = r2; bH[2 * ntp + 1][1] = r3;
            }
#pragma unroll
            for (int mt = 0; mt < 4; mt++)
#pragma unroll
                for (int nt = 0; nt < 4; nt++)
                    MMAH(acc[mt][nt], aF[mt], bH[nt]);
        }
        __syncthreads();
    }

#pragma unroll
    for (int mt = 0; mt < 4; mt++) {
#pragma unroll
        for (int nt = 0; nt < 4; nt++) {
            int row0 = blockRow + warpM + mt * 16 + (lane >> 2);
            int col  = blockCol + warpN + nt * 8 + (lane & 3) * 2;
            float b0 = bias[col], b1 = bias[col + 1];
#pragma unroll
            for (int half = 0; half < 2; half++) {
                int r = row0 + half * 8;
                float vx = acc[mt][nt][half * 2 + 0] + b0;
                float vy = acc[mt][nt][half * 2 + 1] + b1;
                int z = (r >> 11) * NUM_HEADS + (col >> 6);
                int s = r & (SS - 1);
                int d = col & (DEPTH - 1);
                if (zz == 0) {
                    size_t o = ((size_t)z * SS + s) * DEPTH + d;
                    __half2 hp = {__float2half(vx), __float2half(vy)};
                    *(__half2*)&qf[o] = hp;
                } else if (zz == 1) {
                    size_t o = ((size_t)z * SS + s) * DEPTH + d;
                    __half2 hp = {__float2half(vx), __float2half(vy)};
                    *(__half2*)&kf[o] = hp;
                } else {
                    size_t o = ((size_t)z * DEPTH + d) * SS + s;
                    vt[o]      = __float2half(vx);
                    vt[o + SS] = __float2half(vy);
                }
            }
        }
    }
}

// ==================== output projection: O(hi/lo) x W fp16, 2 MMA ============
#define SPAD 40
#define PSTAGE 30720
#define OFF_AH 0
#define OFF_AL 10240
#define OFF_BH 20480

__global__ __launch_bounds__(256, 2)
void proj_out_kernel(const __half* __restrict__ a_hi, const __half* __restrict__ a_lo,
                     const __half* __restrict__ w,
                     const float* __restrict__ bias, float* __restrict__ C)
{
    extern __shared__ char smem[];
    const uint32_t sb0 = smem_u32(smem);

    const int tid  = threadIdx.x;
    const int lane = tid & 31;
    const int wid  = tid >> 5;
    const int warpM = (wid >> 2) * 64;
    const int warpN = (wid & 3) * 32;
    const int blockRow = blockIdx.y * 128;
    const int blockCol = blockIdx.x * 128;

    const int ldRow0 = tid >> 2;
    const int ldQ    = (tid & 3) * 16;
    const int lmRow = lane & 15;
    const int lmK   = (lane >> 4) * 8;

    float acc[4][4][4];
#pragma unroll
    for (int mt = 0; mt < 4; mt++)
#pragma unroll
        for (int nt = 0; nt < 4; nt++)
#pragma unroll
            for (int r = 0; r < 4; r++) acc[mt][nt][r] = 0.0f;

    auto load_stage = [&](int stage, int chunk) {
        const int k0 = chunk * 32;
        const uint32_t sb = sb0 + stage * PSTAGE;
#pragma unroll
        for (int j = 0; j < 2; j++) {
            int row = ldRow0 + j * 64;
            uint32_t so = (uint32_t)(row * 80) + ldQ;
            CP16(sb + OFF_AH + so, &a_hi[(size_t)(blockRow + row) * D_MODEL + k0] + ldQ / 2);
            CP16(sb + OFF_AL + so, &a_lo[(size_t)(blockRow + row) * D_MODEL + k0] + ldQ / 2);
            CP16(sb + OFF_BH + so, &w[(size_t)(blockCol + row) * D_MODEL + k0] + ldQ / 2);
        }
        CP_COMMIT();
    };

    load_stage(0, 0);

    for (int chunk = 0; chunk < 32; chunk++) {
        if (chunk < 31) { load_stage((chunk + 1) & 1, chunk + 1); CP_WAIT1(); }
        else           { CP_WAIT0(); }
        __syncthreads();

        const uint32_t sb = sb0 + (chunk & 1) * PSTAGE;
        const uint32_t aAddrBase = sb + (uint32_t)(((warpM + lmRow) * SPAD + lmK) * 2);
        const uint32_t bAddrBase = sb + (uint32_t)(((warpN + lmRow) * SPAD + lmK) * 2);

#pragma unroll
        for (int ks = 0; ks < 2; ks++) {
            const uint32_t kOff = (uint32_t)(ks * 16 * 2);
            uint32_t aH[4][4], aL[4][4], bH[4][2];
#pragma unroll
            for (int mt = 0; mt < 4; mt++) {
                uint32_t ad = aAddrBase + kOff + (uint32_t)(mt * 16 * SPAD * 2);
                LDSM4(aH[mt][0], aH[mt][1], aH[mt][2], aH[mt][3], ad + OFF_AH);
                LDSM4(aL[mt][0], aL[mt][1], aL[mt][2], aL[mt][3], ad + OFF_AL);
            }
#pragma unroll
            for (int ntp = 0; ntp < 2; ntp++) {
                uint32_t bd = bAddrBase + kOff + (uint32_t)(ntp * 16 * SPAD * 2);
                uint32_t r0, r1, r2, r3;
                LDSM4(r0, r1, r2, r3, bd + OFF_BH);
                bH[2 * ntp][0] = r0; bH[2 * ntp + 1][0] = r1;
                bH[2 * ntp][1] = r2; bH[2 * ntp + 1][1] = r3;
            }
#pragma unroll
            for (int mt = 0; mt < 4; mt++)
#pragma unroll
                for (int nt = 0; nt < 4; nt++) {
                    MMAH(acc[mt][nt], aH[mt], bH[nt]);
                    MMAH(acc[mt][nt], aL[mt], bH[nt]);
                }
        }
        __syncthreads();
    }

#pragma unroll
    for (int mt = 0; mt < 4; mt++) {
#pragma unroll
        for (int nt = 0; nt < 4; nt++) {
            int row0 = blockRow + warpM + mt * 16 + (lane >> 2);
            int col  = blockCol + warpN + nt * 8 + (lane & 3) * 2;
            float b0 = bias[col], b1 = bias[col + 1];
#pragma unroll
            for (int half = 0; half < 2; half++) {
                int r = row0 + half * 8;
                float2 v = {acc[mt][nt][half * 2 + 0] + b0, acc[mt][nt][half * 2 + 1] + b1};
                *(float2*)&C[(size_t)r * D_MODEL + col] = v;
            }
        }
    }
}

// ==================== scores: single-fp16 mma -> e fp16 (staged) =============
#define QPAD 72
#define EPAD 136

__global__ __launch_bounds__(256, 2)
void scores_mma_kernel(const __half* __restrict__ qf, const __half* __restrict__ kf,
                       const float* __restrict__ mask, __half* __restrict__ eout,
                       float* __restrict__ rowsum)
{
    extern __shared__ char sm[];
    const uint32_t sq = smem_u32(sm);
    __half* sQh = (__half*)sm;
    __half* sKh = sQh + 128 * QPAD;
    const uint32_t OQH = 0, OKH = 128 * QPAD * 2;

    const int z = blockIdx.z;
    const int b = z / NUM_HEADS;
    const int tid = threadIdx.x, lane = tid & 31, wid = tid >> 5;
    const int warpM = (wid >> 2) * 64, warpN = (wid & 3) * 32;
    const int blockRow = blockIdx.y * 128, blockCol = blockIdx.x * 128;
    const int lmRow = lane & 15, lmK = (lane >> 4) * 8;

#pragma unroll
    for (int i = 0; i < 4; i++) {
        int id = tid + i * 256;
        int row = id >> 3, q = id & 7;
        size_t gq = ((size_t)z * SS + blockRow + row) * DEPTH + q * 8;
        size_t gk = ((size_t)z * SS + blockCol + row) * DEPTH + q * 8;
        int so = row * QPAD + q * 8;
        *(uint4*)&sQh[so] = *(const uint4*)&qf[gq];
        *(uint4*)&sKh[so] = *(const uint4*)&kf[gk];
    }
    __syncthreads();

    float acc[4][4][4];
#pragma unroll
    for (int mt = 0; mt < 4; mt++)
#pragma unroll
        for (int nt = 0; nt < 4; nt++)
#pragma unroll
            for (int r = 0; r < 4; r++) acc[mt][nt][r] = 0.0f;

    const uint32_t aAddrBase = sq + (uint32_t)(((warpM + lmRow) * QPAD + lmK) * 2);
    const uint32_t bAddrBase = sq + (uint32_t)(((warpN + lmRow) * QPAD + lmK) * 2);

#pragma unroll
    for (int ks = 0; ks < 4; ks++) {
        const uint32_t kOff = (uint32_t)(ks * 16 * 2);
        uint32_t aH[4][4], bH[4][2];
#pragma unroll
        for (int mt = 0; mt < 4; mt++) {
            uint32_t ad = aAddrBase + kOff + (uint32_t)(mt * 16 * QPAD * 2);
            LDSM4(aH[mt][0], aH[mt][1], aH[mt][2], aH[mt][3], ad + OQH);
        }
#pragma unroll
        for (int ntp = 0; ntp < 2; ntp++) {
            uint32_t bd = bAddrBase + kOff + (uint32_t)(ntp * 16 * QPAD * 2);
            uint32_t r0, r1, r2, r3;
            LDSM4(r0, r1, r2, r3, bd + OKH);
            bH[2 * ntp][0] = r0; bH[2 * ntp + 1][0] = r1;
            bH[2 * ntp][1] = r2; bH[2 * ntp + 1][1] = r3;
        }
#pragma unroll
        for (int mt = 0; mt < 4; mt++)
#pragma unroll
            for (int nt = 0; nt < 4; nt++)
                MMAH(acc[mt][nt], aH[mt], bH[nt]);
    }

    float mcol[4][2];
#pragma unroll
    for (int nt = 0; nt < 4; nt++) {
        int col = blockCol + warpN + nt * 8 + (lane & 3) * 2;
        mcol[nt][0] = mask[(size_t)b * SS + col]     * (-1e9f);
        mcol[nt][1] = mask[(size_t)b * SS + col + 1] * (-1e9f);
    }

    __syncthreads();
    __half* sE = (__half*)sm;

#pragma unroll
    for (int mt = 0; mt < 4; mt++) {
#pragma unroll
        for (int half = 0; half < 2; half++) {
            int lrow = warpM + mt * 16 + (lane >> 2) + half * 8;
            float rs = 0.0f;
#pragma unroll
            for (int nt = 0; nt < 4; nt++) {
                int lcol = warpN + nt * 8 + (lane & 3) * 2;
                float e0 = __expf(acc[mt][nt][half * 2 + 0] * 0.125f + mcol[nt][0]);
                float e1 = __expf(acc[mt][nt][half * 2 + 1] * 0.125f + mcol[nt][1]);
                rs += e0 + e1;
                *(__half2*)&sE[lrow * EPAD + lcol] = __floats2half2_rn(e0, e1);
            }
            rs += __shfl_xor_sync(0xffffffffu, rs, 1);
            rs += __shfl_xor_sync(0xffffffffu, rs, 2);
            if ((lane & 3) == 0)
                rowsum[((size_t)z * SS + blockRow + lrow) * RS_W + blockIdx.x * 4 + (wid & 3)] = rs;
        }
    }
    __syncthreads();

    __half* Ez = eout + (size_t)z * SS * SS;
#pragma unroll
    for (int i = 0; i < 8; i++) {
        int id = tid + i * 256;
        int row = id >> 4, q = id & 15;
        *(uint4*)&Ez[(size_t)(blockRow + row) * SS + blockCol + q * 8] =
            *(const uint4*)&sE[row * EPAD + q * 8];
    }
}

// ==================== AV: 256-row blocks, single-fp16 V ======================
#define AVPAD 72
#define AV_OFF_A   0
#define AV_OFF_B   36864      // 256*72*2
#define AV_OFF_INV 46080      // + 64*72*2
#define AV_SMEM    47104      // + 256*4

__global__ __launch_bounds__(256, 2)
void av_mma_kernel(const __half* __restrict__ e, const __half* __restrict__ vt,
                   const float* __restrict__ rowsum, float* __restrict__ attn,
                   __half* __restrict__ o_hi, __half* __restrict__ o_lo)
{
    extern __shared__ char avsm[];
    __half* sA  = (__half*)(avsm + AV_OFF_A);
    __half* sB  = (__half*)(avsm + AV_OFF_B);
    float* invs = (float*)(avsm + AV_OFF_INV);

    const uint32_t aA = smem_u32(sA);
    const uint32_t aB = smem_u32(sB);

    const int z = blockIdx.y;
    const int b = z / NUM_HEADS, h = z % NUM_HEADS;
    const int rowbase = blockIdx.x * 256;
    const int tid = threadIdx.x, lane = tid & 31, wid = tid >> 5;
    const int warpM = wid * 32;
    const int lmRow = lane & 15, lmK = (lane >> 4) * 8;

    {
        const float* rp = &rowsum[((size_t)z * SS + rowbase + tid) * RS_W];
        float s = 0.0f;
#pragma unroll
        for (int j = 0; j < RS_W; j++) s += rp[j];
        invs[tid] = 1.0f / s;
    }
    __syncthreads();

    const __half* Ez = e + (size_t)z * SS * SS;
    float* Az = attn + (size_t)z * SS * SS;

    float acc[2][8][4];
#pragma unroll
    for (int mt = 0; mt < 2; mt++)
#pragma unroll
        for (int nt = 0; nt < 8; nt++)
#pragma unroll
            for (int r = 0; r < 4; r++) acc[mt][nt][r] = 0.0f;

    for (int k0 = 0; k0 < SS; k0 += 64) {
        // e: 256 rows x 64 halves; also emit normalized fp32 attn
#pragma unroll
        for (int i = 0; i < 8; i++) {
            int id = tid + i * 256;
            int row = id >> 3, q = id & 7;
            uint4 ev = *(const uint4*)&Ez[(size_t)(rowbase + row) * SS + k0 + q * 8];
            *(uint4*)&sA[row * AVPAD + q * 8] = ev;
            const float inv = invs[row];
            const __half2* hp = (const __half2*)&ev;
            float2 f0 = __half22float2(hp[0]);
            float2 f1 = __half22float2(hp[1]);
            float2 f2 = __half22float2(hp[2]);
            float2 f3 = __half22float2(hp[3]);
            float4 v0 = {f0.x * inv, f0.y * inv, f1.x * inv, f1.y * inv};
            float4 v1 = {f2.x * inv, f2.y * inv, f3.x * inv, f3.y * inv};
            size_t ao = (size_t)(rowbase + row) * SS + k0 + q * 8;
            *(float4*)&Az[ao]     = v0;
            *(float4*)&Az[ao + 4] = v1;
        }
        // V: 64 rows x 64 halves
        {
            int row = tid >> 2, q = tid & 3;
            size_t g = ((size_t)z * DEPTH + row) * SS + k0 + (q + ((tid & 4) ? 0 : 0)) * 8; // plain
            (void)g;
        }
#pragma unroll
        for (int i = 0; i < 2; i++) {
            int id = tid + i * 256;
            int row = id >> 3, q = id & 7;
            size_t g = ((size_t)z * DEPTH + row) * SS + k0 + q * 8;
            *(uint4*)&sB[row * AVPAD + q * 8] = *(const uint4*)&vt[g];
        }
        __syncthreads();

        const uint32_t aBase = (uint32_t)(((warpM + lmRow) * AVPAD + lmK) * 2);
        const uint32_t bBase = (uint32_t)((lmRow * AVPAD + lmK) * 2);

#pragma unroll
        for (int ks = 0; ks < 4; ks++) {
            const uint32_t kOff = (uint32_t)(ks * 16 * 2);
            uint32_t aF[2][4], bH[8][2];
#pragma unroll
            for (int mt = 0; mt < 2; mt++) {
                uint32_t ad = aBase + kOff + (uint32_t)(mt * 16 * AVPAD * 2);
                LDSM4(aF[mt][0], aF[mt][1], aF[mt][2], aF[mt][3], aA + ad);
            }
#pragma unroll
            for (int ntp = 0; ntp < 4; ntp++) {
                uint32_t bd = bBase + kOff + (uint32_t)(ntp * 16 * AVPAD * 2);
                uint32_t r0, r1, r2, r3;
                LDSM4(r0, r1, r2, r3, aB + bd);
                bH[2 * ntp][0] = r0; bH[2 * ntp + 1][0] = r1;
                bH[2 * ntp][1] = r2; bH[2 * ntp + 1][1] = r3;
            }
#pragma unroll
            for (int mt = 0; mt < 2; mt++)
#pragma unroll
                for (int nt = 0; nt < 8; nt++)
                    MMAH(acc[mt][nt], aF[mt], bH[nt]);
        }
        __syncthreads();
    }

#pragma unroll
    for (int mt = 0; mt < 2; mt++) {
#pragma unroll
        for (int nt = 0; nt < 8; nt++) {
            int lrow0 = warpM + mt * 16 + (lane >> 2);
            int col   = nt * 8 + (lane & 3) * 2;
#pragma unroll
            for (int half = 0; half < 2; half++) {
                int lr = lrow0 + half * 8;
                float inv = invs[lr];
                int r = rowbase + lr;
                float vx = acc[mt][nt][half * 2 + 0] * inv;
                float vy = acc[mt][nt][half * 2 + 1] * inv;
                size_t o = ((size_t)b * SS + r) * D_MODEL + h * DEPTH + col;
                __half hx = __float2half(vx);
                __half hy = __float2half(vy);
                __half2 hp = {hx, hy};
                *(__half2*)&o_hi[o] = hp;
                __half2 lp = {__float2half(vx - __half2float(hx)),
                              __float2half(vy - __half2float(hy))};
                *(__half2*)&o_lo[o] = lp;
            }
        }
    }
}

// =====================================================================
extern "C" void kernel_launch(void* const* d_in, const int* in_sizes, int n_in,
                              void* d_out, int out_size)
{
    const float* Q    = (const float*)d_in[0];
    const float* K    = (const float*)d_in[1];
    const float* V    = (const float*)d_in[2];
    const float* mask = (const float*)d_in[3];
    const float* Wq   = (const float*)d_in[4];
    const float* bq   = (const float*)d_in[5];
    const float* Wk   = (const float*)d_in[6];
    const float* bk   = (const float*)d_in[7];
    const float* Wv   = (const float*)d_in[8];
    const float* bv   = (const float*)d_in[9];
    const float* Wo   = (const float*)d_in[10];
    const float* bo   = (const float*)d_in[11];

    float* out = (float*)d_out;

    float *rowsum, *attn;
    __half *inb, *w, *qf, *kf, *vt, *ohi, *olo, *ebuf;
    cudaGetSymbolAddress((void**)&rowsum, g_rowsum);
    cudaGetSymbolAddress((void**)&ebuf, g_e);
    cudaGetSymbolAddress((void**)&inb, g_in);
    cudaGetSymbolAddress((void**)&w, g_w);
    cudaGetSymbolAddress((void**)&qf, g_q_f);
    cudaGetSymbolAddress((void**)&kf, g_k_f);
    cudaGetSymbolAddress((void**)&vt, g_vt);
    cudaGetSymbolAddress((void**)&ohi, g_o_hi);
    cudaGetSymbolAddress((void**)&olo, g_o_lo);

    if ((size_t)out_size >= OUT_ELEMS + ATTN_ELEMS) {
        attn = out + OUT_ELEMS;
    } else {
        cudaGetSymbolAddress((void**)&attn, g_attn_fallback);
    }

    static bool attr_done = false;
    if (!attr_done) {
        cudaFuncSetAttribute(proj_qkv_kernel, cudaFuncAttributeMaxDynamicSharedMemorySize, 2 * P2STAGE);
        cudaFuncSetAttribute(proj_out_kernel, cudaFuncAttributeMaxDynamicSharedMemorySize, 2 * PSTAGE);
        cudaFuncSetAttribute(scores_mma_kernel, cudaFuncAttributeMaxDynamicSharedMemorySize, 2 * 128 * QPAD * 2);
        cudaFuncSetAttribute(av_mma_kernel, cudaFuncAttributeMaxDynamicSharedMemorySize, AV_SMEM);
        attr_done = true;
    }

    // 1. splits
    dim3 wtBlock(32, 8);
    split_w4_kernel<<<dim3(32, 32, 4), wtBlock>>>(Wq, Wk, Wv, Wo, w);
    split_in3_kernel<<<dim3(NELEM / 256, 3), 256>>>(Q, K, V, inb);

    // 2. QKV projections
    proj_qkv_kernel<<<dim3(8, 32, 3), 256, 2 * P2STAGE>>>(
        inb, w, bq, bk, bv, qf, kf, vt);

    // 3. scores -> e fp16 + rowsum partials
    scores_mma_kernel<<<dim3(16, 16, NZ), 256, 2 * 128 * QPAD * 2>>>(
        qf, kf, mask, ebuf, rowsum);

    // 4. AV (single-fp16 V) + fused attn normalize
    av_mma_kernel<<<dim3(8, NZ), 256, AV_SMEM>>>(ebuf, vt, rowsum, attn, ohi, olo);

    // 5. output projection
    proj_out_kernel<<<dim3(8, 32), 256, 2 * PSTAGE>>>(
        ohi, olo, w + (size_t)3 * WELEM, bo, out);
}

// round 13
// speedup vs baseline: 4.2748x; 1.0278x over previous
#include <cuda_runtime.h>
#include <cuda_bf16.h>
#include <cuda_fp16.h>
#include <cstdint>
#include <math.h>

#define D_MODEL   1024
#define NUM_HEADS 16
#define DEPTH     64
#define BB        2
#define SS        2048
#define MROWS     (BB * SS)                              // 4096
#define ATTN_ELEMS ((size_t)BB * NUM_HEADS * SS * SS)    // 134,217,728
#define OUT_ELEMS  ((size_t)MROWS * D_MODEL)             // 4,194,304
#define NZ        (BB * NUM_HEADS)                       // 32
#define RS_W      64
#define NELEM     (MROWS * D_MODEL)                      // 4,194,304
#define WELEM     (D_MODEL * D_MODEL)                    // 1,048,576

// ---------------- scratch (static device globals; no allocations) ------------
__device__ float g_rowsum[(size_t)NZ * SS * RS_W];
__device__ __half g_e[ATTN_ELEMS];                       // unnormalized exp
__device__ __half g_in[3 * (size_t)NELEM];               // QKV inputs fp16
__device__ __half g_w[4 * (size_t)WELEM];                // Wq,Wk,Wv,Wo [n][k] fp16
__device__ __half g_q_f[(size_t)NZ * SS * DEPTH];        // [z,s,d] fp16
__device__ __half g_k_f[(size_t)NZ * SS * DEPTH];        // [z,s,d] fp16
__device__ __half g_vt[(size_t)NZ * SS * DEPTH];         // [z,d,s] fp16 single
__device__ __half g_o_hi[(size_t)NELEM];                 // O fp16 hi/lo
__device__ __half g_o_lo[(size_t)NELEM];
__device__ float g_attn_fallback[ATTN_ELEMS];

// ============================ PTX helpers ====================================
#define MMAH(d, a, b)                                                         \
    asm volatile("mma.sync.aligned.m16n8k16.row.col.f32.f16.f16.f32 "         \
        "{%0,%1,%2,%3}, {%4,%5,%6,%7}, {%8,%9}, {%0,%1,%2,%3};"               \
        : "+f"((d)[0]), "+f"((d)[1]), "+f"((d)[2]), "+f"((d)[3])              \
        : "r"((a)[0]), "r"((a)[1]), "r"((a)[2]), "r"((a)[3]),                 \
          "r"((b)[0]), "r"((b)[1]))

#define LDSM4(R0, R1, R2, R3, ADDR)                                           \
    asm volatile("ldmatrix.sync.aligned.m8n8.x4.shared.b16 {%0,%1,%2,%3}, [%4];" \
        : "=r"(R0), "=r"(R1), "=r"(R2), "=r"(R3) : "r"(ADDR))

#define CP16(SADDR, GPTR)                                                     \
    asm volatile("cp.async.cg.shared.global [%0], [%1], 16;"                  \
        :: "r"(SADDR), "l"(GPTR))
#define CP_COMMIT() asm volatile("cp.async.commit_group;" ::: "memory")
#define CP_WAIT1()  asm volatile("cp.async.wait_group 1;" ::: "memory")
#define CP_WAIT0()  asm volatile("cp.async.wait_group 0;" ::: "memory")

__device__ __forceinline__ uint32_t smem_u32(const void* p) {
    uint32_t a;
    asm("{ .reg .u64 t; cvta.to.shared.u64 t, %1; cvt.u32.u64 %0, t; }" : "=r"(a) : "l"(p));
    return a;
}

// ============================ split kernels ==================================
__global__ __launch_bounds__(256)
void split_in3_kernel(const float* __restrict__ Q, const float* __restrict__ K,
                      const float* __restrict__ V, __half* __restrict__ dst)
{
    int z = blockIdx.y;
    const float* A = (z == 0) ? Q : (z == 1) ? K : V;
    size_t i = (size_t)blockIdx.x * 256 + threadIdx.x;
    dst[(size_t)z * NELEM + i] = __float2half(A[i]);
}

__global__ __launch_bounds__(256)
void split_w4_kernel(const float* __restrict__ W0, const float* __restrict__ W1,
                     const float* __restrict__ W2, const float* __restrict__ W3,
                     __half* __restrict__ wt)
{
    __shared__ float t[32][33];
    int z = blockIdx.z;
    const float* W = (z == 0) ? W0 : (z == 1) ? W1 : (z == 2) ? W2 : W3;
    int tx = threadIdx.x, ty = threadIdx.y;
    int n0 = blockIdx.x * 32, k0 = blockIdx.y * 32;
#pragma unroll
    for (int j = 0; j < 4; j++)
        t[ty + j * 8][tx] = W[(size_t)(k0 + ty + j * 8) * D_MODEL + n0 + tx];
    __syncthreads();
#pragma unroll
    for (int j = 0; j < 4; j++) {
        size_t o = (size_t)z * WELEM + (size_t)(n0 + ty + j * 8) * D_MODEL + k0 + tx;
        wt[o] = __float2half(t[tx][ty + j * 8]);
    }
}

// ==================== QKV projection: fp16 x fp16, K-chunk 64 ================
#define P2PAD 72
#define P2STAGE 36864     // 2 arrays * 128*72*2
#define P2_OFF_A 0
#define P2_OFF_B 18432

__global__ __launch_bounds__(256, 2)
void proj_qkv_kernel(const __half* __restrict__ in, const __half* __restrict__ w,
                     const float* __restrict__ bq, const float* __restrict__ bk,
                     const float* __restrict__ bv,
                     __half* __restrict__ qf, __half* __restrict__ kf,
                     __half* __restrict__ vt)
{
    extern __shared__ char smem[];
    const uint32_t sb0 = smem_u32(smem);

    const int zz = blockIdx.z;
    const __half* a  = in + (size_t)zz * NELEM;
    const __half* wh = w + (size_t)zz * WELEM;
    const float* bias = (zz == 0) ? bq : (zz == 1) ? bk : bv;

    const int tid  = threadIdx.x;
    const int lane = tid & 31;
    const int wid  = tid >> 5;
    const int warpM = (wid >> 2) * 64;
    const int warpN = (wid & 3) * 32;
    const int blockRow = blockIdx.y * 128;
    const int blockCol = blockIdx.x * 128;

    const int lmRow = lane & 15;
    const int lmK   = (lane >> 4) * 8;

    float acc[4][4][4];
#pragma unroll
    for (int mt = 0; mt < 4; mt++)
#pragma unroll
        for (int nt = 0; nt < 4; nt++)
#pragma unroll
            for (int r = 0; r < 4; r++) acc[mt][nt][r] = 0.0f;

    auto load_stage = [&](int stage, int chunk) {
        const int k0 = chunk * 64;
        const uint32_t sb = sb0 + stage * P2STAGE;
#pragma unroll
        for (int j = 0; j < 4; j++) {
            int id = tid + j * 256;
            int row = id >> 3, q = id & 7;
            uint32_t so = (uint32_t)(row * 144 + q * 16);
            CP16(sb + P2_OFF_A + so, &a[(size_t)(blockRow + row) * D_MODEL + k0 + q * 8]);
            CP16(sb + P2_OFF_B + so, &wh[(size_t)(blockCol + row) * D_MODEL + k0 + q * 8]);
        }
        CP_COMMIT();
    };

    load_stage(0, 0);

    for (int chunk = 0; chunk < 16; chunk++) {
        if (chunk < 15) { load_stage((chunk + 1) & 1, chunk + 1); CP_WAIT1(); }
        else           { CP_WAIT0(); }
        __syncthreads();

        const uint32_t sb = sb0 + (chunk & 1) * P2STAGE;
        const uint32_t aBase = sb + P2_OFF_A + (uint32_t)(((warpM + lmRow) * P2PAD + lmK) * 2);
        const uint32_t bBase = sb + P2_OFF_B + (uint32_t)(((warpN + lmRow) * P2PAD + lmK) * 2);

#pragma unroll
        for (int ks = 0; ks < 4; ks++) {
            const uint32_t kOff = (uint32_t)(ks * 16 * 2);
            uint32_t aF[4][4], bH[4][2];
#pragma unroll
            for (int mt = 0; mt < 4; mt++) {
                uint32_t ad = aBase + kOff + (uint32_t)(mt * 16 * P2PAD * 2);
                LDSM4(aF[mt][0], aF[mt][1], aF[mt][2], aF[mt][3], ad);
            }
#pragma unroll
            for (int ntp = 0; ntp < 2; ntp++) {
                uint32_t bd = bBase + kOff + (uint32_t)(ntp * 16 * P2PAD * 2);
                uint32_t r0, r1, r2, r3;
                LDSM4(r0, r1, r2, r3, bd);
                bH[2 * ntp][0] = r0; bH[2 * ntp + 1][0] = r1;
                bH[2 * ntp][1] = r2; bH[2 * ntp + 1][1] = r3;
            }
#pragma unroll
            for (int mt = 0; mt < 4; mt++)
#pragma unroll
                for (int nt = 0; nt < 4; nt++)
                    MMAH(acc[mt][nt], aF[mt], bH[nt]);
        }
        __syncthreads();
    }

#pragma unroll
    for (int mt = 0; mt < 4; mt++) {
#pragma unroll
        for (int nt = 0; nt < 4; nt++) {
            int row0 = blockRow + warpM + mt * 16 + (lane >> 2);
            int col  = blockCol + warpN + nt * 8 + (lane & 3) * 2;
            float b0 = bias[col], b1 = bias[col + 1];
#pragma unroll
            for (int half = 0; half < 2; half++) {
                int r = row0 + half * 8;
                float vx = acc[mt][nt][half * 2 + 0] + b0;
                float vy = acc[mt][nt][half * 2 + 1] + b1;
                int z = (r >> 11) * NUM_HEADS + (col >> 6);
                int s = r & (SS - 1);
                int d = col & (DEPTH - 1);
                if (zz == 0) {
                    size_t o = ((size_t)z * SS + s) * DEPTH + d;
                    __half2 hp = {__float2half(vx), __float2half(vy)};
                    *(__half2*)&qf[o] = hp;
                } else if (zz == 1) {
                    size_t o = ((size_t)z * SS + s) * DEPTH + d;
                    __half2 hp = {__float2half(vx), __float2half(vy)};
                    *(__half2*)&kf[o] = hp;
                } else {
                    size_t o = ((size_t)z * DEPTH + d) * SS + s;
                    vt[o]      = __float2half(vx);
                    vt[o + SS] = __float2half(vy);
                }
            }
        }
    }
}

// ==================== output projection: O(hi/lo) x W fp16, 2 MMA ============
#define SPAD 40
#define PSTAGE 30720
#define OFF_AH 0
#define OFF_AL 10240
#define OFF_BH 20480

__global__ __launch_bounds__(256, 2)
void proj_out_kernel(const __half* __restrict__ a_hi, const __half* __restrict__ a_lo,
                     const __half* __restrict__ w,
                     const float* __restrict__ bias, float* __restrict__ C)
{
    extern __shared__ char smem[];
    const uint32_t sb0 = smem_u32(smem);

    const int tid  = threadIdx.x;
    const int lane = tid & 31;
    const int wid  = tid >> 5;
    const int warpM = (wid >> 2) * 64;
    const int warpN = (wid & 3) * 32;
    const int blockRow = blockIdx.y * 128;
    const int blockCol = blockIdx.x * 128;

    const int ldRow0 = tid >> 2;
    const int ldQ    = (tid & 3) * 16;
    const int lmRow = lane & 15;
    const int lmK   = (lane >> 4) * 8;

    float acc[4][4][4];
#pragma unroll
    for (int mt = 0; mt < 4; mt++)
#pragma unroll
        for (int nt = 0; nt < 4; nt++)
#pragma unroll
            for (int r = 0; r < 4; r++) acc[mt][nt][r] = 0.0f;

    auto load_stage = [&](int stage, int chunk) {
        const int k0 = chunk * 32;
        const uint32_t sb = sb0 + stage * PSTAGE;
#pragma unroll
        for (int j = 0; j < 2; j++) {
            int row = ldRow0 + j * 64;
            uint32_t so = (uint32_t)(row * 80) + ldQ;
            CP16(sb + OFF_AH + so, &a_hi[(size_t)(blockRow + row) * D_MODEL + k0] + ldQ / 2);
            CP16(sb + OFF_AL + so, &a_lo[(size_t)(blockRow + row) * D_MODEL + k0] + ldQ / 2);
            CP16(sb + OFF_BH + so, &w[(size_t)(blockCol + row) * D_MODEL + k0] + ldQ / 2);
        }
        CP_COMMIT();
    };

    load_stage(0, 0);

    for (int chunk = 0; chunk < 32; chunk++) {
        if (chunk < 31) { load_stage((chunk + 1) & 1, chunk + 1); CP_WAIT1(); }
        else           { CP_WAIT0(); }
        __syncthreads();

        const uint32_t sb = sb0 + (chunk & 1) * PSTAGE;
        const uint32_t aAddrBase = sb + (uint32_t)(((warpM + lmRow) * SPAD + lmK) * 2);
        const uint32_t bAddrBase = sb + (uint32_t)(((warpN + lmRow) * SPAD + lmK) * 2);

#pragma unroll
        for (int ks = 0; ks < 2; ks++) {
            const uint32_t kOff = (uint32_t)(ks * 16 * 2);
            uint32_t aH[4][4], aL[4][4], bH[4][2];
#pragma unroll
            for (int mt = 0; mt < 4; mt++) {
                uint32_t ad = aAddrBase + kOff + (uint32_t)(mt * 16 * SPAD * 2);
                LDSM4(aH[mt][0], aH[mt][1], aH[mt][2], aH[mt][3], ad + OFF_AH);
                LDSM4(aL[mt][0], aL[mt][1], aL[mt][2], aL[mt][3], ad + OFF_AL);
            }
#pragma unroll
            for (int ntp = 0; ntp < 2; ntp++) {
                uint32_t bd = bAddrBase + kOff + (uint32_t)(ntp * 16 * SPAD * 2);
                uint32_t r0, r1, r2, r3;
                LDSM4(r0, r1, r2, r3, bd + OFF_BH);
                bH[2 * ntp][0] = r0; bH[2 * ntp + 1][0] = r1;
                bH[2 * ntp][1] = r2; bH[2 * ntp + 1][1] = r3;
            }
#pragma unroll
            for (int mt = 0; mt < 4; mt++)
#pragma unroll
                for (int nt = 0; nt < 4; nt++) {
                    MMAH(acc[mt][nt], aH[mt], bH[nt]);
                    MMAH(acc[mt][nt], aL[mt], bH[nt]);
                }
        }
        __syncthreads();
    }

#pragma unroll
    for (int mt = 0; mt < 4; mt++) {
#pragma unroll
        for (int nt = 0; nt < 4; nt++) {
            int row0 = blockRow + warpM + mt * 16 + (lane >> 2);
            int col  = blockCol + warpN + nt * 8 + (lane & 3) * 2;
            float b0 = bias[col], b1 = bias[col + 1];
#pragma unroll
            for (int half = 0; half < 2; half++) {
                int r = row0 + half * 8;
                float2 v = {acc[mt][nt][half * 2 + 0] + b0, acc[mt][nt][half * 2 + 1] + b1};
                *(float2*)&C[(size_t)r * D_MODEL + col] = v;
            }
        }
    }
}

// ==================== scores: single-fp16 mma -> e fp16 (staged) =============
#define QPAD 72
#define EPAD 136

__global__ __launch_bounds__(256, 2)
void scores_mma_kernel(const __half* __restrict__ qf, const __half* __restrict__ kf,
                       const float* __restrict__ mask, __half* __restrict__ eout,
                       float* __restrict__ rowsum)
{
    extern __shared__ char sm[];
    const uint32_t sq = smem_u32(sm);
    __half* sQh = (__half*)sm;
    __half* sKh = sQh + 128 * QPAD;
    const uint32_t OQH = 0, OKH = 128 * QPAD * 2;

    const int z = blockIdx.z;
    const int b = z / NUM_HEADS;
    const int tid = threadIdx.x, lane = tid & 31, wid = tid >> 5;
    const int warpM = (wid >> 2) * 64, warpN = (wid & 3) * 32;
    const int blockRow = blockIdx.y * 128, blockCol = blockIdx.x * 128;
    const int lmRow = lane & 15, lmK = (lane >> 4) * 8;

#pragma unroll
    for (int i = 0; i < 4; i++) {
        int id = tid + i * 256;
        int row = id >> 3, q = id & 7;
        size_t gq = ((size_t)z * SS + blockRow + row) * DEPTH + q * 8;
        size_t gk = ((size_t)z * SS + blockCol + row) * DEPTH + q * 8;
        int so = row * QPAD + q * 8;
        *(uint4*)&sQh[so] = *(const uint4*)&qf[gq];
        *(uint4*)&sKh[so] = *(const uint4*)&kf[gk];
    }
    __syncthreads();

    float acc[4][4][4];
#pragma unroll
    for (int mt = 0; mt < 4; mt++)
#pragma unroll
        for (int nt = 0; nt < 4; nt++)
#pragma unroll
            for (int r = 0; r < 4; r++) acc[mt][nt][r] = 0.0f;

    const uint32_t aAddrBase = sq + (uint32_t)(((warpM + lmRow) * QPAD + lmK) * 2);
    const uint32_t bAddrBase = sq + (uint32_t)(((warpN + lmRow) * QPAD + lmK) * 2);

#pragma unroll
    for (int ks = 0; ks < 4; ks++) {
        const uint32_t kOff = (uint32_t)(ks * 16 * 2);
        uint32_t aH[4][4], bH[4][2];
#pragma unroll
        for (int mt = 0; mt < 4; mt++) {
            uint32_t ad = aAddrBase + kOff + (uint32_t)(mt * 16 * QPAD * 2);
            LDSM4(aH[mt][0], aH[mt][1], aH[mt][2], aH[mt][3], ad + OQH);
        }
#pragma unroll
        for (int ntp = 0; ntp < 2; ntp++) {
            uint32_t bd = bAddrBase + kOff + (uint32_t)(ntp * 16 * QPAD * 2);
            uint32_t r0, r1, r2, r3;
            LDSM4(r0, r1, r2, r3, bd + OKH);
            bH[2 * ntp][0] = r0; bH[2 * ntp + 1][0] = r1;
            bH[2 * ntp][1] = r2; bH[2 * ntp + 1][1] = r3;
        }
#pragma unroll
        for (int mt = 0; mt < 4; mt++)
#pragma unroll
            for (int nt = 0; nt < 4; nt++)
                MMAH(acc[mt][nt], aH[mt], bH[nt]);
    }

    float mcol[4][2];
#pragma unroll
    for (int nt = 0; nt < 4; nt++) {
        int col = blockCol + warpN + nt * 8 + (lane & 3) * 2;
        mcol[nt][0] = mask[(size_t)b * SS + col]     * (-1e9f);
        mcol[nt][1] = mask[(size_t)b * SS + col + 1] * (-1e9f);
    }

    __syncthreads();
    __half* sE = (__half*)sm;

#pragma unroll
    for (int mt = 0; mt < 4; mt++) {
#pragma unroll
        for (int half = 0; half < 2; half++) {
            int lrow = warpM + mt * 16 + (lane >> 2) + half * 8;
            float rs = 0.0f;
#pragma unroll
            for (int nt = 0; nt < 4; nt++) {
                int lcol = warpN + nt * 8 + (lane & 3) * 2;
                float e0 = __expf(acc[mt][nt][half * 2 + 0] * 0.125f + mcol[nt][0]);
                float e1 = __expf(acc[mt][nt][half * 2 + 1] * 0.125f + mcol[nt][1]);
                rs += e0 + e1;
                *(__half2*)&sE[lrow * EPAD + lcol] = __floats2half2_rn(e0, e1);
            }
            rs += __shfl_xor_sync(0xffffffffu, rs, 1);
            rs += __shfl_xor_sync(0xffffffffu, rs, 2);
            if ((lane & 3) == 0)
                rowsum[((size_t)z * SS + blockRow + lrow) * RS_W + blockIdx.x * 4 + (wid & 3)] = rs;
        }
    }
    __syncthreads();

    __half* Ez = eout + (size_t)z * SS * SS;
#pragma unroll
    for (int i = 0; i < 8; i++) {
        int id = tid + i * 256;
        int row = id >> 4, q = id & 15;
        *(uint4*)&Ez[(size_t)(blockRow + row) * SS + blockCol + q * 8] =
            *(const uint4*)&sE[row * EPAD + q * 8];
    }
}

// ==================== AV: cp.async pipelined, single-fp16 V ==================
#define AVPAD 72
#define AV_STAGE   46080      // A 256*72*2 + B 64*72*2
#define AV_OFF_B   36864
#define AV_OFF_INV 92160      // after 2 stages
#define AV_SMEM    93184      // + 256*4

__global__ __launch_bounds__(256, 2)
void av_mma_kernel(const __half* __restrict__ e, const __half* __restrict__ vt,
                   const float* __restrict__ rowsum, float* __restrict__ attn,
                   __half* __restrict__ o_hi, __half* __restrict__ o_lo)
{
    extern __shared__ char avsm[];
    const uint32_t sb0 = smem_u32(avsm);
    float* invs = (float*)(avsm + AV_OFF_INV);

    const int z = blockIdx.y;
    const int b = z / NUM_HEADS, h = z % NUM_HEADS;
    const int rowbase = blockIdx.x * 256;
    const int tid = threadIdx.x, lane = tid & 31, wid = tid >> 5;
    const int warpM = wid * 32;
    const int lmRow = lane & 15, lmK = (lane >> 4) * 8;

    {
        const float* rp = &rowsum[((size_t)z * SS + rowbase + tid) * RS_W];
        float s = 0.0f;
#pragma unroll
        for (int j = 0; j < RS_W; j++) s += rp[j];
        invs[tid] = 1.0f / s;
    }
    __syncthreads();

    const __half* Ez = e + (size_t)z * SS * SS;
    float* Az = attn + (size_t)z * SS * SS;

    auto load_stage = [&](int stage, int chunk) {
        const int k0 = chunk * 64;
        const uint32_t sb = sb0 + stage * AV_STAGE;
#pragma unroll
        for (int i = 0; i < 8; i++) {
            int id = tid + i * 256;
            int row = id >> 3, q = id & 7;
            CP16(sb + (uint32_t)(row * 144 + q * 16),
                 &Ez[(size_t)(rowbase + row) * SS + k0 + q * 8]);
        }
#pragma unroll
        for (int i = 0; i < 2; i++) {
            int id = tid + i * 256;
            int row = id >> 3, q = id & 7;
            CP16(sb + AV_OFF_B + (uint32_t)(row * 144 + q * 16),
                 &vt[((size_t)z * DEPTH + row) * SS + k0 + q * 8]);
        }
        CP_COMMIT();
    };

    float acc[2][8][4];
#pragma unroll
    for (int mt = 0; mt < 2; mt++)
#pragma unroll
        for (int nt = 0; nt < 8; nt++)
#pragma unroll
            for (int r = 0; r < 4; r++) acc[mt][nt][r] = 0.0f;

    load_stage(0, 0);

    for (int chunk = 0; chunk < 32; chunk++) {
        if (chunk < 31) { load_stage((chunk + 1) & 1, chunk + 1); CP_WAIT1(); }
        else           { CP_WAIT0(); }
        __syncthreads();

        const uint32_t sb = sb0 + (chunk & 1) * AV_STAGE;
        const __half* sA = (const __half*)(avsm + (chunk & 1) * AV_STAGE);
        const uint32_t aBase = sb + (uint32_t)(((warpM + lmRow) * AVPAD + lmK) * 2);
        const uint32_t bBase = sb + AV_OFF_B + (uint32_t)((lmRow * AVPAD + lmK) * 2);

        // MMA first (tensor pipe starts immediately)
#pragma unroll
        for (int ks = 0; ks < 4; ks++) {
            const uint32_t kOff = (uint32_t)(ks * 16 * 2);
            uint32_t aF[2][4], bH[8][2];
#pragma unroll
            for (int mt = 0; mt < 2; mt++) {
                uint32_t ad = aBase + kOff + (uint32_t)(mt * 16 * AVPAD * 2);
                LDSM4(aF[mt][0], aF[mt][1], aF[mt][2], aF[mt][3], ad);
            }
#pragma unroll
            for (int ntp = 0; ntp < 4; ntp++) {
                uint32_t bd = bBase + kOff + (uint32_t)(ntp * 16 * AVPAD * 2);
                uint32_t r0, r1, r2, r3;
                LDSM4(r0, r1, r2, r3, bd);
                bH[2 * ntp][0] = r0; bH[2 * ntp + 1][0] = r1;
                bH[2 * ntp][1] = r2; bH[2 * ntp + 1][1] = r3;
            }
#pragma unroll
            for (int mt = 0; mt < 2; mt++)
#pragma unroll
                for (int nt = 0; nt < 8; nt++)
                    MMAH(acc[mt][nt], aF[mt], bH[nt]);
        }

        // normalize + attn write (reads e tile back from smem)
        const int k0 = chunk * 64;
#pragma unroll
        for (int i = 0; i < 8; i++) {
            int id = tid + i * 256;
            int row = id >> 3, q = id & 7;
            uint4 ev = *(const uint4*)&sA[row * AVPAD + q * 8];
            const float inv = invs[row];
            const __half2* hp = (const __half2*)&ev;
            float2 f0 = __half22float2(hp[0]);
            float2 f1 = __half22float2(hp[1]);
            float2 f2 = __half22float2(hp[2]);
            float2 f3 = __half22float2(hp[3]);
            float4 v0 = {f0.x * inv, f0.y * inv, f1.x * inv, f1.y * inv};
            float4 v1 = {f2.x * inv, f2.y * inv, f3.x * inv, f3.y * inv};
            size_t ao = (size_t)(rowbase + row) * SS + k0 + q * 8;
            *(float4*)&Az[ao]     = v0;
            *(float4*)&Az[ao + 4] = v1;
        }
        __syncthreads();
    }

#pragma unroll
    for (int mt = 0; mt < 2; mt++) {
#pragma unroll
        for (int nt = 0; nt < 8; nt++) {
            int lrow0 = warpM + mt * 16 + (lane >> 2);
            int col   = nt * 8 + (lane & 3) * 2;
#pragma unroll
            for (int half = 0; half < 2; half++) {
                int lr = lrow0 + half * 8;
                float inv = invs[lr];
                int r = rowbase + lr;
                float vx = acc[mt][nt][half * 2 + 0] * inv;
                float vy = acc[mt][nt][half * 2 + 1] * inv;
                size_t o = ((size_t)b * SS + r) * D_MODEL + h * DEPTH + col;
                __half hx = __float2half(vx);
                __half hy = __float2half(vy);
                __half2 hp = {hx, hy};
                *(__half2*)&o_hi[o] = hp;
                __half2 lp = {__float2half(vx - __half2float(hx)),
                              __float2half(vy - __half2float(hy))};
                *(__half2*)&o_lo[o] = lp;
            }
        }
    }
}

// =====================================================================
extern "C" void kernel_launch(void* const* d_in, const int* in_sizes, int n_in,
                              void* d_out, int out_size)
{
    const float* Q    = (const float*)d_in[0];
    const float* K    = (const float*)d_in[1];
    const float* V    = (const float*)d_in[2];
    const float* mask = (const float*)d_in[3];
    const float* Wq   = (const float*)d_in[4];
    const float* bq   = (const float*)d_in[5];
    const float* Wk   = (const float*)d_in[6];
    const float* bk   = (const float*)d_in[7];
    const float* Wv   = (const float*)d_in[8];
    const float* bv   = (const float*)d_in[9];
    const float* Wo   = (const float*)d_in[10];
    const float* bo   = (const float*)d_in[11];

    float* out = (float*)d_out;

    float *rowsum, *attn;
    __half *inb, *w, *qf, *kf, *vt, *ohi, *olo, *ebuf;
    cudaGetSymbolAddress((void**)&rowsum, g_rowsum);
    cudaGetSymbolAddress((void**)&ebuf, g_e);
    cudaGetSymbolAddress((void**)&inb, g_in);
    cudaGetSymbolAddress((void**)&w, g_w);
    cudaGetSymbolAddress((void**)&qf, g_q_f);
    cudaGetSymbolAddress((void**)&kf, g_k_f);
    cudaGetSymbolAddress((void**)&vt, g_vt);
    cudaGetSymbolAddress((void**)&ohi, g_o_hi);
    cudaGetSymbolAddress((void**)&olo, g_o_lo);

    if ((size_t)out_size >= OUT_ELEMS + ATTN_ELEMS) {
        attn = out + OUT_ELEMS;
    } else {
        cudaGetSymbolAddress((void**)&attn, g_attn_fallback);
    }

    static bool attr_done = false;
    if (!attr_done) {
        cudaFuncSetAttribute(proj_qkv_kernel, cudaFuncAttributeMaxDynamicSharedMemorySize, 2 * P2STAGE);
        cudaFuncSetAttribute(proj_out_kernel, cudaFuncAttributeMaxDynamicSharedMemorySize, 2 * PSTAGE);
        cudaFuncSetAttribute(scores_mma_kernel, cudaFuncAttributeMaxDynamicSharedMemorySize, 2 * 128 * QPAD * 2);
        cudaFuncSetAttribute(av_mma_kernel, cudaFuncAttributeMaxDynamicSharedMemorySize, AV_SMEM);
        attr_done = true;
    }

    // 1. splits
    dim3 wtBlock(32, 8);
    split_w4_kernel<<<dim3(32, 32, 4), wtBlock>>>(Wq, Wk, Wv, Wo, w);
    split_in3_kernel<<<dim3(NELEM / 256, 3), 256>>>(Q, K, V, inb);

    // 2. QKV projections
    proj_qkv_kernel<<<dim3(8, 32, 3), 256, 2 * P2STAGE>>>(
        inb, w, bq, bk, bv, qf, kf, vt);

    // 3. scores -> e fp16 + rowsum partials
    scores_mma_kernel<<<dim3(16, 16, NZ), 256, 2 * 128 * QPAD * 2>>>(
        qf, kf, mask, ebuf, rowsum);

    // 4. AV (cp.async pipelined) + fused attn normalize
    av_mma_kernel<<<dim3(8, NZ), 256, AV_SMEM>>>(ebuf, vt, rowsum, attn, ohi, olo);

    // 5. output projection
    proj_out_kernel<<<dim3(8, 32), 256, 2 * PSTAGE>>>(
        ohi, olo, w + (size_t)3 * WELEM, bo, out);
}